// round 1
// baseline (speedup 1.0000x reference)
#include <cuda_runtime.h>
#include <math.h>

// Problem constants
#define Bq 8
#define Tq 2048
#define Cq 1024
#define Hq 16
#define BTq (Bq*Tq)

typedef unsigned long long ull;

// ---------------------------------------------------------------------------
// Scratch (static device globals — no allocation at runtime)
// ---------------------------------------------------------------------------
__device__ float g_dxa [BTq*Cq];
__device__ float g_xm  [BTq*Cq];
__device__ float g_xx  [5*BTq*Cq];
__device__ float g_k   [BTq*Cq];
__device__ float g_v   [BTq*Cq];
__device__ float g_r   [BTq*Cq];
__device__ float g_g   [BTq*Cq];
__device__ float g_w   [BTq*Cq];
__device__ float g_y   [BTq*Cq];
__device__ float g_yg  [BTq*Cq];
__device__ float g_lorap [BTq*256];   // tanh(xm @ A_lora), padded N=256
__device__ float g_tdhp  [BTq*128];   // tanh(w_in @ td_A), padded N=128
__device__ float g_AloraT[256*1024];  // A_lora^T zero-padded (256,1024)
__device__ float g_tdAT  [128*1024];  // td_A^T zero-padded (128,1024)
__device__ float g_tdBT  [1024*64];   // td_B^T (1024,64)
__device__ float g_BloraT[5*1024*32]; // B_lora^T per branch (5,1024,32)

// ---------------------------------------------------------------------------
// Packed f32x2 helpers (Blackwell FFMA2 — 2x FMA per issue vs 3-reg FFMA)
// ---------------------------------------------------------------------------
__device__ __forceinline__ void fma2(ull& d, ull a, ull b){
    asm("fma.rn.f32x2 %0, %1, %2, %0;" : "+l"(d) : "l"(a), "l"(b));
}
__device__ __forceinline__ float2 unp(ull v){
    float2 r; asm("mov.b64 {%0, %1}, %2;" : "=f"(r.x), "=f"(r.y) : "l"(v)); return r;
}

// ---------------------------------------------------------------------------
// SGEMM  C[M,N] = A[M,K] @ B[N,K]^T  (both row-major, K contiguous)
// 128x128 tile, BK=8, 256 threads, 8x8 per thread via f32x2 pairs.
// Epilogue variants fused.
// ---------------------------------------------------------------------------
#define EPI_NONE 0
#define EPI_SILU 1
#define EPI_TANH 2
#define EPI_BIAS 3
#define EPI_MIX  4

template<int EPI>
__global__ void __launch_bounds__(256) sgemm_nt(
    const float* __restrict__ A, int lda,
    const float* __restrict__ Bm, int ldb,
    float* __restrict__ Cp, int N, int K,
    const float* __restrict__ e0, const float* __restrict__ e1,
    const float* __restrict__ e2)
{
    __shared__ __align__(16) float As2[8][256];  // A duplicated per element (a,a)
    __shared__ __align__(16) float Bs [8][128];

    int tid  = threadIdx.x;
    int m0   = blockIdx.y * 128, n0 = blockIdx.x * 128;
    int lrow = tid >> 1;            // 0..127
    int lkq  = (tid & 1) * 4;       // 0 or 4
    const float* Ap = A  + (size_t)(m0 + lrow) * lda + lkq;
    const float* Bp = Bm + (size_t)(n0 + lrow) * ldb + lkq;
    int ty = tid >> 4, tx = tid & 15;

    ull acc[8][4];
    #pragma unroll
    for (int i = 0; i < 8; i++)
        #pragma unroll
        for (int p = 0; p < 4; p++) acc[i][p] = 0ull;

    for (int k0 = 0; k0 < K; k0 += 8) {
        float4 av = *(const float4*)(Ap + k0);
        float4 bv = *(const float4*)(Bp + k0);
        *(float2*)&As2[lkq+0][2*lrow] = make_float2(av.x, av.x);
        *(float2*)&As2[lkq+1][2*lrow] = make_float2(av.y, av.y);
        *(float2*)&As2[lkq+2][2*lrow] = make_float2(av.z, av.z);
        *(float2*)&As2[lkq+3][2*lrow] = make_float2(av.w, av.w);
        Bs[lkq+0][lrow] = bv.x;
        Bs[lkq+1][lrow] = bv.y;
        Bs[lkq+2][lrow] = bv.z;
        Bs[lkq+3][lrow] = bv.w;
        __syncthreads();
        #pragma unroll
        for (int kk = 0; kk < 8; kk++) {
            const ull* ar = (const ull*)As2[kk];
            const ull* br = (const ull*)Bs[kk];
            ull a_[8], b_[4];
            #pragma unroll
            for (int i = 0; i < 8; i++) a_[i] = ar[ty*8 + i];
            #pragma unroll
            for (int p = 0; p < 4; p++) b_[p] = br[tx*4 + p];
            #pragma unroll
            for (int i = 0; i < 8; i++)
                #pragma unroll
                for (int p = 0; p < 4; p++) fma2(acc[i][p], a_[i], b_[p]);
        }
        __syncthreads();
    }

    #pragma unroll
    for (int i = 0; i < 8; i++) {
        size_t m = (size_t)(m0 + ty*8 + i);
        #pragma unroll
        for (int p = 0; p < 4; p++) {
            float2 vv = unp(acc[i][p]);
            int n = n0 + tx*8 + 2*p;
            size_t idx = m * (size_t)N + n;
            if (EPI == EPI_SILU) {
                vv.x = vv.x / (1.f + expf(-vv.x));
                vv.y = vv.y / (1.f + expf(-vv.y));
            } else if (EPI == EPI_TANH) {
                vv.x = tanhf(vv.x); vv.y = tanhf(vv.y);
            } else if (EPI == EPI_BIAS) {
                vv.x += e0[n]; vv.y += e0[n+1];
            } else if (EPI == EPI_MIX) {
                vv.x = e0[idx]   + e1[idx]   * (e2[n]   + vv.x);
                vv.y = e0[idx+1] + e1[idx+1] * (e2[n+1] + vv.y);
            }
            *(float2*)(Cp + idx) = vv;
        }
    }
}

// ---------------------------------------------------------------------------
// prep: dxa = shift(x) - x ; xm = x + dxa * miu_x   (float4, per batch-row)
// ---------------------------------------------------------------------------
__global__ void __launch_bounds__(256) prep_kernel(
    const float4* __restrict__ x4, const float4* __restrict__ mu4,
    float4* __restrict__ dxa4, float4* __restrict__ xm4)
{
    size_t i = (size_t)blockIdx.x * 256 + threadIdx.x;   // over BT*256 float4s
    int m = (int)(i >> 8);          // row index (b*T + t); C/4 = 256
    int t = m & (Tq - 1);
    float4 xv = x4[i];
    float4 xl = make_float4(0.f, 0.f, 0.f, 0.f);
    if (t) xl = x4[i - 256];
    float4 mu = mu4[i & 255];
    float4 d  = make_float4(xl.x - xv.x, xl.y - xv.y, xl.z - xv.z, xl.w - xv.w);
    float4 xm = make_float4(fmaf(d.x, mu.x, xv.x), fmaf(d.y, mu.y, xv.y),
                            fmaf(d.z, mu.z, xv.z), fmaf(d.w, mu.w, xv.w));
    dxa4[i] = d;
    xm4[i]  = xm;
}

// ---------------------------------------------------------------------------
// transpose + zero-pad:  dst[n*Kd + k] = (n < Nsrc) ? src[k*ldsrc + n] : 0
// ---------------------------------------------------------------------------
__global__ void transpose_pad(float* __restrict__ dst, const float* __restrict__ src,
                              int Nd, int Kd, int Nsrc, int ldsrc)
{
    int i = blockIdx.x * blockDim.x + threadIdx.x;
    if (i >= Nd * Kd) return;
    int n = i / Kd, k = i % Kd;
    dst[i] = (n < Nsrc) ? src[(size_t)k * ldsrc + n] : 0.f;
}

// ---------------------------------------------------------------------------
// WKV6 scan. One block per (b,h). 256 threads: thread (j = tid>>2, rg = tid&3)
// owns state rows [rg*16, rg*16+16) of column j. Double-buffered smem staging,
// one barrier per timestep. pk packed as {k, u*k, r, decay} with [4][17]
// padding for conflict-free LDS.128.
// ---------------------------------------------------------------------------
__global__ void __launch_bounds__(256) wkv6_kernel(
    const float* __restrict__ rp, const float* __restrict__ kp,
    const float* __restrict__ vp, const float* __restrict__ wp,
    const float* __restrict__ up, float* __restrict__ yp)
{
    __shared__ float4 pk[2][4][17];
    __shared__ float  sv[2][64];
    int bh = blockIdx.x;
    int b = bh >> 4, h = bh & 15;
    size_t base = ((size_t)b * Tq) * Cq + h * 64;
    int tid = threadIdx.x;
    int j = tid >> 2, rg = tid & 3;
    float uu = 0.f;
    if (tid < 64) uu = up[h * 64 + tid];
    float S[16];
    #pragma unroll
    for (int i = 0; i < 16; i++) S[i] = 0.f;

    for (int t = 0; t < Tq; t++) {
        int buf = t & 1;
        size_t off = base + (size_t)t * Cq;
        if (tid < 64) {
            float kk = kp[off + tid];
            float rr = rp[off + tid];
            float ww = wp[off + tid];
            sv[buf][tid] = vp[off + tid];
            float dd = expf(-expf(ww));
            pk[buf][tid >> 4][tid & 15] = make_float4(kk, uu * kk, rr, dd);
        }
        __syncthreads();
        float vj = sv[buf][j];
        float yv = 0.f;
        #pragma unroll
        for (int ii = 0; ii < 16; ii++) {
            float4 p = pk[buf][rg][ii];
            float s = S[ii];
            yv = fmaf(p.z, fmaf(p.y, vj, s), yv);     // r * (S + u*k*v)
            S[ii] = fmaf(p.w, s, p.x * vj);           // S = d*S + k*v
        }
        yv += __shfl_xor_sync(0xffffffffu, yv, 1);
        yv += __shfl_xor_sync(0xffffffffu, yv, 2);
        if (rg == 0) yp[off + j] = yv;
    }
}

// ---------------------------------------------------------------------------
// GroupNorm over 16 heads of 64 ch, fused with gate multiply.
// One block per token; thread handles 4 channels (float4). 16 lanes per head.
// ---------------------------------------------------------------------------
__global__ void __launch_bounds__(256) gnorm_kernel(
    const float* __restrict__ y, const float* __restrict__ g,
    const float* __restrict__ gamma, const float* __restrict__ beta,
    float* __restrict__ out)
{
    int m = blockIdx.x, tid = threadIdx.x;
    size_t i4 = (size_t)m * 256 + tid;
    float4 yv = ((const float4*)y)[i4];
    float s  = yv.x + yv.y + yv.z + yv.w;
    float ss = yv.x*yv.x + yv.y*yv.y + yv.z*yv.z + yv.w*yv.w;
    #pragma unroll
    for (int o = 1; o < 16; o <<= 1) {
        s  += __shfl_xor_sync(0xffffffffu, s,  o);
        ss += __shfl_xor_sync(0xffffffffu, ss, o);
    }
    float mean = s * (1.f / 64.f);
    float var  = ss * (1.f / 64.f) - mean * mean;
    float rstd = rsqrtf(fmaxf(var, 0.f) + 1.6e-4f);   // eps = 1e-5 * n_head
    float4 ga = ((const float4*)gamma)[tid];
    float4 be = ((const float4*)beta)[tid];
    float4 gv = ((const float4*)g)[i4];
    float4 o4;
    o4.x = ((yv.x - mean) * rstd * ga.x + be.x) * gv.x;
    o4.y = ((yv.y - mean) * rstd * ga.y + be.y) * gv.y;
    o4.z = ((yv.z - mean) * rstd * ga.z + be.z) * gv.z;
    o4.w = ((yv.w - mean) * rstd * ga.w + be.w) * gv.w;
    ((float4*)out)[i4] = o4;
}

// ---------------------------------------------------------------------------
// Launch
// ---------------------------------------------------------------------------
static inline dim3 g2(int M, int N) { return dim3((unsigned)(N / 128), (unsigned)(M / 128)); }

extern "C" void kernel_launch(void* const* d_in, const int* in_sizes, int n_in,
                              void* d_out, int out_size)
{
    (void)in_sizes; (void)n_in; (void)out_size;
    const float* x       = (const float*)d_in[0];
    const float* miu_x   = (const float*)d_in[1];
    const float* lambda_ = (const float*)d_in[2];
    const float* A_lora  = (const float*)d_in[3];
    const float* B_lora  = (const float*)d_in[4];
    const float* td_miu  = (const float*)d_in[5];
    const float* td_A    = (const float*)d_in[6];
    const float* td_B    = (const float*)d_in[7];
    const float* u       = (const float*)d_in[8];
    const float* Wr      = (const float*)d_in[9];
    const float* Wk      = (const float*)d_in[10];
    const float* Wv      = (const float*)d_in[11];
    const float* Wg      = (const float*)d_in[12];
    const float* Wo      = (const float*)d_in[13];
    const float* gamma   = (const float*)d_in[14];
    const float* beta    = (const float*)d_in[15];
    float* out = (float*)d_out;

    float *p_dxa,*p_xm,*p_xx,*p_k,*p_v,*p_r,*p_g,*p_w,*p_y,*p_yg,
          *p_lorap,*p_tdhp,*p_AloraT,*p_tdAT,*p_tdBT,*p_BloraT;
    { void* t;
      cudaGetSymbolAddress(&t, g_dxa);    p_dxa    = (float*)t;
      cudaGetSymbolAddress(&t, g_xm);     p_xm     = (float*)t;
      cudaGetSymbolAddress(&t, g_xx);     p_xx     = (float*)t;
      cudaGetSymbolAddress(&t, g_k);      p_k      = (float*)t;
      cudaGetSymbolAddress(&t, g_v);      p_v      = (float*)t;
      cudaGetSymbolAddress(&t, g_r);      p_r      = (float*)t;
      cudaGetSymbolAddress(&t, g_g);      p_g      = (float*)t;
      cudaGetSymbolAddress(&t, g_w);      p_w      = (float*)t;
      cudaGetSymbolAddress(&t, g_y);      p_y      = (float*)t;
      cudaGetSymbolAddress(&t, g_yg);     p_yg     = (float*)t;
      cudaGetSymbolAddress(&t, g_lorap);  p_lorap  = (float*)t;
      cudaGetSymbolAddress(&t, g_tdhp);   p_tdhp   = (float*)t;
      cudaGetSymbolAddress(&t, g_AloraT); p_AloraT = (float*)t;
      cudaGetSymbolAddress(&t, g_tdAT);   p_tdAT   = (float*)t;
      cudaGetSymbolAddress(&t, g_tdBT);   p_tdBT   = (float*)t;
      cudaGetSymbolAddress(&t, g_BloraT); p_BloraT = (float*)t;
    }
    const size_t SZ = (size_t)BTq * Cq;

    // 1) token shift + static lerp
    prep_kernel<<<BTq * Cq / 4 / 256, 256>>>((const float4*)x, (const float4*)miu_x,
                                             (float4*)p_dxa, (float4*)p_xm);

    // 2) weight transposes (tiny)
    transpose_pad<<<(256*1024 + 255) / 256, 256>>>(p_AloraT, A_lora, 256, 1024, 160, 160);
    transpose_pad<<<(128*1024 + 255) / 256, 256>>>(p_tdAT,   td_A,   128, 1024,  64,  64);
    transpose_pad<<<(1024*64  + 255) / 256, 256>>>(p_tdBT,   td_B,  1024,   64, 1024, 1024);
    for (int f = 0; f < 5; f++)
        transpose_pad<<<(1024*32 + 255) / 256, 256>>>(p_BloraT + f*1024*32,
                                                      B_lora + f*32*1024,
                                                      1024, 32, 1024, 1024);

    // 3) lora_h = tanh(xm @ A_lora)  (N padded 160 -> 256)
    sgemm_nt<EPI_TANH><<<g2(BTq, 256), 256>>>(p_xm, Cq, p_AloraT, 1024,
                                              p_lorap, 256, 1024,
                                              nullptr, nullptr, nullptr);

    // 4) xx_f = x + dxa * (lambda_f + lora_h_f @ B_lora_f)   (fused epilogue)
    for (int f = 0; f < 5; f++)
        sgemm_nt<EPI_MIX><<<g2(BTq, Cq), 256>>>(p_lorap + f*32, 256,
                                                p_BloraT + f*1024*32, 32,
                                                p_xx + (size_t)f*SZ, Cq, 32,
                                                x, p_dxa, lambda_ + f*Cq);

    // 5) projections
    sgemm_nt<EPI_NONE><<<g2(BTq, Cq), 256>>>(p_xx + 1*SZ, Cq, Wk, Cq, p_k, Cq, Cq, nullptr, nullptr, nullptr);
    sgemm_nt<EPI_NONE><<<g2(BTq, Cq), 256>>>(p_xx + 2*SZ, Cq, Wv, Cq, p_v, Cq, Cq, nullptr, nullptr, nullptr);
    sgemm_nt<EPI_NONE><<<g2(BTq, Cq), 256>>>(p_xx + 3*SZ, Cq, Wr, Cq, p_r, Cq, Cq, nullptr, nullptr, nullptr);
    sgemm_nt<EPI_SILU><<<g2(BTq, Cq), 256>>>(p_xx + 4*SZ, Cq, Wg, Cq, p_g, Cq, Cq, nullptr, nullptr, nullptr);

    // 6) w = td_miu + tanh(w_in @ td_A) @ td_B
    sgemm_nt<EPI_TANH><<<g2(BTq, 128), 256>>>(p_xx + 0*SZ, Cq, p_tdAT, 1024,
                                              p_tdhp, 128, 1024,
                                              nullptr, nullptr, nullptr);
    sgemm_nt<EPI_BIAS><<<g2(BTq, Cq), 256>>>(p_tdhp, 128, p_tdBT, 64,
                                             p_w, Cq, 64, td_miu, nullptr, nullptr);

    // 7) WKV6 scan
    wkv6_kernel<<<Bq * Hq, 256>>>(p_r, p_k, p_v, p_w, u, p_y);

    // 8) GroupNorm * gate
    gnorm_kernel<<<BTq, 256>>>(p_y, p_g, gamma, beta, p_yg);

    // 9) output projection
    sgemm_nt<EPI_NONE><<<g2(BTq, Cq), 256>>>(p_yg, Cq, Wo, Cq, out, Cq, Cq, nullptr, nullptr, nullptr);
}

// round 3
// speedup vs baseline: 1.7195x; 1.7195x over previous
#include <cuda_runtime.h>
#include <cuda_bf16.h>
#include <math.h>
#include <stdint.h>

#define Bq 8
#define Tq 2048
#define Cq 1024
#define Hq 16
#define BTq (Bq*Tq)
#define WWq (Cq*Cq)

typedef unsigned long long ull;
static const size_t SZq = (size_t)BTq * Cq;

// ---------------------------------------------------------------------------
// Scratch (static device globals — no runtime allocation)
// ---------------------------------------------------------------------------
__device__ float g_dxa [BTq*Cq];
__device__ float g_xm  [BTq*Cq];
__device__ float g_xx0 [BTq*Cq];      // w_in branch only (fp32)
__device__ float g_k   [BTq*Cq];
__device__ float g_v   [BTq*Cq];
__device__ float g_r   [BTq*Cq];
__device__ float g_g   [BTq*Cq];
__device__ float g_w   [BTq*Cq];
__device__ float g_y   [BTq*Cq];
__device__ float g_lorap [BTq*256];
__device__ float g_tdhp  [BTq*128];
__device__ float g_AloraT[256*1024];
__device__ float g_tdAT  [128*1024];
__device__ float g_tdBT  [1024*64];
__device__ float g_BloraT[5*1024*32];
__device__ __nv_bfloat16 g_abh[4*BTq*Cq];   // k,v,r,g branch inputs (hi)
__device__ __nv_bfloat16 g_abl[4*BTq*Cq];   // (lo)
__device__ __nv_bfloat16 g_ygh[BTq*Cq];
__device__ __nv_bfloat16 g_ygl[BTq*Cq];
__device__ __nv_bfloat16 g_wbh[5*WWq];      // Wk,Wv,Wr,Wg,Wo (hi)
__device__ __nv_bfloat16 g_wbl[5*WWq];      // (lo)

// ---------------------------------------------------------------------------
// PTX helpers (all sm_80+ — valid on compute_103 virtual arch)
// ---------------------------------------------------------------------------
__device__ __forceinline__ uint32_t sm2u32(const void* p){
    uint32_t a;
    asm("{ .reg .u64 t; cvta.to.shared.u64 t, %1; cvt.u32.u64 %0, t; }" : "=r"(a) : "l"(p));
    return a;
}
__device__ __forceinline__ void cpa16(uint32_t dst, const void* src){
    asm volatile("cp.async.cg.shared.global [%0], [%1], 16;" :: "r"(dst), "l"(src) : "memory");
}
__device__ __forceinline__ void cpa_commit(){
    asm volatile("cp.async.commit_group;" ::: "memory");
}
template<int N>
__device__ __forceinline__ void cpa_wait(){
    asm volatile("cp.async.wait_group %0;" :: "n"(N) : "memory");
}
__device__ __forceinline__ void ldsm_x4(uint32_t* r, uint32_t addr){
    asm volatile("ldmatrix.sync.aligned.m8n8.x4.shared.b16 {%0,%1,%2,%3}, [%4];"
        : "=r"(r[0]), "=r"(r[1]), "=r"(r[2]), "=r"(r[3]) : "r"(addr));
}
__device__ __forceinline__ void mma_bf16(float* d, const uint32_t* a, const uint32_t* b){
    asm volatile("mma.sync.aligned.m16n8k16.row.col.f32.bf16.bf16.f32 "
        "{%0,%1,%2,%3}, {%4,%5,%6,%7}, {%8,%9}, {%0,%1,%2,%3};"
        : "+f"(d[0]), "+f"(d[1]), "+f"(d[2]), "+f"(d[3])
        : "r"(a[0]), "r"(a[1]), "r"(a[2]), "r"(a[3]), "r"(b[0]), "r"(b[1]));
}

// ---------------------------------------------------------------------------
// bf16-split GEMM via mma.sync: C[M,N] = (Ah+Al)[M,K] @ (Bh+Bl)[N,K]^T
// 128x128 tile, BK=32, 2-stage cp.async pipeline, 8 warps (2x4), warp 64x32.
// Smem per stage: 4 arrays x [128 rows x 40 halves] (padded, conflict-free).
// ---------------------------------------------------------------------------
#define HG_STAGE  40960                 // 4 * 128*40*2 bytes
#define HG_ARR    10240                 // per-array bytes
#define HG_SMEM   (2 * HG_STAGE)

template<int SILU>
__global__ void __launch_bounds__(256) hgemm(
    const __nv_bfloat16* __restrict__ Ah, const __nv_bfloat16* __restrict__ Al,
    const __nv_bfloat16* __restrict__ Bh, const __nv_bfloat16* __restrict__ Bl,
    float* __restrict__ Cp, int M, int N, int K)
{
    extern __shared__ char sm[];
    int tid = threadIdx.x, lane = tid & 31, wid = tid >> 5;
    int wy = wid & 1, wx = wid >> 1;           // 2 x 4 warp grid
    int m0 = blockIdx.y * 128, n0 = blockIdx.x * 128;
    uint32_t sb = sm2u32(sm);

    // per-thread load descriptors: 8 chunks of 16B
    const __nv_bfloat16* gptr[8];
    uint32_t soff[8];
    #pragma unroll
    for (int t = 0; t < 8; t++){
        int idx = t * 256 + tid;                // 0..2047
        int arr = idx >> 9;                     // 0:Ah 1:Al 2:Bh 3:Bl
        int rem = idx & 511;
        int row = rem >> 2, ch = rem & 3;
        size_t go = (arr < 2) ? ((size_t)(m0 + row) * K + ch * 8)
                              : ((size_t)(n0 + row) * K + ch * 8);
        const __nv_bfloat16* base = (arr == 0) ? Ah : (arr == 1) ? Al : (arr == 2) ? Bh : Bl;
        gptr[t] = base + go;
        soff[t] = (uint32_t)(arr * HG_ARR + row * 80 + ch * 16);
    }

    float acc[4][4][4];
    #pragma unroll
    for (int i = 0; i < 4; i++)
        #pragma unroll
        for (int j = 0; j < 4; j++)
            #pragma unroll
            for (int q = 0; q < 4; q++) acc[i][j][q] = 0.f;

    // ldmatrix base offsets
    uint32_t a_row = (uint32_t)(wy * 64 + (lane & 15));
    uint32_t a_kh  = (uint32_t)((lane >> 4) * 8);
    uint32_t b_row0 = (uint32_t)(wx * 32 + (lane & 7) + ((lane >> 4) * 8));
    uint32_t b_kh   = (uint32_t)(((lane >> 3) & 1) * 8);

    const int NC = K >> 5;

    // prologue: stage 0
    #pragma unroll
    for (int t = 0; t < 8; t++) cpa16(sb + soff[t], gptr[t]);
    cpa_commit();

    for (int c = 0; c < NC; c++){
        int buf = c & 1;
        if (c + 1 < NC){
            int nb = buf ^ 1;
            uint32_t db = sb + (uint32_t)nb * HG_STAGE;
            const __nv_bfloat16* kadd = (const __nv_bfloat16*)0 + (size_t)(c + 1) * 32;
            #pragma unroll
            for (int t = 0; t < 8; t++) cpa16(db + soff[t], gptr[t] + (size_t)(c + 1) * 32);
            cpa_commit();
            cpa_wait<1>();
            (void)kadd;
        } else {
            cpa_wait<0>();
        }
        __syncthreads();

        uint32_t base = sb + (uint32_t)buf * HG_STAGE;
        #pragma unroll
        for (int ks = 0; ks < 2; ks++){
            uint32_t ah[4][4], al[4][4], bh[2][4], bl[2][4];
            uint32_t akh = (uint32_t)(ks * 16) + a_kh;
            #pragma unroll
            for (int mf = 0; mf < 4; mf++){
                uint32_t ao = base + (a_row + mf * 16) * 80 + akh * 2;
                ldsm_x4(ah[mf], ao);
                ldsm_x4(al[mf], ao + HG_ARR);
            }
            uint32_t bkh = (uint32_t)(ks * 16) + b_kh;
            #pragma unroll
            for (int bi = 0; bi < 2; bi++){
                uint32_t bo = base + 2*HG_ARR + (b_row0 + bi * 16) * 80 + bkh * 2;
                ldsm_x4(bh[bi], bo);
                ldsm_x4(bl[bi], bo + HG_ARR);
            }
            #pragma unroll
            for (int mf = 0; mf < 4; mf++)
                #pragma unroll
                for (int nf = 0; nf < 4; nf++){
                    const uint32_t* bhp = &bh[nf >> 1][(nf & 1) * 2];
                    const uint32_t* blp = &bl[nf >> 1][(nf & 1) * 2];
                    mma_bf16(acc[mf][nf], ah[mf], bhp);
                    mma_bf16(acc[mf][nf], ah[mf], blp);
                    mma_bf16(acc[mf][nf], al[mf], bhp);
                }
        }
        __syncthreads();
    }

    // epilogue
    #pragma unroll
    for (int mf = 0; mf < 4; mf++){
        int row0 = m0 + wy * 64 + mf * 16 + (lane >> 2);
        #pragma unroll
        for (int nf = 0; nf < 4; nf++){
            int col = n0 + wx * 32 + nf * 8 + (lane & 3) * 2;
            float2 v01 = make_float2(acc[mf][nf][0], acc[mf][nf][1]);
            float2 v23 = make_float2(acc[mf][nf][2], acc[mf][nf][3]);
            if (SILU){
                v01.x = v01.x / (1.f + expf(-v01.x));
                v01.y = v01.y / (1.f + expf(-v01.y));
                v23.x = v23.x / (1.f + expf(-v23.x));
                v23.y = v23.y / (1.f + expf(-v23.y));
            }
            *(float2*)(Cp + (size_t)row0 * N + col)       = v01;
            *(float2*)(Cp + (size_t)(row0 + 8) * N + col) = v23;
        }
    }
}

// ---------------------------------------------------------------------------
// FFMA2 helpers + SGEMM for the small GEMMs (proven round-1 code)
// ---------------------------------------------------------------------------
__device__ __forceinline__ void fma2(ull& d, ull a, ull b){
    asm("fma.rn.f32x2 %0, %1, %2, %0;" : "+l"(d) : "l"(a), "l"(b));
}
__device__ __forceinline__ float2 unp(ull v){
    float2 r; asm("mov.b64 {%0, %1}, %2;" : "=f"(r.x), "=f"(r.y) : "l"(v)); return r;
}

#define EPI_TANH 2
#define EPI_BIAS 3

template<int EPI>
__global__ void __launch_bounds__(256) sgemm_nt(
    const float* __restrict__ A, int lda,
    const float* __restrict__ Bm, int ldb,
    float* __restrict__ Cp, int N, int K,
    const float* __restrict__ e0)
{
    __shared__ __align__(16) float As2[8][256];
    __shared__ __align__(16) float Bs [8][128];

    int tid  = threadIdx.x;
    int m0   = blockIdx.y * 128, n0 = blockIdx.x * 128;
    int lrow = tid >> 1;
    int lkq  = (tid & 1) * 4;
    const float* Ap = A  + (size_t)(m0 + lrow) * lda + lkq;
    const float* Bp = Bm + (size_t)(n0 + lrow) * ldb + lkq;
    int ty = tid >> 4, tx = tid & 15;

    ull acc[8][4];
    #pragma unroll
    for (int i = 0; i < 8; i++)
        #pragma unroll
        for (int p = 0; p < 4; p++) acc[i][p] = 0ull;

    for (int k0 = 0; k0 < K; k0 += 8) {
        float4 av = *(const float4*)(Ap + k0);
        float4 bv = *(const float4*)(Bp + k0);
        *(float2*)&As2[lkq+0][2*lrow] = make_float2(av.x, av.x);
        *(float2*)&As2[lkq+1][2*lrow] = make_float2(av.y, av.y);
        *(float2*)&As2[lkq+2][2*lrow] = make_float2(av.z, av.z);
        *(float2*)&As2[lkq+3][2*lrow] = make_float2(av.w, av.w);
        Bs[lkq+0][lrow] = bv.x;
        Bs[lkq+1][lrow] = bv.y;
        Bs[lkq+2][lrow] = bv.z;
        Bs[lkq+3][lrow] = bv.w;
        __syncthreads();
        #pragma unroll
        for (int kk = 0; kk < 8; kk++) {
            const ull* ar = (const ull*)As2[kk];
            const ull* br = (const ull*)Bs[kk];
            ull a_[8], b_[4];
            #pragma unroll
            for (int i = 0; i < 8; i++) a_[i] = ar[ty*8 + i];
            #pragma unroll
            for (int p = 0; p < 4; p++) b_[p] = br[tx*4 + p];
            #pragma unroll
            for (int i = 0; i < 8; i++)
                #pragma unroll
                for (int p = 0; p < 4; p++) fma2(acc[i][p], a_[i], b_[p]);
        }
        __syncthreads();
    }

    #pragma unroll
    for (int i = 0; i < 8; i++) {
        size_t m = (size_t)(m0 + ty*8 + i);
        #pragma unroll
        for (int p = 0; p < 4; p++) {
            float2 vv = unp(acc[i][p]);
            int n = n0 + tx*8 + 2*p;
            size_t idx = m * (size_t)N + n;
            if (EPI == EPI_TANH) {
                vv.x = tanhf(vv.x); vv.y = tanhf(vv.y);
            } else if (EPI == EPI_BIAS) {
                vv.x += e0[n]; vv.y += e0[n+1];
            }
            *(float2*)(Cp + idx) = vv;
        }
    }
}

// ---------------------------------------------------------------------------
// ddlerp MIX GEMM (K=32) with fused epilogue: f=0 -> fp32 xx0;
// f=1..4 -> bf16 hi/lo branch-input arrays.
// ---------------------------------------------------------------------------
__global__ void __launch_bounds__(256) mix_gemm(
    const float* __restrict__ lorap, const float* __restrict__ BloraT,
    const float* __restrict__ x, const float* __restrict__ dxa,
    const float* __restrict__ lam,
    float* __restrict__ xx0,
    __nv_bfloat16* __restrict__ abh, __nv_bfloat16* __restrict__ abl)
{
    __shared__ __align__(16) float As2[8][256];
    __shared__ __align__(16) float Bs [8][128];

    int f = blockIdx.z;
    const float* A  = lorap  + f*32;
    const float* Bm = BloraT + f*32768;
    const float* e2 = lam    + f*Cq;

    int tid  = threadIdx.x;
    int m0   = blockIdx.y * 128, n0 = blockIdx.x * 128;
    int lrow = tid >> 1;
    int lkq  = (tid & 1) * 4;
    const float* Ap = A  + (size_t)(m0 + lrow) * 256 + lkq;
    const float* Bp = Bm + (size_t)(n0 + lrow) * 32  + lkq;
    int ty = tid >> 4, tx = tid & 15;

    ull acc[8][4];
    #pragma unroll
    for (int i = 0; i < 8; i++)
        #pragma unroll
        for (int p = 0; p < 4; p++) acc[i][p] = 0ull;

    for (int k0 = 0; k0 < 32; k0 += 8) {
        float4 av = *(const float4*)(Ap + k0);
        float4 bv = *(const float4*)(Bp + k0);
        *(float2*)&As2[lkq+0][2*lrow] = make_float2(av.x, av.x);
        *(float2*)&As2[lkq+1][2*lrow] = make_float2(av.y, av.y);
        *(float2*)&As2[lkq+2][2*lrow] = make_float2(av.z, av.z);
        *(float2*)&As2[lkq+3][2*lrow] = make_float2(av.w, av.w);
        Bs[lkq+0][lrow] = bv.x;
        Bs[lkq+1][lrow] = bv.y;
        Bs[lkq+2][lrow] = bv.z;
        Bs[lkq+3][lrow] = bv.w;
        __syncthreads();
        #pragma unroll
        for (int kk = 0; kk < 8; kk++) {
            const ull* ar = (const ull*)As2[kk];
            const ull* br = (const ull*)Bs[kk];
            ull a_[8], b_[4];
            #pragma unroll
            for (int i = 0; i < 8; i++) a_[i] = ar[ty*8 + i];
            #pragma unroll
            for (int p = 0; p < 4; p++) b_[p] = br[tx*4 + p];
            #pragma unroll
            for (int i = 0; i < 8; i++)
                #pragma unroll
                for (int p = 0; p < 4; p++) fma2(acc[i][p], a_[i], b_[p]);
        }
        __syncthreads();
    }

    #pragma unroll
    for (int i = 0; i < 8; i++) {
        size_t m = (size_t)(m0 + ty*8 + i);
        #pragma unroll
        for (int p = 0; p < 4; p++) {
            float2 vv = unp(acc[i][p]);
            int n = n0 + tx*8 + 2*p;
            size_t idx = m * (size_t)Cq + n;
            float vx = x[idx]   + dxa[idx]   * (e2[n]   + vv.x);
            float vy = x[idx+1] + dxa[idx+1] * (e2[n+1] + vv.y);
            if (f == 0) {
                *(float2*)(xx0 + idx) = make_float2(vx, vy);
            } else {
                size_t o = (size_t)(f-1) * SZq + idx;
                __nv_bfloat16 hx = __float2bfloat16(vx);
                __nv_bfloat16 hy = __float2bfloat16(vy);
                float lx = vx - __bfloat162float(hx);
                float ly = vy - __bfloat162float(hy);
                __nv_bfloat162 hp; hp.x = hx; hp.y = hy;
                __nv_bfloat162 lp; lp.x = __float2bfloat16(lx); lp.y = __float2bfloat16(ly);
                *(__nv_bfloat162*)(abh + o) = hp;
                *(__nv_bfloat162*)(abl + o) = lp;
            }
        }
    }
}

// ---------------------------------------------------------------------------
// prep: dxa = shift(x) - x ; xm = x + dxa * miu_x
// ---------------------------------------------------------------------------
__global__ void __launch_bounds__(256) prep_kernel(
    const float4* __restrict__ x4, const float4* __restrict__ mu4,
    float4* __restrict__ dxa4, float4* __restrict__ xm4)
{
    size_t i = (size_t)blockIdx.x * 256 + threadIdx.x;
    int m = (int)(i >> 8);
    int t = m & (Tq - 1);
    float4 xv = x4[i];
    float4 xl = make_float4(0.f, 0.f, 0.f, 0.f);
    if (t) xl = x4[i - 256];
    float4 mu = mu4[i & 255];
    float4 d  = make_float4(xl.x - xv.x, xl.y - xv.y, xl.z - xv.z, xl.w - xv.w);
    float4 xm = make_float4(fmaf(d.x, mu.x, xv.x), fmaf(d.y, mu.y, xv.y),
                            fmaf(d.z, mu.z, xv.z), fmaf(d.w, mu.w, xv.w));
    dxa4[i] = d;
    xm4[i]  = xm;
}

// ---------------------------------------------------------------------------
// All weight transposes in one kernel (flat-indexed ranges)
// ---------------------------------------------------------------------------
__global__ void __launch_bounds__(256) transpose_all(
    float* __restrict__ AloraT, const float* __restrict__ A_lora,
    float* __restrict__ tdAT,   const float* __restrict__ td_A,
    float* __restrict__ tdBT,   const float* __restrict__ td_B,
    float* __restrict__ BloraT, const float* __restrict__ B_lora)
{
    int i = blockIdx.x * 256 + threadIdx.x;
    if (i < 262144) {                       // AloraT[n*1024+k] (256x1024), pad n>=160
        int n = i >> 10, k = i & 1023;
        AloraT[i] = (n < 160) ? A_lora[k*160 + n] : 0.f;
    } else if (i < 393216) {                // tdAT[n*1024+k] (128x1024), pad n>=64
        int j = i - 262144; int n = j >> 10, k = j & 1023;
        tdAT[j] = (n < 64) ? td_A[k*64 + n] : 0.f;
    } else if (i < 458752) {                // tdBT[n*64+k] (1024x64)
        int j = i - 393216; int n = j >> 6, k = j & 63;
        tdBT[j] = td_B[k*1024 + n];
    } else if (i < 622592) {                // BloraT[f][n*32+k] (5x1024x32)
        int j = i - 458752;
        int f = j >> 15, rr = j & 32767, n = rr >> 5, k = rr & 31;
        BloraT[j] = B_lora[(f*32 + k)*1024 + n];
    }
}

// ---------------------------------------------------------------------------
// Weight bf16 hi/lo conversion (Wk,Wv,Wr,Wg,Wo)
// ---------------------------------------------------------------------------
__global__ void __launch_bounds__(256) wconv_kernel(
    const float* __restrict__ w0, const float* __restrict__ w1,
    const float* __restrict__ w2, const float* __restrict__ w3,
    const float* __restrict__ w4,
    __nv_bfloat16* __restrict__ h, __nv_bfloat16* __restrict__ l)
{
    int i = blockIdx.x * 256 + threadIdx.x;   // < 5 * 2^20
    int w = i >> 20;
    int j = i & 1048575;
    const float* src = (w == 0) ? w0 : (w == 1) ? w1 : (w == 2) ? w2 : (w == 3) ? w3 : w4;
    float x = src[j];
    __nv_bfloat16 hh = __float2bfloat16(x);
    float lo = x - __bfloat162float(hh);
    h[i] = hh;
    l[i] = __float2bfloat16(lo);
}

// ---------------------------------------------------------------------------
// WKV6 scan (unchanged, proven)
// ---------------------------------------------------------------------------
__global__ void __launch_bounds__(256) wkv6_kernel(
    const float* __restrict__ rp, const float* __restrict__ kp,
    const float* __restrict__ vp, const float* __restrict__ wp,
    const float* __restrict__ up, float* __restrict__ yp)
{
    __shared__ float4 pk[2][4][17];
    __shared__ float  sv[2][64];
    int bh = blockIdx.x;
    int b = bh >> 4, h = bh & 15;
    size_t base = ((size_t)b * Tq) * Cq + h * 64;
    int tid = threadIdx.x;
    int j = tid >> 2, rg = tid & 3;
    float uu = 0.f;
    if (tid < 64) uu = up[h * 64 + tid];
    float S[16];
    #pragma unroll
    for (int i = 0; i < 16; i++) S[i] = 0.f;

    for (int t = 0; t < Tq; t++) {
        int buf = t & 1;
        size_t off = base + (size_t)t * Cq;
        if (tid < 64) {
            float kk = kp[off + tid];
            float rr = rp[off + tid];
            float ww = wp[off + tid];
            sv[buf][tid] = vp[off + tid];
            float dd = expf(-expf(ww));
            pk[buf][tid >> 4][tid & 15] = make_float4(kk, uu * kk, rr, dd);
        }
        __syncthreads();
        float vj = sv[buf][j];
        float yv = 0.f;
        #pragma unroll
        for (int ii = 0; ii < 16; ii++) {
            float4 p = pk[buf][rg][ii];
            float s = S[ii];
            yv = fmaf(p.z, fmaf(p.y, vj, s), yv);
            S[ii] = fmaf(p.w, s, p.x * vj);
        }
        yv += __shfl_xor_sync(0xffffffffu, yv, 1);
        yv += __shfl_xor_sync(0xffffffffu, yv, 2);
        if (rg == 0) yp[off + j] = yv;
    }
}

// ---------------------------------------------------------------------------
// GroupNorm * gate, outputs bf16 hi/lo for the Wo GEMM
// ---------------------------------------------------------------------------
__global__ void __launch_bounds__(256) gnorm_kernel(
    const float* __restrict__ y, const float* __restrict__ g,
    const float* __restrict__ gamma, const float* __restrict__ beta,
    __nv_bfloat16* __restrict__ ygh, __nv_bfloat16* __restrict__ ygl)
{
    int m = blockIdx.x, tid = threadIdx.x;
    size_t i4 = (size_t)m * 256 + tid;
    float4 yv = ((const float4*)y)[i4];
    float s  = yv.x + yv.y + yv.z + yv.w;
    float ss = yv.x*yv.x + yv.y*yv.y + yv.z*yv.z + yv.w*yv.w;
    #pragma unroll
    for (int o = 1; o < 16; o <<= 1) {
        s  += __shfl_xor_sync(0xffffffffu, s,  o);
        ss += __shfl_xor_sync(0xffffffffu, ss, o);
    }
    float mean = s * (1.f / 64.f);
    float var  = ss * (1.f / 64.f) - mean * mean;
    float rstd = rsqrtf(fmaxf(var, 0.f) + 1.6e-4f);
    float4 ga = ((const float4*)gamma)[tid];
    float4 be = ((const float4*)beta)[tid];
    float4 gv = ((const float4*)g)[i4];
    float o0 = ((yv.x - mean) * rstd * ga.x + be.x) * gv.x;
    float o1 = ((yv.y - mean) * rstd * ga.y + be.y) * gv.y;
    float o2 = ((yv.z - mean) * rstd * ga.z + be.z) * gv.z;
    float o3 = ((yv.w - mean) * rstd * ga.w + be.w) * gv.w;

    __nv_bfloat16 h0 = __float2bfloat16(o0), h1 = __float2bfloat16(o1);
    __nv_bfloat16 h2 = __float2bfloat16(o2), h3 = __float2bfloat16(o3);
    __nv_bfloat162 hp0; hp0.x = h0; hp0.y = h1;
    __nv_bfloat162 hp1; hp1.x = h2; hp1.y = h3;
    __nv_bfloat162 lp0;
    lp0.x = __float2bfloat16(o0 - __bfloat162float(h0));
    lp0.y = __float2bfloat16(o1 - __bfloat162float(h1));
    __nv_bfloat162 lp1;
    lp1.x = __float2bfloat16(o2 - __bfloat162float(h2));
    lp1.y = __float2bfloat16(o3 - __bfloat162float(h3));
    ((__nv_bfloat162*)ygh)[i4*2]   = hp0;
    ((__nv_bfloat162*)ygh)[i4*2+1] = hp1;
    ((__nv_bfloat162*)ygl)[i4*2]   = lp0;
    ((__nv_bfloat162*)ygl)[i4*2+1] = lp1;
}

// ---------------------------------------------------------------------------
// Launch
// ---------------------------------------------------------------------------
extern "C" void kernel_launch(void* const* d_in, const int* in_sizes, int n_in,
                              void* d_out, int out_size)
{
    (void)in_sizes; (void)n_in; (void)out_size;
    const float* x       = (const float*)d_in[0];
    const float* miu_x   = (const float*)d_in[1];
    const float* lambda_ = (const float*)d_in[2];
    const float* A_lora  = (const float*)d_in[3];
    const float* B_lora  = (const float*)d_in[4];
    const float* td_miu  = (const float*)d_in[5];
    const float* td_A    = (const float*)d_in[6];
    const float* td_B    = (const float*)d_in[7];
    const float* u       = (const float*)d_in[8];
    const float* Wr      = (const float*)d_in[9];
    const float* Wk      = (const float*)d_in[10];
    const float* Wv      = (const float*)d_in[11];
    const float* Wg      = (const float*)d_in[12];
    const float* Wo      = (const float*)d_in[13];
    const float* gamma   = (const float*)d_in[14];
    const float* beta    = (const float*)d_in[15];
    float* out = (float*)d_out;

    float *p_dxa,*p_xm,*p_xx0,*p_k,*p_v,*p_r,*p_g,*p_w,*p_y,
          *p_lorap,*p_tdhp,*p_AloraT,*p_tdAT,*p_tdBT,*p_BloraT;
    __nv_bfloat16 *p_abh,*p_abl,*p_ygh,*p_ygl,*p_wbh,*p_wbl;
    { void* t;
      cudaGetSymbolAddress(&t, g_dxa);    p_dxa    = (float*)t;
      cudaGetSymbolAddress(&t, g_xm);     p_xm     = (float*)t;
      cudaGetSymbolAddress(&t, g_xx0);    p_xx0    = (float*)t;
      cudaGetSymbolAddress(&t, g_k);      p_k      = (float*)t;
      cudaGetSymbolAddress(&t, g_v);      p_v      = (float*)t;
      cudaGetSymbolAddress(&t, g_r);      p_r      = (float*)t;
      cudaGetSymbolAddress(&t, g_g);      p_g      = (float*)t;
      cudaGetSymbolAddress(&t, g_w);      p_w      = (float*)t;
      cudaGetSymbolAddress(&t, g_y);      p_y      = (float*)t;
      cudaGetSymbolAddress(&t, g_lorap);  p_lorap  = (float*)t;
      cudaGetSymbolAddress(&t, g_tdhp);   p_tdhp   = (float*)t;
      cudaGetSymbolAddress(&t, g_AloraT); p_AloraT = (float*)t;
      cudaGetSymbolAddress(&t, g_tdAT);   p_tdAT   = (float*)t;
      cudaGetSymbolAddress(&t, g_tdBT);   p_tdBT   = (float*)t;
      cudaGetSymbolAddress(&t, g_BloraT); p_BloraT = (float*)t;
      cudaGetSymbolAddress(&t, g_abh);    p_abh    = (__nv_bfloat16*)t;
      cudaGetSymbolAddress(&t, g_abl);    p_abl    = (__nv_bfloat16*)t;
      cudaGetSymbolAddress(&t, g_ygh);    p_ygh    = (__nv_bfloat16*)t;
      cudaGetSymbolAddress(&t, g_ygl);    p_ygl    = (__nv_bfloat16*)t;
      cudaGetSymbolAddress(&t, g_wbh);    p_wbh    = (__nv_bfloat16*)t;
      cudaGetSymbolAddress(&t, g_wbl);    p_wbl    = (__nv_bfloat16*)t;
    }

    cudaFuncSetAttribute(hgemm<0>, cudaFuncAttributeMaxDynamicSharedMemorySize, HG_SMEM);
    cudaFuncSetAttribute(hgemm<1>, cudaFuncAttributeMaxDynamicSharedMemorySize, HG_SMEM);

    dim3 tg(8, 128);   // N/128, M/128

    // 0: token shift + static lerp
    prep_kernel<<<BTq * Cq / 4 / 256, 256>>>((const float4*)x, (const float4*)miu_x,
                                             (float4*)p_dxa, (float4*)p_xm);
    // 1: weight transposes
    transpose_all<<<(622592 + 255) / 256, 256>>>(p_AloraT, A_lora, p_tdAT, td_A,
                                                 p_tdBT, td_B, p_BloraT, B_lora);
    // 2: weight bf16 hi/lo   (order: Wk,Wv,Wr,Wg,Wo)
    wconv_kernel<<<5 * 1048576 / 256, 256>>>(Wk, Wv, Wr, Wg, Wo, p_wbh, p_wbl);
    // 3: lora_h = tanh(xm @ A_lora)
    sgemm_nt<EPI_TANH><<<dim3(2, 128), 256>>>(p_xm, Cq, p_AloraT, 1024,
                                              p_lorap, 256, 1024, nullptr);
    // 4: ddlerp mix (all 5 branches; k/v/r/g out as bf16 hi/lo)
    mix_gemm<<<dim3(8, 128, 5), 256>>>(p_lorap, p_BloraT, x, p_dxa, lambda_,
                                       p_xx0, p_abh, p_abl);
    // 5-8: tensor-core (mma.sync) projections (k, v, r, g)
    hgemm<0><<<tg, 256, HG_SMEM>>>(p_abh + 0*SZq, p_abl + 0*SZq, p_wbh + 0*WWq, p_wbl + 0*WWq, p_k, BTq, Cq, Cq);
    hgemm<0><<<tg, 256, HG_SMEM>>>(p_abh + 1*SZq, p_abl + 1*SZq, p_wbh + 1*WWq, p_wbl + 1*WWq, p_v, BTq, Cq, Cq);
    hgemm<0><<<tg, 256, HG_SMEM>>>(p_abh + 2*SZq, p_abl + 2*SZq, p_wbh + 2*WWq, p_wbl + 2*WWq, p_r, BTq, Cq, Cq);
    hgemm<1><<<tg, 256, HG_SMEM>>>(p_abh + 3*SZq, p_abl + 3*SZq, p_wbh + 3*WWq, p_wbl + 3*WWq, p_g, BTq, Cq, Cq);
    // 9-10: time-decay lora
    sgemm_nt<EPI_TANH><<<dim3(1, 128), 256>>>(p_xx0, Cq, p_tdAT, 1024,
                                              p_tdhp, 128, 1024, nullptr);
    sgemm_nt<EPI_BIAS><<<dim3(8, 128), 256>>>(p_tdhp, 128, p_tdBT, 64,
                                              p_w, Cq, 64, td_miu);
    // 11: WKV6 scan
    wkv6_kernel<<<Bq * Hq, 256>>>(p_r, p_k, p_v, p_w, u, p_y);
    // 12: GroupNorm * gate -> bf16 hi/lo
    gnorm_kernel<<<BTq, 256>>>(p_y, p_g, gamma, beta, p_ygh, p_ygl);
    // 13: output projection
    hgemm<0><<<tg, 256, HG_SMEM>>>(p_ygh, p_ygl, p_wbh + 4*WWq, p_wbl + 4*WWq, out, BTq, Cq, Cq);
}

// round 5
// speedup vs baseline: 1.8509x; 1.0764x over previous
#include <cuda_runtime.h>
#include <cuda_bf16.h>
#include <math.h>
#include <stdint.h>

#define Bq 8
#define Tq 2048
#define Cq 1024
#define Hq 16
#define BTq (Bq*Tq)
#define WWq (Cq*Cq)

typedef unsigned long long ull;
static const size_t SZq = (size_t)BTq * Cq;

// ---------------------------------------------------------------------------
// Scratch (static device globals — no runtime allocation)
// ---------------------------------------------------------------------------
__device__ float g_dxa [BTq*Cq];
__device__ float g_xx0 [BTq*Cq];             // w_in branch (fp32 — precision-critical)
__device__ float g_k   [BTq*Cq];
__device__ float g_v   [BTq*Cq];
__device__ float g_r   [BTq*Cq];
__device__ float g_g   [BTq*Cq];
__device__ float g_w   [BTq*Cq];
__device__ float g_y   [BTq*Cq];
__device__ float g_lorap [BTq*256];          // tanh(xm @ A_lora) fp32 (padded 256)
__device__ float g_tdhp  [BTq*128];          // tanh(w_in @ td_A) fp32 (padded 128)
__device__ float g_BloraT[5*1024*32];        // B_lora^T per branch, fp32
__device__ float g_tdAT  [128*1024];         // td_A^T zero-padded fp32
__device__ float g_tdBT  [1024*64];          // td_B^T fp32

__device__ __nv_bfloat16 g_xmh[BTq*Cq];      // xm hi/lo
__device__ __nv_bfloat16 g_xml[BTq*Cq];
__device__ __nv_bfloat16 g_abh[4*BTq*Cq];    // k,v,r,g branch inputs hi
__device__ __nv_bfloat16 g_abl[4*BTq*Cq];    // lo
__device__ __nv_bfloat16 g_ygh[BTq*Cq];
__device__ __nv_bfloat16 g_ygl[BTq*Cq];
__device__ __nv_bfloat16 g_wbh[5*WWq];       // Wk,Wv,Wr,Wg,Wo hi
__device__ __nv_bfloat16 g_wbl[5*WWq];       // lo
__device__ __nv_bfloat16 g_AloraTh[256*1024];
__device__ __nv_bfloat16 g_AloraTl[256*1024];

// ---------------------------------------------------------------------------
// PTX helpers (sm_80+ — valid on compute_103 virtual arch)
// ---------------------------------------------------------------------------
__device__ __forceinline__ uint32_t sm2u32(const void* p){
    uint32_t a;
    asm("{ .reg .u64 t; cvta.to.shared.u64 t, %1; cvt.u32.u64 %0, t; }" : "=r"(a) : "l"(p));
    return a;
}
__device__ __forceinline__ void cpa16(uint32_t dst, const void* src){
    asm volatile("cp.async.cg.shared.global [%0], [%1], 16;" :: "r"(dst), "l"(src) : "memory");
}
__device__ __forceinline__ void cpa_commit(){
    asm volatile("cp.async.commit_group;" ::: "memory");
}
template<int N>
__device__ __forceinline__ void cpa_wait(){
    asm volatile("cp.async.wait_group %0;" :: "n"(N) : "memory");
}
__device__ __forceinline__ void ldsm_x4(uint32_t* r, uint32_t addr){
    asm volatile("ldmatrix.sync.aligned.m8n8.x4.shared.b16 {%0,%1,%2,%3}, [%4];"
        : "=r"(r[0]), "=r"(r[1]), "=r"(r[2]), "=r"(r[3]) : "r"(addr));
}
__device__ __forceinline__ void mma_bf16(float* d, const uint32_t* a, const uint32_t* b){
    asm volatile("mma.sync.aligned.m16n8k16.row.col.f32.bf16.bf16.f32 "
        "{%0,%1,%2,%3}, {%4,%5,%6,%7}, {%8,%9}, {%0,%1,%2,%3};"
        : "+f"(d[0]), "+f"(d[1]), "+f"(d[2]), "+f"(d[3])
        : "r"(a[0]), "r"(a[1]), "r"(a[2]), "r"(a[3]), "r"(b[0]), "r"(b[1]));
}
__device__ __forceinline__ void split_bf(float v, __nv_bfloat16& h, __nv_bfloat16& l){
    h = __float2bfloat16(v);
    l = __float2bfloat16(v - __bfloat162float(h));
}

// ---------------------------------------------------------------------------
// bf16-split GEMM via mma.sync: C[M,N] = (Ah+Al)[M,K] @ (Bh+Bl)[N,K]^T
// 128x128 tile, BK=32, 2-stage cp.async pipeline, 8 warps (2x4), warp 64x32.
// EPI: 0 none, 1 silu, 2 tanh->fp32
// ---------------------------------------------------------------------------
#define HG_STAGE  40960
#define HG_ARR    10240
#define HG_SMEM   (2 * HG_STAGE)

template<int EPI>
__global__ void __launch_bounds__(256) hgemm(
    const __nv_bfloat16* __restrict__ Ah, const __nv_bfloat16* __restrict__ Al,
    const __nv_bfloat16* __restrict__ Bh, const __nv_bfloat16* __restrict__ Bl,
    float* __restrict__ Cp, int M, int N, int K)
{
    extern __shared__ char sm[];
    int tid = threadIdx.x, lane = tid & 31, wid = tid >> 5;
    int wy = wid & 1, wx = wid >> 1;
    int m0 = blockIdx.y * 128, n0 = blockIdx.x * 128;
    uint32_t sb = sm2u32(sm);

    const __nv_bfloat16* gptr[8];
    uint32_t soff[8];
    #pragma unroll
    for (int t = 0; t < 8; t++){
        int idx = t * 256 + tid;
        int arr = idx >> 9;
        int rem = idx & 511;
        int row = rem >> 2, ch = rem & 3;
        size_t go = (arr < 2) ? ((size_t)(m0 + row) * K + ch * 8)
                              : ((size_t)(n0 + row) * K + ch * 8);
        const __nv_bfloat16* base = (arr == 0) ? Ah : (arr == 1) ? Al : (arr == 2) ? Bh : Bl;
        gptr[t] = base + go;
        soff[t] = (uint32_t)(arr * HG_ARR + row * 80 + ch * 16);
    }

    float acc[4][4][4];
    #pragma unroll
    for (int i = 0; i < 4; i++)
        #pragma unroll
        for (int j = 0; j < 4; j++)
            #pragma unroll
            for (int q = 0; q < 4; q++) acc[i][j][q] = 0.f;

    uint32_t a_row = (uint32_t)(wy * 64 + (lane & 15));
    uint32_t a_kh  = (uint32_t)((lane >> 4) * 8);
    uint32_t b_row0 = (uint32_t)(wx * 32 + (lane & 7) + ((lane >> 4) * 8));
    uint32_t b_kh   = (uint32_t)(((lane >> 3) & 1) * 8);

    const int NC = K >> 5;

    #pragma unroll
    for (int t = 0; t < 8; t++) cpa16(sb + soff[t], gptr[t]);
    cpa_commit();

    for (int c = 0; c < NC; c++){
        int buf = c & 1;
        if (c + 1 < NC){
            int nb = buf ^ 1;
            uint32_t db = sb + (uint32_t)nb * HG_STAGE;
            #pragma unroll
            for (int t = 0; t < 8; t++) cpa16(db + soff[t], gptr[t] + (size_t)(c + 1) * 32);
            cpa_commit();
            cpa_wait<1>();
        } else {
            cpa_wait<0>();
        }
        __syncthreads();

        uint32_t base = sb + (uint32_t)buf * HG_STAGE;
        #pragma unroll
        for (int ks = 0; ks < 2; ks++){
            uint32_t ah[4][4], al[4][4], bh[2][4], bl[2][4];
            uint32_t akh = (uint32_t)(ks * 16) + a_kh;
            #pragma unroll
            for (int mf = 0; mf < 4; mf++){
                uint32_t ao = base + (a_row + mf * 16) * 80 + akh * 2;
                ldsm_x4(ah[mf], ao);
                ldsm_x4(al[mf], ao + HG_ARR);
            }
            uint32_t bkh = (uint32_t)(ks * 16) + b_kh;
            #pragma unroll
            for (int bi = 0; bi < 2; bi++){
                uint32_t bo = base + 2*HG_ARR + (b_row0 + bi * 16) * 80 + bkh * 2;
                ldsm_x4(bh[bi], bo);
                ldsm_x4(bl[bi], bo + HG_ARR);
            }
            #pragma unroll
            for (int mf = 0; mf < 4; mf++)
                #pragma unroll
                for (int nf = 0; nf < 4; nf++){
                    const uint32_t* bhp = &bh[nf >> 1][(nf & 1) * 2];
                    const uint32_t* blp = &bl[nf >> 1][(nf & 1) * 2];
                    mma_bf16(acc[mf][nf], ah[mf], bhp);
                    mma_bf16(acc[mf][nf], ah[mf], blp);
                    mma_bf16(acc[mf][nf], al[mf], bhp);
                }
        }
        __syncthreads();
    }

    #pragma unroll
    for (int mf = 0; mf < 4; mf++){
        int row0 = m0 + wy * 64 + mf * 16 + (lane >> 2);
        #pragma unroll
        for (int nf = 0; nf < 4; nf++){
            int col = n0 + wx * 32 + nf * 8 + (lane & 3) * 2;
            float v[4] = {acc[mf][nf][0], acc[mf][nf][1], acc[mf][nf][2], acc[mf][nf][3]};
            if (EPI == 1){
                #pragma unroll
                for (int q = 0; q < 4; q++) v[q] = v[q] / (1.f + expf(-v[q]));
            } else if (EPI == 2){
                #pragma unroll
                for (int q = 0; q < 4; q++) v[q] = tanhf(v[q]);
            }
            *(float2*)(Cp + (size_t)row0 * N + col)       = make_float2(v[0], v[1]);
            *(float2*)(Cp + (size_t)(row0 + 8) * N + col) = make_float2(v[2], v[3]);
        }
    }
}

// ---------------------------------------------------------------------------
// FFMA2 helpers + fp32 SGEMM (precision-critical td path; proven round-1 code)
// ---------------------------------------------------------------------------
__device__ __forceinline__ void fma2(ull& d, ull a, ull b){
    asm("fma.rn.f32x2 %0, %1, %2, %0;" : "+l"(d) : "l"(a), "l"(b));
}
__device__ __forceinline__ float2 unp(ull v){
    float2 r; asm("mov.b64 {%0, %1}, %2;" : "=f"(r.x), "=f"(r.y) : "l"(v)); return r;
}

#define EPI_TANH 2
#define EPI_BIAS 3

template<int EPI>
__global__ void __launch_bounds__(256) sgemm_nt(
    const float* __restrict__ A, int lda,
    const float* __restrict__ Bm, int ldb,
    float* __restrict__ Cp, int N, int K,
    const float* __restrict__ e0)
{
    __shared__ __align__(16) float As2[8][256];
    __shared__ __align__(16) float Bs [8][128];

    int tid  = threadIdx.x;
    int m0   = blockIdx.y * 128, n0 = blockIdx.x * 128;
    int lrow = tid >> 1;
    int lkq  = (tid & 1) * 4;
    const float* Ap = A  + (size_t)(m0 + lrow) * lda + lkq;
    const float* Bp = Bm + (size_t)(n0 + lrow) * ldb + lkq;
    int ty = tid >> 4, tx = tid & 15;

    ull acc[8][4];
    #pragma unroll
    for (int i = 0; i < 8; i++)
        #pragma unroll
        for (int p = 0; p < 4; p++) acc[i][p] = 0ull;

    for (int k0 = 0; k0 < K; k0 += 8) {
        float4 av = *(const float4*)(Ap + k0);
        float4 bv = *(const float4*)(Bp + k0);
        *(float2*)&As2[lkq+0][2*lrow] = make_float2(av.x, av.x);
        *(float2*)&As2[lkq+1][2*lrow] = make_float2(av.y, av.y);
        *(float2*)&As2[lkq+2][2*lrow] = make_float2(av.z, av.z);
        *(float2*)&As2[lkq+3][2*lrow] = make_float2(av.w, av.w);
        Bs[lkq+0][lrow] = bv.x;
        Bs[lkq+1][lrow] = bv.y;
        Bs[lkq+2][lrow] = bv.z;
        Bs[lkq+3][lrow] = bv.w;
        __syncthreads();
        #pragma unroll
        for (int kk = 0; kk < 8; kk++) {
            const ull* ar = (const ull*)As2[kk];
            const ull* br = (const ull*)Bs[kk];
            ull a_[8], b_[4];
            #pragma unroll
            for (int i = 0; i < 8; i++) a_[i] = ar[ty*8 + i];
            #pragma unroll
            for (int p = 0; p < 4; p++) b_[p] = br[tx*4 + p];
            #pragma unroll
            for (int i = 0; i < 8; i++)
                #pragma unroll
                for (int p = 0; p < 4; p++) fma2(acc[i][p], a_[i], b_[p]);
        }
        __syncthreads();
    }

    #pragma unroll
    for (int i = 0; i < 8; i++) {
        size_t m = (size_t)(m0 + ty*8 + i);
        #pragma unroll
        for (int p = 0; p < 4; p++) {
            float2 vv = unp(acc[i][p]);
            int n = n0 + tx*8 + 2*p;
            size_t idx = m * (size_t)N + n;
            if (EPI == EPI_TANH) {
                vv.x = tanhf(vv.x); vv.y = tanhf(vv.y);
            } else if (EPI == EPI_BIAS) {
                vv.x += e0[n]; vv.y += e0[n+1];
            }
            *(float2*)(Cp + idx) = vv;
        }
    }
}

// ---------------------------------------------------------------------------
// ddlerp MIX GEMM (K=32), f = blockIdx.x (fastest) for L2 reuse of x/dxa.
// f=0 -> fp32 xx0 (w_in, precision-critical); f=1..4 -> bf16 hi/lo slots 0..3.
// ---------------------------------------------------------------------------
__global__ void __launch_bounds__(256) mix_gemm(
    const float* __restrict__ lorap, const float* __restrict__ BloraT,
    const float* __restrict__ x, const float* __restrict__ dxa,
    const float* __restrict__ lam,
    float* __restrict__ xx0,
    __nv_bfloat16* __restrict__ abh, __nv_bfloat16* __restrict__ abl)
{
    __shared__ __align__(16) float As2[8][256];
    __shared__ __align__(16) float Bs [8][128];

    int f = blockIdx.x;
    const float* A  = lorap  + f*32;
    const float* Bm = BloraT + f*32768;
    const float* e2 = lam    + f*Cq;

    int tid  = threadIdx.x;
    int m0   = blockIdx.y * 128, n0 = blockIdx.z * 128;
    int lrow = tid >> 1;
    int lkq  = (tid & 1) * 4;
    const float* Ap = A  + (size_t)(m0 + lrow) * 256 + lkq;
    const float* Bp = Bm + (size_t)(n0 + lrow) * 32  + lkq;
    int ty = tid >> 4, tx = tid & 15;

    ull acc[8][4];
    #pragma unroll
    for (int i = 0; i < 8; i++)
        #pragma unroll
        for (int p = 0; p < 4; p++) acc[i][p] = 0ull;

    for (int k0 = 0; k0 < 32; k0 += 8) {
        float4 av = *(const float4*)(Ap + k0);
        float4 bv = *(const float4*)(Bp + k0);
        *(float2*)&As2[lkq+0][2*lrow] = make_float2(av.x, av.x);
        *(float2*)&As2[lkq+1][2*lrow] = make_float2(av.y, av.y);
        *(float2*)&As2[lkq+2][2*lrow] = make_float2(av.z, av.z);
        *(float2*)&As2[lkq+3][2*lrow] = make_float2(av.w, av.w);
        Bs[lkq+0][lrow] = bv.x;
        Bs[lkq+1][lrow] = bv.y;
        Bs[lkq+2][lrow] = bv.z;
        Bs[lkq+3][lrow] = bv.w;
        __syncthreads();
        #pragma unroll
        for (int kk = 0; kk < 8; kk++) {
            const ull* ar = (const ull*)As2[kk];
            const ull* br = (const ull*)Bs[kk];
            ull a_[8], b_[4];
            #pragma unroll
            for (int i = 0; i < 8; i++) a_[i] = ar[ty*8 + i];
            #pragma unroll
            for (int p = 0; p < 4; p++) b_[p] = br[tx*4 + p];
            #pragma unroll
            for (int i = 0; i < 8; i++)
                #pragma unroll
                for (int p = 0; p < 4; p++) fma2(acc[i][p], a_[i], b_[p]);
        }
        __syncthreads();
    }

    #pragma unroll
    for (int i = 0; i < 8; i++) {
        size_t m = (size_t)(m0 + ty*8 + i);
        #pragma unroll
        for (int p = 0; p < 4; p++) {
            float2 vv = unp(acc[i][p]);
            int n = n0 + tx*8 + 2*p;
            size_t idx = m * (size_t)Cq + n;
            float vx = x[idx]   + dxa[idx]   * (e2[n]   + vv.x);
            float vy = x[idx+1] + dxa[idx+1] * (e2[n+1] + vv.y);
            if (f == 0) {
                *(float2*)(xx0 + idx) = make_float2(vx, vy);
            } else {
                size_t o = (size_t)(f-1) * SZq + idx;
                __nv_bfloat162 hp, lp;
                split_bf(vx, hp.x, lp.x);
                split_bf(vy, hp.y, lp.y);
                *(__nv_bfloat162*)(abh + o) = hp;
                *(__nv_bfloat162*)(abl + o) = lp;
            }
        }
    }
}

// ---------------------------------------------------------------------------
// prep: dxa = shift(x) - x (fp32) ; xm = x + dxa * miu_x -> bf16 hi/lo
// ---------------------------------------------------------------------------
__global__ void __launch_bounds__(256) prep_kernel(
    const float4* __restrict__ x4, const float4* __restrict__ mu4,
    float4* __restrict__ dxa4,
    __nv_bfloat16* __restrict__ xmh, __nv_bfloat16* __restrict__ xml)
{
    size_t i = (size_t)blockIdx.x * 256 + threadIdx.x;
    int m = (int)(i >> 8);
    int t = m & (Tq - 1);
    float4 xv = x4[i];
    float4 xl = make_float4(0.f, 0.f, 0.f, 0.f);
    if (t) xl = x4[i - 256];
    float4 mu = mu4[i & 255];
    float4 d  = make_float4(xl.x - xv.x, xl.y - xv.y, xl.z - xv.z, xl.w - xv.w);
    float xm0 = fmaf(d.x, mu.x, xv.x), xm1 = fmaf(d.y, mu.y, xv.y);
    float xm2 = fmaf(d.z, mu.z, xv.z), xm3 = fmaf(d.w, mu.w, xv.w);
    dxa4[i] = d;
    __nv_bfloat162 h0, l0, h1, l1;
    split_bf(xm0, h0.x, l0.x); split_bf(xm1, h0.y, l0.y);
    split_bf(xm2, h1.x, l1.x); split_bf(xm3, h1.y, l1.y);
    ((__nv_bfloat162*)xmh)[i*2]   = h0;
    ((__nv_bfloat162*)xmh)[i*2+1] = h1;
    ((__nv_bfloat162*)xml)[i*2]   = l0;
    ((__nv_bfloat162*)xml)[i*2+1] = l1;
}

// ---------------------------------------------------------------------------
// transposes: AloraT -> bf16 hi/lo; tdAT, tdBT, BloraT -> fp32
// ---------------------------------------------------------------------------
__global__ void __launch_bounds__(256) transpose_all(
    __nv_bfloat16* __restrict__ AloraTh, __nv_bfloat16* __restrict__ AloraTl,
    const float* __restrict__ A_lora,
    float* __restrict__ tdAT, const float* __restrict__ td_A,
    float* __restrict__ tdBT, const float* __restrict__ td_B,
    float* __restrict__ BloraT, const float* __restrict__ B_lora)
{
    int i = blockIdx.x * 256 + threadIdx.x;
    if (i < 262144) {
        int n = i >> 10, k = i & 1023;
        float v = (n < 160) ? A_lora[k*160 + n] : 0.f;
        __nv_bfloat16 h, l; split_bf(v, h, l);
        AloraTh[i] = h; AloraTl[i] = l;
    } else if (i < 393216) {
        int j = i - 262144; int n = j >> 10, k = j & 1023;
        tdAT[j] = (n < 64) ? td_A[k*64 + n] : 0.f;
    } else if (i < 458752) {
        int j = i - 393216; int n = j >> 6, k = j & 63;
        tdBT[j] = td_B[k*1024 + n];
    } else if (i < 622592) {
        int j = i - 458752;
        int f = j >> 15, rr = j & 32767, n = rr >> 5, k = rr & 31;
        BloraT[j] = B_lora[(f*32 + k)*1024 + n];
    }
}

// ---------------------------------------------------------------------------
// Weight bf16 hi/lo conversion (Wk,Wv,Wr,Wg,Wo)
// ---------------------------------------------------------------------------
__global__ void __launch_bounds__(256) wconv_kernel(
    const float* __restrict__ w0, const float* __restrict__ w1,
    const float* __restrict__ w2, const float* __restrict__ w3,
    const float* __restrict__ w4,
    __nv_bfloat16* __restrict__ h, __nv_bfloat16* __restrict__ l)
{
    int i = blockIdx.x * 256 + threadIdx.x;
    int w = i >> 20;
    int j = i & 1048575;
    const float* src = (w == 0) ? w0 : (w == 1) ? w1 : (w == 2) ? w2 : (w == 3) ? w3 : w4;
    float x = src[j];
    __nv_bfloat16 hh, ll; split_bf(x, hh, ll);
    h[i] = hh;
    l[i] = ll;
}

// ---------------------------------------------------------------------------
// WKV6 scan — software-pipelined: t+1 global loads overlap compute of t.
// ---------------------------------------------------------------------------
__global__ void __launch_bounds__(256) wkv6_kernel(
    const float* __restrict__ rp, const float* __restrict__ kp,
    const float* __restrict__ vp, const float* __restrict__ wp,
    const float* __restrict__ up, float* __restrict__ yp)
{
    __shared__ float4 pk[2][4][17];
    __shared__ float  sv[2][64];
    int bh = blockIdx.x;
    int b = bh >> 4, h = bh & 15;
    size_t base = ((size_t)b * Tq) * Cq + h * 64;
    int tid = threadIdx.x;
    int j = tid >> 2, rg = tid & 3;
    float uu = 0.f;
    if (tid < 64) uu = up[h * 64 + tid];
    float S[16];
    #pragma unroll
    for (int i = 0; i < 16; i++) S[i] = 0.f;

    float lk = 0.f, lr = 0.f, lw = 0.f, lv = 0.f;
    if (tid < 64){
        lk = kp[base + tid]; lr = rp[base + tid];
        lw = wp[base + tid]; lv = vp[base + tid];
    }

    for (int t = 0; t < Tq; t++) {
        int buf = t & 1;
        size_t off = base + (size_t)t * Cq;
        if (tid < 64) {
            sv[buf][tid] = lv;
            float dd = expf(-expf(lw));
            pk[buf][tid >> 4][tid & 15] = make_float4(lk, uu * lk, lr, dd);
        }
        __syncthreads();
        if (t + 1 < Tq && tid < 64){
            size_t o2 = off + Cq + tid;
            lk = kp[o2]; lr = rp[o2]; lw = wp[o2]; lv = vp[o2];
        }
        float vj = sv[buf][j];
        float yv = 0.f;
        #pragma unroll
        for (int ii = 0; ii < 16; ii++) {
            float4 p = pk[buf][rg][ii];
            float s = S[ii];
            yv = fmaf(p.z, fmaf(p.y, vj, s), yv);
            S[ii] = fmaf(p.w, s, p.x * vj);
        }
        yv += __shfl_xor_sync(0xffffffffu, yv, 1);
        yv += __shfl_xor_sync(0xffffffffu, yv, 2);
        if (rg == 0) yp[off + j] = yv;
    }
}

// ---------------------------------------------------------------------------
// GroupNorm * gate -> bf16 hi/lo
// ---------------------------------------------------------------------------
__global__ void __launch_bounds__(256) gnorm_kernel(
    const float* __restrict__ y, const float* __restrict__ g,
    const float* __restrict__ gamma, const float* __restrict__ beta,
    __nv_bfloat16* __restrict__ ygh, __nv_bfloat16* __restrict__ ygl)
{
    int m = blockIdx.x, tid = threadIdx.x;
    size_t i4 = (size_t)m * 256 + tid;
    float4 yv = ((const float4*)y)[i4];
    float s  = yv.x + yv.y + yv.z + yv.w;
    float ss = yv.x*yv.x + yv.y*yv.y + yv.z*yv.z + yv.w*yv.w;
    #pragma unroll
    for (int o = 1; o < 16; o <<= 1) {
        s  += __shfl_xor_sync(0xffffffffu, s,  o);
        ss += __shfl_xor_sync(0xffffffffu, ss, o);
    }
    float mean = s * (1.f / 64.f);
    float var  = ss * (1.f / 64.f) - mean * mean;
    float rstd = rsqrtf(fmaxf(var, 0.f) + 1.6e-4f);
    float4 ga = ((const float4*)gamma)[tid];
    float4 be = ((const float4*)beta)[tid];
    float4 gv = ((const float4*)g)[i4];
    float o0 = ((yv.x - mean) * rstd * ga.x + be.x) * gv.x;
    float o1 = ((yv.y - mean) * rstd * ga.y + be.y) * gv.y;
    float o2 = ((yv.z - mean) * rstd * ga.z + be.z) * gv.z;
    float o3 = ((yv.w - mean) * rstd * ga.w + be.w) * gv.w;

    __nv_bfloat162 hp0, lp0, hp1, lp1;
    split_bf(o0, hp0.x, lp0.x); split_bf(o1, hp0.y, lp0.y);
    split_bf(o2, hp1.x, lp1.x); split_bf(o3, hp1.y, lp1.y);
    ((__nv_bfloat162*)ygh)[i4*2]   = hp0;
    ((__nv_bfloat162*)ygh)[i4*2+1] = hp1;
    ((__nv_bfloat162*)ygl)[i4*2]   = lp0;
    ((__nv_bfloat162*)ygl)[i4*2+1] = lp1;
}

// ---------------------------------------------------------------------------
// Launch
// ---------------------------------------------------------------------------
extern "C" void kernel_launch(void* const* d_in, const int* in_sizes, int n_in,
                              void* d_out, int out_size)
{
    (void)in_sizes; (void)n_in; (void)out_size;
    const float* x       = (const float*)d_in[0];
    const float* miu_x   = (const float*)d_in[1];
    const float* lambda_ = (const float*)d_in[2];
    const float* A_lora  = (const float*)d_in[3];
    const float* B_lora  = (const float*)d_in[4];
    const float* td_miu  = (const float*)d_in[5];
    const float* td_A    = (const float*)d_in[6];
    const float* td_B    = (const float*)d_in[7];
    const float* u       = (const float*)d_in[8];
    const float* Wr      = (const float*)d_in[9];
    const float* Wk      = (const float*)d_in[10];
    const float* Wv      = (const float*)d_in[11];
    const float* Wg      = (const float*)d_in[12];
    const float* Wo      = (const float*)d_in[13];
    const float* gamma   = (const float*)d_in[14];
    const float* beta    = (const float*)d_in[15];
    float* out = (float*)d_out;

    float *p_dxa,*p_xx0,*p_k,*p_v,*p_r,*p_g,*p_w,*p_y,*p_lorap,*p_tdhp,
          *p_BloraT,*p_tdAT,*p_tdBT;
    __nv_bfloat16 *p_xmh,*p_xml,*p_abh,*p_abl,*p_ygh,*p_ygl,*p_wbh,*p_wbl,
                  *p_AloraTh,*p_AloraTl;
    { void* t;
      cudaGetSymbolAddress(&t, g_dxa);     p_dxa     = (float*)t;
      cudaGetSymbolAddress(&t, g_xx0);     p_xx0     = (float*)t;
      cudaGetSymbolAddress(&t, g_k);       p_k       = (float*)t;
      cudaGetSymbolAddress(&t, g_v);       p_v       = (float*)t;
      cudaGetSymbolAddress(&t, g_r);       p_r       = (float*)t;
      cudaGetSymbolAddress(&t, g_g);       p_g       = (float*)t;
      cudaGetSymbolAddress(&t, g_w);       p_w       = (float*)t;
      cudaGetSymbolAddress(&t, g_y);       p_y       = (float*)t;
      cudaGetSymbolAddress(&t, g_lorap);   p_lorap   = (float*)t;
      cudaGetSymbolAddress(&t, g_tdhp);    p_tdhp    = (float*)t;
      cudaGetSymbolAddress(&t, g_BloraT);  p_BloraT  = (float*)t;
      cudaGetSymbolAddress(&t, g_tdAT);    p_tdAT    = (float*)t;
      cudaGetSymbolAddress(&t, g_tdBT);    p_tdBT    = (float*)t;
      cudaGetSymbolAddress(&t, g_xmh);     p_xmh     = (__nv_bfloat16*)t;
      cudaGetSymbolAddress(&t, g_xml);     p_xml     = (__nv_bfloat16*)t;
      cudaGetSymbolAddress(&t, g_abh);     p_abh     = (__nv_bfloat16*)t;
      cudaGetSymbolAddress(&t, g_abl);     p_abl     = (__nv_bfloat16*)t;
      cudaGetSymbolAddress(&t, g_ygh);     p_ygh     = (__nv_bfloat16*)t;
      cudaGetSymbolAddress(&t, g_ygl);     p_ygl     = (__nv_bfloat16*)t;
      cudaGetSymbolAddress(&t, g_wbh);     p_wbh     = (__nv_bfloat16*)t;
      cudaGetSymbolAddress(&t, g_wbl);     p_wbl     = (__nv_bfloat16*)t;
      cudaGetSymbolAddress(&t, g_AloraTh); p_AloraTh = (__nv_bfloat16*)t;
      cudaGetSymbolAddress(&t, g_AloraTl); p_AloraTl = (__nv_bfloat16*)t;
    }

    cudaFuncSetAttribute(hgemm<0>, cudaFuncAttributeMaxDynamicSharedMemorySize, HG_SMEM);
    cudaFuncSetAttribute(hgemm<1>, cudaFuncAttributeMaxDynamicSharedMemorySize, HG_SMEM);
    cudaFuncSetAttribute(hgemm<2>, cudaFuncAttributeMaxDynamicSharedMemorySize, HG_SMEM);

    dim3 tg(8, 128);

    // 0: token shift + static lerp (xm -> bf16 hi/lo)
    prep_kernel<<<BTq * Cq / 4 / 256, 256>>>((const float4*)x, (const float4*)miu_x,
                                             (float4*)p_dxa, p_xmh, p_xml);
    // 1: weight transposes
    transpose_all<<<(622592 + 255) / 256, 256>>>(p_AloraTh, p_AloraTl, A_lora,
                                                 p_tdAT, td_A, p_tdBT, td_B,
                                                 p_BloraT, B_lora);
    // 2: big weight hi/lo
    wconv_kernel<<<5 * 1048576 / 256, 256>>>(Wk, Wv, Wr, Wg, Wo, p_wbh, p_wbl);
    // 3: lora_h = tanh(xm @ A_lora)  (tensor path, fp32 out)
    hgemm<2><<<dim3(2, 128), 256, HG_SMEM>>>(p_xmh, p_xml, p_AloraTh, p_AloraTl,
                                             p_lorap, BTq, 256, Cq);
    // 4: ddlerp mix (f=0 -> fp32 xx0; f=1..4 -> bf16 hi/lo k,v,r,g)
    mix_gemm<<<dim3(5, 128, 8), 256>>>(p_lorap, p_BloraT, x, p_dxa, lambda_,
                                       p_xx0, p_abh, p_abl);
    // 5-8: projections k, v, r, g (tensor path)
    hgemm<0><<<tg, 256, HG_SMEM>>>(p_abh + 0*SZq, p_abl + 0*SZq, p_wbh + 0*WWq, p_wbl + 0*WWq,
                                   p_k, BTq, Cq, Cq);
    hgemm<0><<<tg, 256, HG_SMEM>>>(p_abh + 1*SZq, p_abl + 1*SZq, p_wbh + 1*WWq, p_wbl + 1*WWq,
                                   p_v, BTq, Cq, Cq);
    hgemm<0><<<tg, 256, HG_SMEM>>>(p_abh + 2*SZq, p_abl + 2*SZq, p_wbh + 2*WWq, p_wbl + 2*WWq,
                                   p_r, BTq, Cq, Cq);
    hgemm<1><<<tg, 256, HG_SMEM>>>(p_abh + 3*SZq, p_abl + 3*SZq, p_wbh + 3*WWq, p_wbl + 3*WWq,
                                   p_g, BTq, Cq, Cq);
    // 9-10: time-decay lora (fp32 FFMA2 — precision-critical for the scan)
    sgemm_nt<EPI_TANH><<<dim3(1, 128), 256>>>(p_xx0, Cq, p_tdAT, 1024,
                                              p_tdhp, 128, 1024, nullptr);
    sgemm_nt<EPI_BIAS><<<dim3(8, 128), 256>>>(p_tdhp, 128, p_tdBT, 64,
                                              p_w, Cq, 64, td_miu);
    // 11: WKV6 scan
    wkv6_kernel<<<Bq * Hq, 256>>>(p_r, p_k, p_v, p_w, u, p_y);
    // 12: GroupNorm * gate -> bf16 hi/lo
    gnorm_kernel<<<BTq, 256>>>(p_y, p_g, gamma, beta, p_ygh, p_ygl);
    // 13: output projection
    hgemm<0><<<tg, 256, HG_SMEM>>>(p_ygh, p_ygl, p_wbh + 4*WWq, p_wbl + 4*WWq,
                                   out, BTq, Cq, Cq);
}

// round 6
// speedup vs baseline: 1.9239x; 1.0394x over previous
#include <cuda_runtime.h>
#include <cuda_bf16.h>
#include <math.h>
#include <stdint.h>

#define Bq 8
#define Tq 2048
#define Cq 1024
#define Hq 16
#define BTq (Bq*Tq)
#define WWq (Cq*Cq)

typedef unsigned long long ull;
static const size_t SZq = (size_t)BTq * Cq;

// ---------------------------------------------------------------------------
// Scratch (static device globals — no runtime allocation)
// ---------------------------------------------------------------------------
__device__ float g_dxa [BTq*Cq];
__device__ float g_xx0 [BTq*Cq];             // w_in branch (fp32 — precision-critical)
__device__ float g_k   [BTq*Cq];
__device__ float g_v   [BTq*Cq];
__device__ float g_r   [BTq*Cq];
__device__ float g_g   [BTq*Cq];
__device__ float g_w   [BTq*Cq];
__device__ float g_y   [BTq*Cq];
__device__ float g_lorap [BTq*256];          // tanh(xm @ A_lora) fp32 (padded 256)
__device__ float g_tdhp  [BTq*128];          // tanh(w_in @ td_A) fp32 (padded 128)
__device__ float g_BloraT[5*1024*32];        // B_lora^T per branch, fp32
__device__ float g_tdAT  [128*1024];         // td_A^T zero-padded fp32
__device__ float g_tdBT  [1024*64];          // td_B^T fp32

__device__ __nv_bfloat16 g_xmh[BTq*Cq];      // xm hi/lo
__device__ __nv_bfloat16 g_xml[BTq*Cq];
__device__ __nv_bfloat16 g_abh[4*BTq*Cq];    // k,v,r,g branch inputs hi
__device__ __nv_bfloat16 g_abl[4*BTq*Cq];    // lo
__device__ __nv_bfloat16 g_ygh[BTq*Cq];
__device__ __nv_bfloat16 g_ygl[BTq*Cq];
__device__ __nv_bfloat16 g_wbh[5*WWq];       // Wk,Wv,Wr,Wg,Wo hi
__device__ __nv_bfloat16 g_wbl[5*WWq];       // lo
__device__ __nv_bfloat16 g_AloraTh[256*1024];
__device__ __nv_bfloat16 g_AloraTl[256*1024];

// ---------------------------------------------------------------------------
// PTX helpers (sm_80+ — valid on compute_103 virtual arch)
// ---------------------------------------------------------------------------
__device__ __forceinline__ uint32_t sm2u32(const void* p){
    uint32_t a;
    asm("{ .reg .u64 t; cvta.to.shared.u64 t, %1; cvt.u32.u64 %0, t; }" : "=r"(a) : "l"(p));
    return a;
}
__device__ __forceinline__ void cpa16(uint32_t dst, const void* src){
    asm volatile("cp.async.cg.shared.global [%0], [%1], 16;" :: "r"(dst), "l"(src) : "memory");
}
__device__ __forceinline__ void cpa_commit(){
    asm volatile("cp.async.commit_group;" ::: "memory");
}
template<int N>
__device__ __forceinline__ void cpa_wait(){
    asm volatile("cp.async.wait_group %0;" :: "n"(N) : "memory");
}
__device__ __forceinline__ void ldsm_x4(uint32_t* r, uint32_t addr){
    asm volatile("ldmatrix.sync.aligned.m8n8.x4.shared.b16 {%0,%1,%2,%3}, [%4];"
        : "=r"(r[0]), "=r"(r[1]), "=r"(r[2]), "=r"(r[3]) : "r"(addr));
}
__device__ __forceinline__ void mma_bf16(float* d, const uint32_t* a, const uint32_t* b){
    asm volatile("mma.sync.aligned.m16n8k16.row.col.f32.bf16.bf16.f32 "
        "{%0,%1,%2,%3}, {%4,%5,%6,%7}, {%8,%9}, {%0,%1,%2,%3};"
        : "+f"(d[0]), "+f"(d[1]), "+f"(d[2]), "+f"(d[3])
        : "r"(a[0]), "r"(a[1]), "r"(a[2]), "r"(a[3]), "r"(b[0]), "r"(b[1]));
}
__device__ __forceinline__ void split_bf(float v, __nv_bfloat16& h, __nv_bfloat16& l){
    h = __float2bfloat16(v);
    l = __float2bfloat16(v - __bfloat162float(h));
}

// ---------------------------------------------------------------------------
// bf16-split GEMM core via mma.sync: C = (Ah+Al)[M,K] @ (Bh+Bl)[N,K]^T
// 128x128 tile, BK=32, 2-stage cp.async, 8 warps (2x4), warp 64x32.
// __launch_bounds__(256,2): regs<=128 so 2 CTAs/SM (smem 2x80KB fits 228KB).
// epi: 0 none, 1 silu, 2 tanh
// ---------------------------------------------------------------------------
#define HG_STAGE  40960
#define HG_ARR    10240
#define HG_SMEM   (2 * HG_STAGE)

__device__ __forceinline__ void hg_core(
    const __nv_bfloat16* __restrict__ Ah, const __nv_bfloat16* __restrict__ Al,
    const __nv_bfloat16* __restrict__ Bh, const __nv_bfloat16* __restrict__ Bl,
    float* __restrict__ Cp, int N, int K, int m0, int n0, int epi, char* sm)
{
    int tid = threadIdx.x, lane = tid & 31, wid = tid >> 5;
    int wy = wid & 1, wx = wid >> 1;
    uint32_t sb = sm2u32(sm);

    // per-thread load mapping: row = tid>>1 (0..127), chunk pair = (tid&1)*2
    int lrow = tid >> 1;
    int chp  = (tid & 1) * 2;
    const __nv_bfloat16* pAh = Ah + (size_t)(m0 + lrow) * K + chp * 8;
    const __nv_bfloat16* pAl = Al + (size_t)(m0 + lrow) * K + chp * 8;
    const __nv_bfloat16* pBh = Bh + (size_t)(n0 + lrow) * K + chp * 8;
    const __nv_bfloat16* pBl = Bl + (size_t)(n0 + lrow) * K + chp * 8;
    uint32_t so = (uint32_t)(lrow * 80 + chp * 16);

    float acc[4][4][4];
    #pragma unroll
    for (int i = 0; i < 4; i++)
        #pragma unroll
        for (int j = 0; j < 4; j++)
            #pragma unroll
            for (int q = 0; q < 4; q++) acc[i][j][q] = 0.f;

    uint32_t a_row = (uint32_t)(wy * 64 + (lane & 15));
    uint32_t a_kh  = (uint32_t)((lane >> 4) * 8);
    uint32_t b_row0 = (uint32_t)(wx * 32 + (lane & 7) + ((lane >> 4) * 8));
    uint32_t b_kh   = (uint32_t)(((lane >> 3) & 1) * 8);

    const int NC = K >> 5;

    // prologue: stage 0
    {
        uint32_t d = sb + so;
        cpa16(d + 0*HG_ARR,      pAh);     cpa16(d + 0*HG_ARR + 16, pAh + 8);
        cpa16(d + 1*HG_ARR,      pAl);     cpa16(d + 1*HG_ARR + 16, pAl + 8);
        cpa16(d + 2*HG_ARR,      pBh);     cpa16(d + 2*HG_ARR + 16, pBh + 8);
        cpa16(d + 3*HG_ARR,      pBl);     cpa16(d + 3*HG_ARR + 16, pBl + 8);
    }
    cpa_commit();

    for (int c = 0; c < NC; c++){
        int buf = c & 1;
        if (c + 1 < NC){
            size_t ko = (size_t)(c + 1) * 32;
            uint32_t d = sb + (uint32_t)(buf ^ 1) * HG_STAGE + so;
            cpa16(d + 0*HG_ARR,      pAh + ko); cpa16(d + 0*HG_ARR + 16, pAh + ko + 8);
            cpa16(d + 1*HG_ARR,      pAl + ko); cpa16(d + 1*HG_ARR + 16, pAl + ko + 8);
            cpa16(d + 2*HG_ARR,      pBh + ko); cpa16(d + 2*HG_ARR + 16, pBh + ko + 8);
            cpa16(d + 3*HG_ARR,      pBl + ko); cpa16(d + 3*HG_ARR + 16, pBl + ko + 8);
            cpa_commit();
            cpa_wait<1>();
        } else {
            cpa_wait<0>();
        }
        __syncthreads();

        uint32_t base = sb + (uint32_t)buf * HG_STAGE;
        #pragma unroll
        for (int ks = 0; ks < 2; ks++){
            uint32_t ah[4][4], al[4][4], bh[2][4], bl[2][4];
            uint32_t akh = (uint32_t)(ks * 16) + a_kh;
            #pragma unroll
            for (int mf = 0; mf < 4; mf++){
                uint32_t ao = base + (a_row + mf * 16) * 80 + akh * 2;
                ldsm_x4(ah[mf], ao);
                ldsm_x4(al[mf], ao + HG_ARR);
            }
            uint32_t bkh = (uint32_t)(ks * 16) + b_kh;
            #pragma unroll
            for (int bi = 0; bi < 2; bi++){
                uint32_t bo = base + 2*HG_ARR + (b_row0 + bi * 16) * 80 + bkh * 2;
                ldsm_x4(bh[bi], bo);
                ldsm_x4(bl[bi], bo + HG_ARR);
            }
            #pragma unroll
            for (int mf = 0; mf < 4; mf++)
                #pragma unroll
                for (int nf = 0; nf < 4; nf++){
                    const uint32_t* bhp = &bh[nf >> 1][(nf & 1) * 2];
                    const uint32_t* blp = &bl[nf >> 1][(nf & 1) * 2];
                    mma_bf16(acc[mf][nf], ah[mf], bhp);
                    mma_bf16(acc[mf][nf], ah[mf], blp);
                    mma_bf16(acc[mf][nf], al[mf], bhp);
                }
        }
        __syncthreads();
    }

    #pragma unroll
    for (int mf = 0; mf < 4; mf++){
        int row0 = m0 + wy * 64 + mf * 16 + (lane >> 2);
        #pragma unroll
        for (int nf = 0; nf < 4; nf++){
            int col = n0 + wx * 32 + nf * 8 + (lane & 3) * 2;
            float v[4] = {acc[mf][nf][0], acc[mf][nf][1], acc[mf][nf][2], acc[mf][nf][3]};
            if (epi == 1){
                #pragma unroll
                for (int q = 0; q < 4; q++) v[q] = v[q] / (1.f + expf(-v[q]));
            } else if (epi == 2){
                #pragma unroll
                for (int q = 0; q < 4; q++) v[q] = tanhf(v[q]);
            }
            *(float2*)(Cp + (size_t)row0 * N + col)       = make_float2(v[0], v[1]);
            *(float2*)(Cp + (size_t)(row0 + 8) * N + col) = make_float2(v[2], v[3]);
        }
    }
}

__global__ void __launch_bounds__(256, 2) hgemm_one(
    const __nv_bfloat16* __restrict__ Ah, const __nv_bfloat16* __restrict__ Al,
    const __nv_bfloat16* __restrict__ Bh, const __nv_bfloat16* __restrict__ Bl,
    float* __restrict__ Cp, int N, int K, int epi)
{
    extern __shared__ char sm[];
    hg_core(Ah, Al, Bh, Bl, Cp, N, K, blockIdx.y * 128, blockIdx.x * 128, epi, sm);
}

// merged k/v/r/g projections: z = blockIdx.z selects branch (g gets silu)
__global__ void __launch_bounds__(256, 2) hgemm_kvrg(
    const __nv_bfloat16* __restrict__ abh, const __nv_bfloat16* __restrict__ abl,
    const __nv_bfloat16* __restrict__ wbh, const __nv_bfloat16* __restrict__ wbl,
    float* __restrict__ C0, float* __restrict__ C1,
    float* __restrict__ C2, float* __restrict__ C3)
{
    extern __shared__ char sm[];
    int z = blockIdx.z;
    float* Cp = (z == 0) ? C0 : (z == 1) ? C1 : (z == 2) ? C2 : C3;
    const size_t SZ = (size_t)BTq * Cq;
    hg_core(abh + (size_t)z * SZ, abl + (size_t)z * SZ,
            wbh + (size_t)z * WWq, wbl + (size_t)z * WWq,
            Cp, Cq, Cq, blockIdx.y * 128, blockIdx.x * 128, (z == 3) ? 1 : 0, sm);
}

// ---------------------------------------------------------------------------
// FFMA2 helpers + fp32 SGEMM (precision-critical td path; proven round-1 code)
// ---------------------------------------------------------------------------
__device__ __forceinline__ void fma2(ull& d, ull a, ull b){
    asm("fma.rn.f32x2 %0, %1, %2, %0;" : "+l"(d) : "l"(a), "l"(b));
}
__device__ __forceinline__ float2 unp(ull v){
    float2 r; asm("mov.b64 {%0, %1}, %2;" : "=f"(r.x), "=f"(r.y) : "l"(v)); return r;
}

#define EPI_TANH 2
#define EPI_BIAS 3

template<int EPI>
__global__ void __launch_bounds__(256) sgemm_nt(
    const float* __restrict__ A, int lda,
    const float* __restrict__ Bm, int ldb,
    float* __restrict__ Cp, int N, int K,
    const float* __restrict__ e0)
{
    __shared__ __align__(16) float As2[8][256];
    __shared__ __align__(16) float Bs [8][128];

    int tid  = threadIdx.x;
    int m0   = blockIdx.y * 128, n0 = blockIdx.x * 128;
    int lrow = tid >> 1;
    int lkq  = (tid & 1) * 4;
    const float* Ap = A  + (size_t)(m0 + lrow) * lda + lkq;
    const float* Bp = Bm + (size_t)(n0 + lrow) * ldb + lkq;
    int ty = tid >> 4, tx = tid & 15;

    ull acc[8][4];
    #pragma unroll
    for (int i = 0; i < 8; i++)
        #pragma unroll
        for (int p = 0; p < 4; p++) acc[i][p] = 0ull;

    for (int k0 = 0; k0 < K; k0 += 8) {
        float4 av = *(const float4*)(Ap + k0);
        float4 bv = *(const float4*)(Bp + k0);
        *(float2*)&As2[lkq+0][2*lrow] = make_float2(av.x, av.x);
        *(float2*)&As2[lkq+1][2*lrow] = make_float2(av.y, av.y);
        *(float2*)&As2[lkq+2][2*lrow] = make_float2(av.z, av.z);
        *(float2*)&As2[lkq+3][2*lrow] = make_float2(av.w, av.w);
        Bs[lkq+0][lrow] = bv.x;
        Bs[lkq+1][lrow] = bv.y;
        Bs[lkq+2][lrow] = bv.z;
        Bs[lkq+3][lrow] = bv.w;
        __syncthreads();
        #pragma unroll
        for (int kk = 0; kk < 8; kk++) {
            const ull* ar = (const ull*)As2[kk];
            const ull* br = (const ull*)Bs[kk];
            ull a_[8], b_[4];
            #pragma unroll
            for (int i = 0; i < 8; i++) a_[i] = ar[ty*8 + i];
            #pragma unroll
            for (int p = 0; p < 4; p++) b_[p] = br[tx*4 + p];
            #pragma unroll
            for (int i = 0; i < 8; i++)
                #pragma unroll
                for (int p = 0; p < 4; p++) fma2(acc[i][p], a_[i], b_[p]);
        }
        __syncthreads();
    }

    #pragma unroll
    for (int i = 0; i < 8; i++) {
        size_t m = (size_t)(m0 + ty*8 + i);
        #pragma unroll
        for (int p = 0; p < 4; p++) {
            float2 vv = unp(acc[i][p]);
            int n = n0 + tx*8 + 2*p;
            size_t idx = m * (size_t)N + n;
            if (EPI == EPI_TANH) {
                vv.x = tanhf(vv.x); vv.y = tanhf(vv.y);
            } else if (EPI == EPI_BIAS) {
                vv.x += e0[n]; vv.y += e0[n+1];
            }
            *(float2*)(Cp + idx) = vv;
        }
    }
}

// ---------------------------------------------------------------------------
// ddlerp MIX GEMM (K=32), f = blockIdx.x (fastest) for L2 reuse of x/dxa.
// f=0 -> fp32 xx0 (w_in, precision-critical); f=1..4 -> bf16 hi/lo slots 0..3.
// ---------------------------------------------------------------------------
__global__ void __launch_bounds__(256) mix_gemm(
    const float* __restrict__ lorap, const float* __restrict__ BloraT,
    const float* __restrict__ x, const float* __restrict__ dxa,
    const float* __restrict__ lam,
    float* __restrict__ xx0,
    __nv_bfloat16* __restrict__ abh, __nv_bfloat16* __restrict__ abl)
{
    __shared__ __align__(16) float As2[8][256];
    __shared__ __align__(16) float Bs [8][128];

    int f = blockIdx.x;
    const float* A  = lorap  + f*32;
    const float* Bm = BloraT + f*32768;
    const float* e2 = lam    + f*Cq;

    int tid  = threadIdx.x;
    int m0   = blockIdx.y * 128, n0 = blockIdx.z * 128;
    int lrow = tid >> 1;
    int lkq  = (tid & 1) * 4;
    const float* Ap = A  + (size_t)(m0 + lrow) * 256 + lkq;
    const float* Bp = Bm + (size_t)(n0 + lrow) * 32  + lkq;
    int ty = tid >> 4, tx = tid & 15;

    ull acc[8][4];
    #pragma unroll
    for (int i = 0; i < 8; i++)
        #pragma unroll
        for (int p = 0; p < 4; p++) acc[i][p] = 0ull;

    for (int k0 = 0; k0 < 32; k0 += 8) {
        float4 av = *(const float4*)(Ap + k0);
        float4 bv = *(const float4*)(Bp + k0);
        *(float2*)&As2[lkq+0][2*lrow] = make_float2(av.x, av.x);
        *(float2*)&As2[lkq+1][2*lrow] = make_float2(av.y, av.y);
        *(float2*)&As2[lkq+2][2*lrow] = make_float2(av.z, av.z);
        *(float2*)&As2[lkq+3][2*lrow] = make_float2(av.w, av.w);
        Bs[lkq+0][lrow] = bv.x;
        Bs[lkq+1][lrow] = bv.y;
        Bs[lkq+2][lrow] = bv.z;
        Bs[lkq+3][lrow] = bv.w;
        __syncthreads();
        #pragma unroll
        for (int kk = 0; kk < 8; kk++) {
            const ull* ar = (const ull*)As2[kk];
            const ull* br = (const ull*)Bs[kk];
            ull a_[8], b_[4];
            #pragma unroll
            for (int i = 0; i < 8; i++) a_[i] = ar[ty*8 + i];
            #pragma unroll
            for (int p = 0; p < 4; p++) b_[p] = br[tx*4 + p];
            #pragma unroll
            for (int i = 0; i < 8; i++)
                #pragma unroll
                for (int p = 0; p < 4; p++) fma2(acc[i][p], a_[i], b_[p]);
        }
        __syncthreads();
    }

    #pragma unroll
    for (int i = 0; i < 8; i++) {
        size_t m = (size_t)(m0 + ty*8 + i);
        #pragma unroll
        for (int p = 0; p < 4; p++) {
            float2 vv = unp(acc[i][p]);
            int n = n0 + tx*8 + 2*p;
            size_t idx = m * (size_t)Cq + n;
            float vx = x[idx]   + dxa[idx]   * (e2[n]   + vv.x);
            float vy = x[idx+1] + dxa[idx+1] * (e2[n+1] + vv.y);
            if (f == 0) {
                *(float2*)(xx0 + idx) = make_float2(vx, vy);
            } else {
                size_t o = (size_t)(f-1) * SZq + idx;
                __nv_bfloat162 hp, lp;
                split_bf(vx, hp.x, lp.x);
                split_bf(vy, hp.y, lp.y);
                *(__nv_bfloat162*)(abh + o) = hp;
                *(__nv_bfloat162*)(abl + o) = lp;
            }
        }
    }
}

// ---------------------------------------------------------------------------
// prep: dxa = shift(x) - x (fp32) ; xm = x + dxa * miu_x -> bf16 hi/lo
// ---------------------------------------------------------------------------
__global__ void __launch_bounds__(256) prep_kernel(
    const float4* __restrict__ x4, const float4* __restrict__ mu4,
    float4* __restrict__ dxa4,
    __nv_bfloat16* __restrict__ xmh, __nv_bfloat16* __restrict__ xml)
{
    size_t i = (size_t)blockIdx.x * 256 + threadIdx.x;
    int m = (int)(i >> 8);
    int t = m & (Tq - 1);
    float4 xv = x4[i];
    float4 xl = make_float4(0.f, 0.f, 0.f, 0.f);
    if (t) xl = x4[i - 256];
    float4 mu = mu4[i & 255];
    float4 d  = make_float4(xl.x - xv.x, xl.y - xv.y, xl.z - xv.z, xl.w - xv.w);
    float xm0 = fmaf(d.x, mu.x, xv.x), xm1 = fmaf(d.y, mu.y, xv.y);
    float xm2 = fmaf(d.z, mu.z, xv.z), xm3 = fmaf(d.w, mu.w, xv.w);
    dxa4[i] = d;
    __nv_bfloat162 h0, l0, h1, l1;
    split_bf(xm0, h0.x, l0.x); split_bf(xm1, h0.y, l0.y);
    split_bf(xm2, h1.x, l1.x); split_bf(xm3, h1.y, l1.y);
    ((__nv_bfloat162*)xmh)[i*2]   = h0;
    ((__nv_bfloat162*)xmh)[i*2+1] = h1;
    ((__nv_bfloat162*)xml)[i*2]   = l0;
    ((__nv_bfloat162*)xml)[i*2+1] = l1;
}

// ---------------------------------------------------------------------------
// transposes: AloraT -> bf16 hi/lo; tdAT, tdBT, BloraT -> fp32
// ---------------------------------------------------------------------------
__global__ void __launch_bounds__(256) transpose_all(
    __nv_bfloat16* __restrict__ AloraTh, __nv_bfloat16* __restrict__ AloraTl,
    const float* __restrict__ A_lora,
    float* __restrict__ tdAT, const float* __restrict__ td_A,
    float* __restrict__ tdBT, const float* __restrict__ td_B,
    float* __restrict__ BloraT, const float* __restrict__ B_lora)
{
    int i = blockIdx.x * 256 + threadIdx.x;
    if (i < 262144) {
        int n = i >> 10, k = i & 1023;
        float v = (n < 160) ? A_lora[k*160 + n] : 0.f;
        __nv_bfloat16 h, l; split_bf(v, h, l);
        AloraTh[i] = h; AloraTl[i] = l;
    } else if (i < 393216) {
        int j = i - 262144; int n = j >> 10, k = j & 1023;
        tdAT[j] = (n < 64) ? td_A[k*64 + n] : 0.f;
    } else if (i < 458752) {
        int j = i - 393216; int n = j >> 6, k = j & 63;
        tdBT[j] = td_B[k*1024 + n];
    } else if (i < 622592) {
        int j = i - 458752;
        int f = j >> 15, rr = j & 32767, n = rr >> 5, k = rr & 31;
        BloraT[j] = B_lora[(f*32 + k)*1024 + n];
    }
}

// ---------------------------------------------------------------------------
// Weight bf16 hi/lo conversion (Wk,Wv,Wr,Wg,Wo)
// ---------------------------------------------------------------------------
__global__ void __launch_bounds__(256) wconv_kernel(
    const float* __restrict__ w0, const float* __restrict__ w1,
    const float* __restrict__ w2, const float* __restrict__ w3,
    const float* __restrict__ w4,
    __nv_bfloat16* __restrict__ h, __nv_bfloat16* __restrict__ l)
{
    int i = blockIdx.x * 256 + threadIdx.x;
    int w = i >> 20;
    int j = i & 1048575;
    const float* src = (w == 0) ? w0 : (w == 1) ? w1 : (w == 2) ? w2 : (w == 3) ? w3 : w4;
    float x = src[j];
    __nv_bfloat16 hh, ll; split_bf(x, hh, ll);
    h[i] = hh;
    l[i] = ll;
}

// ---------------------------------------------------------------------------
// WKV6 scan — software-pipelined: t+1 global loads overlap compute of t.
// ---------------------------------------------------------------------------
__global__ void __launch_bounds__(256) wkv6_kernel(
    const float* __restrict__ rp, const float* __restrict__ kp,
    const float* __restrict__ vp, const float* __restrict__ wp,
    const float* __restrict__ up, float* __restrict__ yp)
{
    __shared__ float4 pk[2][4][17];
    __shared__ float  sv[2][64];
    int bh = blockIdx.x;
    int b = bh >> 4, h = bh & 15;
    size_t base = ((size_t)b * Tq) * Cq + h * 64;
    int tid = threadIdx.x;
    int j = tid >> 2, rg = tid & 3;
    float uu = 0.f;
    if (tid < 64) uu = up[h * 64 + tid];
    float S[16];
    #pragma unroll
    for (int i = 0; i < 16; i++) S[i] = 0.f;

    float lk = 0.f, lr = 0.f, lw = 0.f, lv = 0.f;
    if (tid < 64){
        lk = kp[base + tid]; lr = rp[base + tid];
        lw = wp[base + tid]; lv = vp[base + tid];
    }

    for (int t = 0; t < Tq; t++) {
        int buf = t & 1;
        size_t off = base + (size_t)t * Cq;
        if (tid < 64) {
            sv[buf][tid] = lv;
            float dd = expf(-expf(lw));
            pk[buf][tid >> 4][tid & 15] = make_float4(lk, uu * lk, lr, dd);
        }
        __syncthreads();
        if (t + 1 < Tq && tid < 64){
            size_t o2 = off + Cq + tid;
            lk = kp[o2]; lr = rp[o2]; lw = wp[o2]; lv = vp[o2];
        }
        float vj = sv[buf][j];
        float yv = 0.f;
        #pragma unroll
        for (int ii = 0; ii < 16; ii++) {
            float4 p = pk[buf][rg][ii];
            float s = S[ii];
            yv = fmaf(p.z, fmaf(p.y, vj, s), yv);
            S[ii] = fmaf(p.w, s, p.x * vj);
        }
        yv += __shfl_xor_sync(0xffffffffu, yv, 1);
        yv += __shfl_xor_sync(0xffffffffu, yv, 2);
        if (rg == 0) yp[off + j] = yv;
    }
}

// ---------------------------------------------------------------------------
// GroupNorm * gate -> bf16 hi/lo
// ---------------------------------------------------------------------------
__global__ void __launch_bounds__(256) gnorm_kernel(
    const float* __restrict__ y, const float* __restrict__ g,
    const float* __restrict__ gamma, const float* __restrict__ beta,
    __nv_bfloat16* __restrict__ ygh, __nv_bfloat16* __restrict__ ygl)
{
    int m = blockIdx.x, tid = threadIdx.x;
    size_t i4 = (size_t)m * 256 + tid;
    float4 yv = ((const float4*)y)[i4];
    float s  = yv.x + yv.y + yv.z + yv.w;
    float ss = yv.x*yv.x + yv.y*yv.y + yv.z*yv.z + yv.w*yv.w;
    #pragma unroll
    for (int o = 1; o < 16; o <<= 1) {
        s  += __shfl_xor_sync(0xffffffffu, s,  o);
        ss += __shfl_xor_sync(0xffffffffu, ss, o);
    }
    float mean = s * (1.f / 64.f);
    float var  = ss * (1.f / 64.f) - mean * mean;
    float rstd = rsqrtf(fmaxf(var, 0.f) + 1.6e-4f);
    float4 ga = ((const float4*)gamma)[tid];
    float4 be = ((const float4*)beta)[tid];
    float4 gv = ((const float4*)g)[i4];
    float o0 = ((yv.x - mean) * rstd * ga.x + be.x) * gv.x;
    float o1 = ((yv.y - mean) * rstd * ga.y + be.y) * gv.y;
    float o2 = ((yv.z - mean) * rstd * ga.z + be.z) * gv.z;
    float o3 = ((yv.w - mean) * rstd * ga.w + be.w) * gv.w;

    __nv_bfloat162 hp0, lp0, hp1, lp1;
    split_bf(o0, hp0.x, lp0.x); split_bf(o1, hp0.y, lp0.y);
    split_bf(o2, hp1.x, lp1.x); split_bf(o3, hp1.y, lp1.y);
    ((__nv_bfloat162*)ygh)[i4*2]   = hp0;
    ((__nv_bfloat162*)ygh)[i4*2+1] = hp1;
    ((__nv_bfloat162*)ygl)[i4*2]   = lp0;
    ((__nv_bfloat162*)ygl)[i4*2+1] = lp1;
}

// ---------------------------------------------------------------------------
// Launch
// ---------------------------------------------------------------------------
extern "C" void kernel_launch(void* const* d_in, const int* in_sizes, int n_in,
                              void* d_out, int out_size)
{
    (void)in_sizes; (void)n_in; (void)out_size;
    const float* x       = (const float*)d_in[0];
    const float* miu_x   = (const float*)d_in[1];
    const float* lambda_ = (const float*)d_in[2];
    const float* A_lora  = (const float*)d_in[3];
    const float* B_lora  = (const float*)d_in[4];
    const float* td_miu  = (const float*)d_in[5];
    const float* td_A    = (const float*)d_in[6];
    const float* td_B    = (const float*)d_in[7];
    const float* u       = (const float*)d_in[8];
    const float* Wr      = (const float*)d_in[9];
    const float* Wk      = (const float*)d_in[10];
    const float* Wv      = (const float*)d_in[11];
    const float* Wg      = (const float*)d_in[12];
    const float* Wo      = (const float*)d_in[13];
    const float* gamma   = (const float*)d_in[14];
    const float* beta    = (const float*)d_in[15];
    float* out = (float*)d_out;

    float *p_dxa,*p_xx0,*p_k,*p_v,*p_r,*p_g,*p_w,*p_y,*p_lorap,*p_tdhp,
          *p_BloraT,*p_tdAT,*p_tdBT;
    __nv_bfloat16 *p_xmh,*p_xml,*p_abh,*p_abl,*p_ygh,*p_ygl,*p_wbh,*p_wbl,
                  *p_AloraTh,*p_AloraTl;
    { void* t;
      cudaGetSymbolAddress(&t, g_dxa);     p_dxa     = (float*)t;
      cudaGetSymbolAddress(&t, g_xx0);     p_xx0     = (float*)t;
      cudaGetSymbolAddress(&t, g_k);       p_k       = (float*)t;
      cudaGetSymbolAddress(&t, g_v);       p_v       = (float*)t;
      cudaGetSymbolAddress(&t, g_r);       p_r       = (float*)t;
      cudaGetSymbolAddress(&t, g_g);       p_g       = (float*)t;
      cudaGetSymbolAddress(&t, g_w);       p_w       = (float*)t;
      cudaGetSymbolAddress(&t, g_y);       p_y       = (float*)t;
      cudaGetSymbolAddress(&t, g_lorap);   p_lorap   = (float*)t;
      cudaGetSymbolAddress(&t, g_tdhp);    p_tdhp    = (float*)t;
      cudaGetSymbolAddress(&t, g_BloraT);  p_BloraT  = (float*)t;
      cudaGetSymbolAddress(&t, g_tdAT);    p_tdAT    = (float*)t;
      cudaGetSymbolAddress(&t, g_tdBT);    p_tdBT    = (float*)t;
      cudaGetSymbolAddress(&t, g_xmh);     p_xmh     = (__nv_bfloat16*)t;
      cudaGetSymbolAddress(&t, g_xml);     p_xml     = (__nv_bfloat16*)t;
      cudaGetSymbolAddress(&t, g_abh);     p_abh     = (__nv_bfloat16*)t;
      cudaGetSymbolAddress(&t, g_abl);     p_abl     = (__nv_bfloat16*)t;
      cudaGetSymbolAddress(&t, g_ygh);     p_ygh     = (__nv_bfloat16*)t;
      cudaGetSymbolAddress(&t, g_ygl);     p_ygl     = (__nv_bfloat16*)t;
      cudaGetSymbolAddress(&t, g_wbh);     p_wbh     = (__nv_bfloat16*)t;
      cudaGetSymbolAddress(&t, g_wbl);     p_wbl     = (__nv_bfloat16*)t;
      cudaGetSymbolAddress(&t, g_AloraTh); p_AloraTh = (__nv_bfloat16*)t;
      cudaGetSymbolAddress(&t, g_AloraTl); p_AloraTl = (__nv_bfloat16*)t;
    }

    cudaFuncSetAttribute(hgemm_one, cudaFuncAttributeMaxDynamicSharedMemorySize, HG_SMEM);
    cudaFuncSetAttribute(hgemm_kvrg, cudaFuncAttributeMaxDynamicSharedMemorySize, HG_SMEM);

    // 0: token shift + static lerp (xm -> bf16 hi/lo)
    prep_kernel<<<BTq * Cq / 4 / 256, 256>>>((const float4*)x, (const float4*)miu_x,
                                             (float4*)p_dxa, p_xmh, p_xml);
    // 1: weight transposes
    transpose_all<<<(622592 + 255) / 256, 256>>>(p_AloraTh, p_AloraTl, A_lora,
                                                 p_tdAT, td_A, p_tdBT, td_B,
                                                 p_BloraT, B_lora);
    // 2: big weight hi/lo
    wconv_kernel<<<5 * 1048576 / 256, 256>>>(Wk, Wv, Wr, Wg, Wo, p_wbh, p_wbl);
    // 3: lora_h = tanh(xm @ A_lora)  (tensor path, fp32 out)
    hgemm_one<<<dim3(2, 128), 256, HG_SMEM>>>(p_xmh, p_xml, p_AloraTh, p_AloraTl,
                                              p_lorap, 256, Cq, 2);
    // 4: ddlerp mix (f=0 -> fp32 xx0; f=1..4 -> bf16 hi/lo k,v,r,g)
    mix_gemm<<<dim3(5, 128, 8), 256>>>(p_lorap, p_BloraT, x, p_dxa, lambda_,
                                       p_xx0, p_abh, p_abl);
    // 5: merged projections k, v, r, g (tensor path, 2 CTAs/SM)
    hgemm_kvrg<<<dim3(8, 128, 4), 256, HG_SMEM>>>(p_abh, p_abl, p_wbh, p_wbl,
                                                  p_k, p_v, p_r, p_g);
    // 6-7: time-decay lora (fp32 FFMA2 — precision-critical for the scan)
    sgemm_nt<EPI_TANH><<<dim3(1, 128), 256>>>(p_xx0, Cq, p_tdAT, 1024,
                                              p_tdhp, 128, 1024, nullptr);
    sgemm_nt<EPI_BIAS><<<dim3(8, 128), 256>>>(p_tdhp, 128, p_tdBT, 64,
                                              p_w, Cq, 64, td_miu);
    // 8: WKV6 scan
    wkv6_kernel<<<Bq * Hq, 256>>>(p_r, p_k, p_v, p_w, u, p_y);
    // 9: GroupNorm * gate -> bf16 hi/lo
    gnorm_kernel<<<BTq, 256>>>(p_y, p_g, gamma, beta, p_ygh, p_ygl);
    // 10: output projection
    hgemm_one<<<dim3(8, 128), 256, HG_SMEM>>>(p_ygh, p_ygl, p_wbh + 4*WWq, p_wbl + 4*WWq,
                                              out, Cq, Cq, 0);
}

// round 8
// speedup vs baseline: 1.9394x; 1.0081x over previous
#include <cuda_runtime.h>
#include <cuda_bf16.h>
#include <cuda_fp16.h>
#include <math.h>
#include <stdint.h>

#define Bq 8
#define Tq 2048
#define Cq 1024
#define Hq 16
#define BTq (Bq*Tq)
#define WWq (Cq*Cq)

typedef unsigned long long ull;
static const size_t SZq = (size_t)BTq * Cq;

// ---------------------------------------------------------------------------
// Scratch (static device globals — no runtime allocation)
// ---------------------------------------------------------------------------
__device__ float g_dxa [BTq*Cq];
__device__ float g_k   [BTq*Cq];
__device__ float g_v   [BTq*Cq];
__device__ float g_r   [BTq*Cq];
__device__ float g_g   [BTq*Cq];
__device__ float g_w   [BTq*Cq];
__device__ float g_y   [BTq*Cq];
__device__ float g_lorap [BTq*256];          // tanh(xm @ A_lora) fp32 (padded 256)
__device__ float g_BloraT[5*1024*32];        // B_lora^T per branch, fp32

__device__ __nv_bfloat16 g_xmh[BTq*Cq];      // xm hi/lo (bf16 split)
__device__ __nv_bfloat16 g_xml[BTq*Cq];
__device__ __nv_bfloat16 g_abh[4*BTq*Cq];    // k,v,r,g branch inputs hi
__device__ __nv_bfloat16 g_abl[4*BTq*Cq];    // lo
__device__ __nv_bfloat16 g_ygh[BTq*Cq];
__device__ __nv_bfloat16 g_ygl[BTq*Cq];
__device__ __nv_bfloat16 g_wbh[5*WWq];       // Wk,Wv,Wr,Wg,Wo hi
__device__ __nv_bfloat16 g_wbl[5*WWq];       // lo
__device__ __nv_bfloat16 g_AloraTh[256*1024];
__device__ __nv_bfloat16 g_AloraTl[256*1024];

// fp16-split td path (2^-22 residual — precision-safe for the decay scan)
__device__ __half g_xx0h[BTq*Cq];            // w_in branch hi/lo
__device__ __half g_xx0l[BTq*Cq];
__device__ __half g_tdhh[BTq*128];           // tanh(w_in @ td_A) hi/lo (padded 128)
__device__ __half g_tdhl[BTq*128];
__device__ __half g_tdATh[128*1024];
__device__ __half g_tdATl[128*1024];
__device__ __half g_tdBTh[1024*64];
__device__ __half g_tdBTl[1024*64];

// ---------------------------------------------------------------------------
// PTX helpers (sm_80+ — valid on compute_103 virtual arch)
// ---------------------------------------------------------------------------
__device__ __forceinline__ uint32_t sm2u32(const void* p){
    uint32_t a;
    asm("{ .reg .u64 t; cvta.to.shared.u64 t, %1; cvt.u32.u64 %0, t; }" : "=r"(a) : "l"(p));
    return a;
}
__device__ __forceinline__ void cpa16(uint32_t dst, const void* src){
    asm volatile("cp.async.cg.shared.global [%0], [%1], 16;" :: "r"(dst), "l"(src) : "memory");
}
__device__ __forceinline__ void cpa_commit(){
    asm volatile("cp.async.commit_group;" ::: "memory");
}
template<int N>
__device__ __forceinline__ void cpa_wait(){
    asm volatile("cp.async.wait_group %0;" :: "n"(N) : "memory");
}
__device__ __forceinline__ void ldsm_x4(uint32_t* r, uint32_t addr){
    asm volatile("ldmatrix.sync.aligned.m8n8.x4.shared.b16 {%0,%1,%2,%3}, [%4];"
        : "=r"(r[0]), "=r"(r[1]), "=r"(r[2]), "=r"(r[3]) : "r"(addr));
}
template<bool FP16>
__device__ __forceinline__ void mma_any(float* d, const uint32_t* a, const uint32_t* b){
    if (FP16){
        asm volatile("mma.sync.aligned.m16n8k16.row.col.f32.f16.f16.f32 "
            "{%0,%1,%2,%3}, {%4,%5,%6,%7}, {%8,%9}, {%0,%1,%2,%3};"
            : "+f"(d[0]), "+f"(d[1]), "+f"(d[2]), "+f"(d[3])
            : "r"(a[0]), "r"(a[1]), "r"(a[2]), "r"(a[3]), "r"(b[0]), "r"(b[1]));
    } else {
        asm volatile("mma.sync.aligned.m16n8k16.row.col.f32.bf16.bf16.f32 "
            "{%0,%1,%2,%3}, {%4,%5,%6,%7}, {%8,%9}, {%0,%1,%2,%3};"
            : "+f"(d[0]), "+f"(d[1]), "+f"(d[2]), "+f"(d[3])
            : "r"(a[0]), "r"(a[1]), "r"(a[2]), "r"(a[3]), "r"(b[0]), "r"(b[1]));
    }
}
__device__ __forceinline__ void splitv(float v, __nv_bfloat16& h, __nv_bfloat16& l){
    h = __float2bfloat16(v);
    l = __float2bfloat16(v - __bfloat162float(h));
}
__device__ __forceinline__ void splitv(float v, __half& h, __half& l){
    h = __float2half_rn(v);
    l = __float2half_rn(v - __half2float(h));
}
__device__ __forceinline__ uint16_t u16of(__half v){ return *(uint16_t*)&v; }
__device__ __forceinline__ uint16_t u16of(__nv_bfloat16 v){ return *(uint16_t*)&v; }

// ---------------------------------------------------------------------------
// split GEMM core via mma.sync: C = (Ah+Al)[M,K] @ (Bh+Bl)[N,K]^T (fp32 acc)
// 128x128 tile, BK=16, 4-stage cp.async ring, ONE __syncthreads per iter.
// Row stride 48B (16B-aligned for cp.async/ldmatrix; conflict-free ldsm).
// 8 warps (2x4), warp tile 64x32. 2 CTAs/SM (2x96KB smem fits 228KB).
// epi: 0 none, 1 silu, 2 tanh->fp32, 3 tanh->split OT, 4 bias(e0)->fp32
// ---------------------------------------------------------------------------
#define NSTAGE    4
#define STG_ARR   6144                 // 128 rows * 48B
#define STG_BYTES 24576                // 4 arrays
#define HG_SMEM   (NSTAGE * STG_BYTES) // 98304

template<bool FP16, typename OT>
__device__ __forceinline__ void hg_core(
    const uint16_t* __restrict__ Ah, const uint16_t* __restrict__ Al,
    const uint16_t* __restrict__ Bh, const uint16_t* __restrict__ Bl,
    float* __restrict__ Cp, OT* __restrict__ Ch, OT* __restrict__ Cl,
    const float* __restrict__ e0,
    int N, int K, int lda, int ldb, int m0, int n0, int epi, char* sm)
{
    int tid = threadIdx.x, lane = tid & 31, wid = tid >> 5;
    int wy = wid & 1, wx = wid >> 1;
    uint32_t sb = sm2u32(sm);

    // load mapping: 256 threads cover 2 arrays x 128 rows; each thread 2 arrays
    int arr0 = tid >> 7;                 // 0 or 1 (A-hi / A-lo)
    int rowa = tid & 127;
    const uint16_t* p0 = ((arr0 == 0) ? Ah : Al) + (size_t)(m0 + rowa) * lda;
    const uint16_t* p1 = ((arr0 == 0) ? Bh : Bl) + (size_t)(n0 + rowa) * ldb;
    uint32_t so0 = (uint32_t)(arr0 * STG_ARR + rowa * 48);
    uint32_t so1 = so0 + 2 * STG_ARR;

    float acc[4][4][4];
    #pragma unroll
    for (int i = 0; i < 4; i++)
        #pragma unroll
        for (int j = 0; j < 4; j++)
            #pragma unroll
            for (int q = 0; q < 4; q++) acc[i][j][q] = 0.f;

    uint32_t a_row = (uint32_t)(wy * 64 + (lane & 15));
    uint32_t a_kh  = (uint32_t)((lane >> 4) * 8);
    uint32_t b_row0 = (uint32_t)(wx * 32 + (lane & 7) + ((lane >> 4) * 8));
    uint32_t b_kh   = (uint32_t)(((lane >> 3) & 1) * 8);

    const int NC = K >> 4;

    // prologue: fill 3 stages
    #pragma unroll
    for (int s = 0; s < 3; s++){
        uint32_t d = sb + (uint32_t)s * STG_BYTES;
        int kk = s * 16;
        cpa16(d + so0,      p0 + kk);  cpa16(d + so0 + 16, p0 + kk + 8);
        cpa16(d + so1,      p1 + kk);  cpa16(d + so1 + 16, p1 + kk + 8);
        cpa_commit();
    }

    #pragma unroll 4
    for (int c = 0; c < NC; c++){
        cpa_wait<2>();
        __syncthreads();
        if (c + 3 < NC){
            uint32_t d = sb + (uint32_t)((c + 3) & 3) * STG_BYTES;
            int kk = (c + 3) << 4;
            cpa16(d + so0,      p0 + kk);  cpa16(d + so0 + 16, p0 + kk + 8);
            cpa16(d + so1,      p1 + kk);  cpa16(d + so1 + 16, p1 + kk + 8);
        }
        cpa_commit();

        uint32_t base = sb + (uint32_t)(c & 3) * STG_BYTES;
        uint32_t ah[4][4], al[4][4], bh[2][4], bl[2][4];
        #pragma unroll
        for (int mf = 0; mf < 4; mf++){
            uint32_t ao = base + (a_row + mf * 16) * 48 + a_kh * 2;
            ldsm_x4(ah[mf], ao);
            ldsm_x4(al[mf], ao + STG_ARR);
        }
        #pragma unroll
        for (int bi = 0; bi < 2; bi++){
            uint32_t bo = base + 2*STG_ARR + (b_row0 + bi * 16) * 48 + b_kh * 2;
            ldsm_x4(bh[bi], bo);
            ldsm_x4(bl[bi], bo + STG_ARR);
        }
        #pragma unroll
        for (int mf = 0; mf < 4; mf++)
            #pragma unroll
            for (int nf = 0; nf < 4; nf++){
                const uint32_t* bhp = &bh[nf >> 1][(nf & 1) * 2];
                const uint32_t* blp = &bl[nf >> 1][(nf & 1) * 2];
                mma_any<FP16>(acc[mf][nf], ah[mf], bhp);
                mma_any<FP16>(acc[mf][nf], ah[mf], blp);
                mma_any<FP16>(acc[mf][nf], al[mf], bhp);
            }
    }

    #pragma unroll
    for (int mf = 0; mf < 4; mf++){
        int row0 = m0 + wy * 64 + mf * 16 + (lane >> 2);
        #pragma unroll
        for (int nf = 0; nf < 4; nf++){
            int col = n0 + wx * 32 + nf * 8 + (lane & 3) * 2;
            float v[4] = {acc[mf][nf][0], acc[mf][nf][1], acc[mf][nf][2], acc[mf][nf][3]};
            if (epi == 1){
                #pragma unroll
                for (int q = 0; q < 4; q++) v[q] = v[q] / (1.f + expf(-v[q]));
            } else if (epi == 2 || epi == 3){
                #pragma unroll
                for (int q = 0; q < 4; q++) v[q] = tanhf(v[q]);
            } else if (epi == 4){
                v[0] += e0[col]; v[1] += e0[col+1];
                v[2] += e0[col]; v[3] += e0[col+1];
            }
            size_t i01 = (size_t)row0 * N + col;
            size_t i23 = (size_t)(row0 + 8) * N + col;
            if (epi == 3){
                OT h[4], l[4];
                #pragma unroll
                for (int q = 0; q < 4; q++) splitv(v[q], h[q], l[q]);
                *(uint32_t*)(Ch + i01) = (uint32_t)u16of(h[0]) | ((uint32_t)u16of(h[1]) << 16);
                *(uint32_t*)(Cl + i01) = (uint32_t)u16of(l[0]) | ((uint32_t)u16of(l[1]) << 16);
                *(uint32_t*)(Ch + i23) = (uint32_t)u16of(h[2]) | ((uint32_t)u16of(h[3]) << 16);
                *(uint32_t*)(Cl + i23) = (uint32_t)u16of(l[2]) | ((uint32_t)u16of(l[3]) << 16);
            } else {
                *(float2*)(Cp + i01) = make_float2(v[0], v[1]);
                *(float2*)(Cp + i23) = make_float2(v[2], v[3]);
            }
        }
    }
}

// bf16 single-output kernel (lora epi2, Wo epi0)
__global__ void __launch_bounds__(256, 2) hgemm_one(
    const __nv_bfloat16* __restrict__ Ah, const __nv_bfloat16* __restrict__ Al,
    const __nv_bfloat16* __restrict__ Bh, const __nv_bfloat16* __restrict__ Bl,
    float* __restrict__ Cp, int N, int K, int epi)
{
    extern __shared__ char sm[];
    hg_core<false, __nv_bfloat16>((const uint16_t*)Ah, (const uint16_t*)Al,
        (const uint16_t*)Bh, (const uint16_t*)Bl,
        Cp, (__nv_bfloat16*)nullptr, (__nv_bfloat16*)nullptr, nullptr,
        N, K, K, K, blockIdx.y * 128, blockIdx.x * 128, epi, sm);
}

// merged k/v/r/g projections: z selects branch (g gets silu)
__global__ void __launch_bounds__(256, 2) hgemm_kvrg(
    const __nv_bfloat16* __restrict__ abh, const __nv_bfloat16* __restrict__ abl,
    const __nv_bfloat16* __restrict__ wbh, const __nv_bfloat16* __restrict__ wbl,
    float* __restrict__ C0, float* __restrict__ C1,
    float* __restrict__ C2, float* __restrict__ C3)
{
    extern __shared__ char sm[];
    int z = blockIdx.z;
    float* Cp = (z == 0) ? C0 : (z == 1) ? C1 : (z == 2) ? C2 : C3;
    hg_core<false, __nv_bfloat16>(
        (const uint16_t*)(abh + (size_t)z * SZq), (const uint16_t*)(abl + (size_t)z * SZq),
        (const uint16_t*)(wbh + (size_t)z * WWq), (const uint16_t*)(wbl + (size_t)z * WWq),
        Cp, (__nv_bfloat16*)nullptr, (__nv_bfloat16*)nullptr, nullptr,
        Cq, Cq, Cq, Cq, blockIdx.y * 128, blockIdx.x * 128, (z == 3) ? 1 : 0, sm);
}

// fp16-split kernel (td path; epi 3 = tanh->split out, epi 4 = bias->fp32)
__global__ void __launch_bounds__(256, 2) hgemm_h(
    const __half* __restrict__ Ah, const __half* __restrict__ Al,
    const __half* __restrict__ Bh, const __half* __restrict__ Bl,
    float* __restrict__ Cp, __half* __restrict__ Ch, __half* __restrict__ Cl,
    const float* __restrict__ e0, int N, int K, int lda, int ldb, int epi)
{
    extern __shared__ char sm[];
    hg_core<true, __half>((const uint16_t*)Ah, (const uint16_t*)Al,
        (const uint16_t*)Bh, (const uint16_t*)Bl,
        Cp, Ch, Cl, e0,
        N, K, lda, ldb, blockIdx.y * 128, blockIdx.x * 128, epi, sm);
}

// ---------------------------------------------------------------------------
// FFMA2 helpers (mix_gemm K=32, memory-bound)
// ---------------------------------------------------------------------------
__device__ __forceinline__ void fma2(ull& d, ull a, ull b){
    asm("fma.rn.f32x2 %0, %1, %2, %0;" : "+l"(d) : "l"(a), "l"(b));
}
__device__ __forceinline__ float2 unp(ull v){
    float2 r; asm("mov.b64 {%0, %1}, %2;" : "=f"(r.x), "=f"(r.y) : "l"(v)); return r;
}

// ---------------------------------------------------------------------------
// ddlerp MIX GEMM (K=32), f = blockIdx.x (fastest) for L2 reuse of x/dxa.
// f=0 -> fp16 hi/lo xx0 (w_in); f=1..4 -> bf16 hi/lo slots 0..3 (k,v,r,g).
// ---------------------------------------------------------------------------
__global__ void __launch_bounds__(256) mix_gemm(
    const float* __restrict__ lorap, const float* __restrict__ BloraT,
    const float* __restrict__ x, const float* __restrict__ dxa,
    const float* __restrict__ lam,
    __half* __restrict__ xx0h, __half* __restrict__ xx0l,
    __nv_bfloat16* __restrict__ abh, __nv_bfloat16* __restrict__ abl)
{
    __shared__ __align__(16) float As2[8][256];
    __shared__ __align__(16) float Bs [8][128];

    int f = blockIdx.x;
    const float* A  = lorap  + f*32;
    const float* Bm = BloraT + f*32768;
    const float* e2 = lam    + f*Cq;

    int tid  = threadIdx.x;
    int m0   = blockIdx.y * 128, n0 = blockIdx.z * 128;
    int lrow = tid >> 1;
    int lkq  = (tid & 1) * 4;
    const float* Ap = A  + (size_t)(m0 + lrow) * 256 + lkq;
    const float* Bp = Bm + (size_t)(n0 + lrow) * 32  + lkq;
    int ty = tid >> 4, tx = tid & 15;

    ull acc[8][4];
    #pragma unroll
    for (int i = 0; i < 8; i++)
        #pragma unroll
        for (int p = 0; p < 4; p++) acc[i][p] = 0ull;

    for (int k0 = 0; k0 < 32; k0 += 8) {
        float4 av = *(const float4*)(Ap + k0);
        float4 bv = *(const float4*)(Bp + k0);
        *(float2*)&As2[lkq+0][2*lrow] = make_float2(av.x, av.x);
        *(float2*)&As2[lkq+1][2*lrow] = make_float2(av.y, av.y);
        *(float2*)&As2[lkq+2][2*lrow] = make_float2(av.z, av.z);
        *(float2*)&As2[lkq+3][2*lrow] = make_float2(av.w, av.w);
        Bs[lkq+0][lrow] = bv.x;
        Bs[lkq+1][lrow] = bv.y;
        Bs[lkq+2][lrow] = bv.z;
        Bs[lkq+3][lrow] = bv.w;
        __syncthreads();
        #pragma unroll
        for (int kk = 0; kk < 8; kk++) {
            const ull* ar = (const ull*)As2[kk];
            const ull* br = (const ull*)Bs[kk];
            ull a_[8], b_[4];
            #pragma unroll
            for (int i = 0; i < 8; i++) a_[i] = ar[ty*8 + i];
            #pragma unroll
            for (int p = 0; p < 4; p++) b_[p] = br[tx*4 + p];
            #pragma unroll
            for (int i = 0; i < 8; i++)
                #pragma unroll
                for (int p = 0; p < 4; p++) fma2(acc[i][p], a_[i], b_[p]);
        }
        __syncthreads();
    }

    #pragma unroll
    for (int i = 0; i < 8; i++) {
        size_t m = (size_t)(m0 + ty*8 + i);
        #pragma unroll
        for (int p = 0; p < 4; p++) {
            float2 vv = unp(acc[i][p]);
            int n = n0 + tx*8 + 2*p;
            size_t idx = m * (size_t)Cq + n;
            float vx = x[idx]   + dxa[idx]   * (e2[n]   + vv.x);
            float vy = x[idx+1] + dxa[idx+1] * (e2[n+1] + vv.y);
            if (f == 0) {
                __half hx, lx, hy, ly;
                splitv(vx, hx, lx); splitv(vy, hy, ly);
                __half2 hp; hp.x = hx; hp.y = hy;
                __half2 lp; lp.x = lx; lp.y = ly;
                *(__half2*)(xx0h + idx) = hp;
                *(__half2*)(xx0l + idx) = lp;
            } else {
                size_t o = (size_t)(f-1) * SZq + idx;
                __nv_bfloat162 hp, lp;
                splitv(vx, hp.x, lp.x);
                splitv(vy, hp.y, lp.y);
                *(__nv_bfloat162*)(abh + o) = hp;
                *(__nv_bfloat162*)(abl + o) = lp;
            }
        }
    }
}

// ---------------------------------------------------------------------------
// prep: dxa = shift(x) - x (fp32) ; xm = x + dxa * miu_x -> bf16 hi/lo
// ---------------------------------------------------------------------------
__global__ void __launch_bounds__(256) prep_kernel(
    const float4* __restrict__ x4, const float4* __restrict__ mu4,
    float4* __restrict__ dxa4,
    __nv_bfloat16* __restrict__ xmh, __nv_bfloat16* __restrict__ xml)
{
    size_t i = (size_t)blockIdx.x * 256 + threadIdx.x;
    int m = (int)(i >> 8);
    int t = m & (Tq - 1);
    float4 xv = x4[i];
    float4 xl = make_float4(0.f, 0.f, 0.f, 0.f);
    if (t) xl = x4[i - 256];
    float4 mu = mu4[i & 255];
    float4 d  = make_float4(xl.x - xv.x, xl.y - xv.y, xl.z - xv.z, xl.w - xv.w);
    float xm0 = fmaf(d.x, mu.x, xv.x), xm1 = fmaf(d.y, mu.y, xv.y);
    float xm2 = fmaf(d.z, mu.z, xv.z), xm3 = fmaf(d.w, mu.w, xv.w);
    dxa4[i] = d;
    __nv_bfloat162 h0, l0, h1, l1;
    splitv(xm0, h0.x, l0.x); splitv(xm1, h0.y, l0.y);
    splitv(xm2, h1.x, l1.x); splitv(xm3, h1.y, l1.y);
    ((__nv_bfloat162*)xmh)[i*2]   = h0;
    ((__nv_bfloat162*)xmh)[i*2+1] = h1;
    ((__nv_bfloat162*)xml)[i*2]   = l0;
    ((__nv_bfloat162*)xml)[i*2+1] = l1;
}

// ---------------------------------------------------------------------------
// transposes: AloraT -> bf16 hi/lo; tdAT, tdBT -> fp16 hi/lo; BloraT fp32
// ---------------------------------------------------------------------------
__global__ void __launch_bounds__(256) transpose_all(
    __nv_bfloat16* __restrict__ AloraTh, __nv_bfloat16* __restrict__ AloraTl,
    const float* __restrict__ A_lora,
    __half* __restrict__ tdATh, __half* __restrict__ tdATl,
    const float* __restrict__ td_A,
    __half* __restrict__ tdBTh, __half* __restrict__ tdBTl,
    const float* __restrict__ td_B,
    float* __restrict__ BloraT, const float* __restrict__ B_lora)
{
    int i = blockIdx.x * 256 + threadIdx.x;
    if (i < 262144) {
        int n = i >> 10, k = i & 1023;
        float v = (n < 160) ? A_lora[k*160 + n] : 0.f;
        __nv_bfloat16 h, l; splitv(v, h, l);
        AloraTh[i] = h; AloraTl[i] = l;
    } else if (i < 393216) {
        int j = i - 262144; int n = j >> 10, k = j & 1023;
        float v = (n < 64) ? td_A[k*64 + n] : 0.f;
        __half h, l; splitv(v, h, l);
        tdATh[j] = h; tdATl[j] = l;
    } else if (i < 458752) {
        int j = i - 393216; int n = j >> 6, k = j & 63;
        float v = td_B[k*1024 + n];
        __half h, l; splitv(v, h, l);
        tdBTh[j] = h; tdBTl[j] = l;
    } else if (i < 622592) {
        int j = i - 458752;
        int f = j >> 15, rr = j & 32767, n = rr >> 5, k = rr & 31;
        BloraT[j] = B_lora[(f*32 + k)*1024 + n];
    }
}

// ---------------------------------------------------------------------------
// Weight bf16 hi/lo conversion (Wk,Wv,Wr,Wg,Wo)
// ---------------------------------------------------------------------------
__global__ void __launch_bounds__(256) wconv_kernel(
    const float* __restrict__ w0, const float* __restrict__ w1,
    const float* __restrict__ w2, const float* __restrict__ w3,
    const float* __restrict__ w4,
    __nv_bfloat16* __restrict__ h, __nv_bfloat16* __restrict__ l)
{
    int i = blockIdx.x * 256 + threadIdx.x;
    int w = i >> 20;
    int j = i & 1048575;
    const float* src = (w == 0) ? w0 : (w == 1) ? w1 : (w == 2) ? w2 : (w == 3) ? w3 : w4;
    float x = src[j];
    __nv_bfloat16 hh, ll; splitv(x, hh, ll);
    h[i] = hh;
    l[i] = ll;
}

// ---------------------------------------------------------------------------
// WKV6 scan — software-pipelined: t+1 global loads overlap compute of t.
// ---------------------------------------------------------------------------
__global__ void __launch_bounds__(256) wkv6_kernel(
    const float* __restrict__ rp, const float* __restrict__ kp,
    const float* __restrict__ vp, const float* __restrict__ wp,
    const float* __restrict__ up, float* __restrict__ yp)
{
    __shared__ float4 pk[2][4][17];
    __shared__ float  sv[2][64];
    int bh = blockIdx.x;
    int b = bh >> 4, h = bh & 15;
    size_t base = ((size_t)b * Tq) * Cq + h * 64;
    int tid = threadIdx.x;
    int j = tid >> 2, rg = tid & 3;
    float uu = 0.f;
    if (tid < 64) uu = up[h * 64 + tid];
    float S[16];
    #pragma unroll
    for (int i = 0; i < 16; i++) S[i] = 0.f;

    float lk = 0.f, lr = 0.f, lw = 0.f, lv = 0.f;
    if (tid < 64){
        lk = kp[base + tid]; lr = rp[base + tid];
        lw = wp[base + tid]; lv = vp[base + tid];
    }

    for (int t = 0; t < Tq; t++) {
        int buf = t & 1;
        size_t off = base + (size_t)t * Cq;
        if (tid < 64) {
            sv[buf][tid] = lv;
            float dd = expf(-expf(lw));
            pk[buf][tid >> 4][tid & 15] = make_float4(lk, uu * lk, lr, dd);
        }
        __syncthreads();
        if (t + 1 < Tq && tid < 64){
            size_t o2 = off + Cq + tid;
            lk = kp[o2]; lr = rp[o2]; lw = wp[o2]; lv = vp[o2];
        }
        float vj = sv[buf][j];
        float yv = 0.f;
        #pragma unroll
        for (int ii = 0; ii < 16; ii++) {
            float4 p = pk[buf][rg][ii];
            float s = S[ii];
            yv = fmaf(p.z, fmaf(p.y, vj, s), yv);
            S[ii] = fmaf(p.w, s, p.x * vj);
        }
        yv += __shfl_xor_sync(0xffffffffu, yv, 1);
        yv += __shfl_xor_sync(0xffffffffu, yv, 2);
        if (rg == 0) yp[off + j] = yv;
    }
}

// ---------------------------------------------------------------------------
// GroupNorm * gate -> bf16 hi/lo
// ---------------------------------------------------------------------------
__global__ void __launch_bounds__(256) gnorm_kernel(
    const float* __restrict__ y, const float* __restrict__ g,
    const float* __restrict__ gamma, const float* __restrict__ beta,
    __nv_bfloat16* __restrict__ ygh, __nv_bfloat16* __restrict__ ygl)
{
    int m = blockIdx.x, tid = threadIdx.x;
    size_t i4 = (size_t)m * 256 + tid;
    float4 yv = ((const float4*)y)[i4];
    float s  = yv.x + yv.y + yv.z + yv.w;
    float ss = yv.x*yv.x + yv.y*yv.y + yv.z*yv.z + yv.w*yv.w;
    #pragma unroll
    for (int o = 1; o < 16; o <<= 1) {
        s  += __shfl_xor_sync(0xffffffffu, s,  o);
        ss += __shfl_xor_sync(0xffffffffu, ss, o);
    }
    float mean = s * (1.f / 64.f);
    float var  = ss * (1.f / 64.f) - mean * mean;
    float rstd = rsqrtf(fmaxf(var, 0.f) + 1.6e-4f);
    float4 ga = ((const float4*)gamma)[tid];
    float4 be = ((const float4*)beta)[tid];
    float4 gv = ((const float4*)g)[i4];
    float o0 = ((yv.x - mean) * rstd * ga.x + be.x) * gv.x;
    float o1 = ((yv.y - mean) * rstd * ga.y + be.y) * gv.y;
    float o2 = ((yv.z - mean) * rstd * ga.z + be.z) * gv.z;
    float o3 = ((yv.w - mean) * rstd * ga.w + be.w) * gv.w;

    __nv_bfloat162 hp0, lp0, hp1, lp1;
    splitv(o0, hp0.x, lp0.x); splitv(o1, hp0.y, lp0.y);
    splitv(o2, hp1.x, lp1.x); splitv(o3, hp1.y, lp1.y);
    ((__nv_bfloat162*)ygh)[i4*2]   = hp0;
    ((__nv_bfloat162*)ygh)[i4*2+1] = hp1;
    ((__nv_bfloat162*)ygl)[i4*2]   = lp0;
    ((__nv_bfloat162*)ygl)[i4*2+1] = lp1;
}

// ---------------------------------------------------------------------------
// Launch
// ---------------------------------------------------------------------------
extern "C" void kernel_launch(void* const* d_in, const int* in_sizes, int n_in,
                              void* d_out, int out_size)
{
    (void)in_sizes; (void)n_in; (void)out_size;
    const float* x       = (const float*)d_in[0];
    const float* miu_x   = (const float*)d_in[1];
    const float* lambda_ = (const float*)d_in[2];
    const float* A_lora  = (const float*)d_in[3];
    const float* B_lora  = (const float*)d_in[4];
    const float* td_miu  = (const float*)d_in[5];
    const float* td_A    = (const float*)d_in[6];
    const float* td_B    = (const float*)d_in[7];
    const float* u       = (const float*)d_in[8];
    const float* Wr      = (const float*)d_in[9];
    const float* Wk      = (const float*)d_in[10];
    const float* Wv      = (const float*)d_in[11];
    const float* Wg      = (const float*)d_in[12];
    const float* Wo      = (const float*)d_in[13];
    const float* gamma   = (const float*)d_in[14];
    const float* beta    = (const float*)d_in[15];
    float* out = (float*)d_out;

    float *p_dxa,*p_k,*p_v,*p_r,*p_g,*p_w,*p_y,*p_lorap,*p_BloraT;
    __nv_bfloat16 *p_xmh,*p_xml,*p_abh,*p_abl,*p_ygh,*p_ygl,*p_wbh,*p_wbl,
                  *p_AloraTh,*p_AloraTl;
    __half *p_xx0h,*p_xx0l,*p_tdhh,*p_tdhl,*p_tdATh,*p_tdATl,*p_tdBTh,*p_tdBTl;
    { void* t;
      cudaGetSymbolAddress(&t, g_dxa);     p_dxa     = (float*)t;
      cudaGetSymbolAddress(&t, g_k);       p_k       = (float*)t;
      cudaGetSymbolAddress(&t, g_v);       p_v       = (float*)t;
      cudaGetSymbolAddress(&t, g_r);       p_r       = (float*)t;
      cudaGetSymbolAddress(&t, g_g);       p_g       = (float*)t;
      cudaGetSymbolAddress(&t, g_w);       p_w       = (float*)t;
      cudaGetSymbolAddress(&t, g_y);       p_y       = (float*)t;
      cudaGetSymbolAddress(&t, g_lorap);   p_lorap   = (float*)t;
      cudaGetSymbolAddress(&t, g_BloraT);  p_BloraT  = (float*)t;
      cudaGetSymbolAddress(&t, g_xmh);     p_xmh     = (__nv_bfloat16*)t;
      cudaGetSymbolAddress(&t, g_xml);     p_xml     = (__nv_bfloat16*)t;
      cudaGetSymbolAddress(&t, g_abh);     p_abh     = (__nv_bfloat16*)t;
      cudaGetSymbolAddress(&t, g_abl);     p_abl     = (__nv_bfloat16*)t;
      cudaGetSymbolAddress(&t, g_ygh);     p_ygh     = (__nv_bfloat16*)t;
      cudaGetSymbolAddress(&t, g_ygl);     p_ygl     = (__nv_bfloat16*)t;
      cudaGetSymbolAddress(&t, g_wbh);     p_wbh     = (__nv_bfloat16*)t;
      cudaGetSymbolAddress(&t, g_wbl);     p_wbl     = (__nv_bfloat16*)t;
      cudaGetSymbolAddress(&t, g_AloraTh); p_AloraTh = (__nv_bfloat16*)t;
      cudaGetSymbolAddress(&t, g_AloraTl); p_AloraTl = (__nv_bfloat16*)t;
      cudaGetSymbolAddress(&t, g_xx0h);    p_xx0h    = (__half*)t;
      cudaGetSymbolAddress(&t, g_xx0l);    p_xx0l    = (__half*)t;
      cudaGetSymbolAddress(&t, g_tdhh);    p_tdhh    = (__half*)t;
      cudaGetSymbolAddress(&t, g_tdhl);    p_tdhl    = (__half*)t;
      cudaGetSymbolAddress(&t, g_tdATh);   p_tdATh   = (__half*)t;
      cudaGetSymbolAddress(&t, g_tdATl);   p_tdATl   = (__half*)t;
      cudaGetSymbolAddress(&t, g_tdBTh);   p_tdBTh   = (__half*)t;
      cudaGetSymbolAddress(&t, g_tdBTl);   p_tdBTl   = (__half*)t;
    }

    cudaFuncSetAttribute(hgemm_one,  cudaFuncAttributeMaxDynamicSharedMemorySize, HG_SMEM);
    cudaFuncSetAttribute(hgemm_kvrg, cudaFuncAttributeMaxDynamicSharedMemorySize, HG_SMEM);
    cudaFuncSetAttribute(hgemm_h,    cudaFuncAttributeMaxDynamicSharedMemorySize, HG_SMEM);

    // 0: token shift + static lerp (xm -> bf16 hi/lo)
    prep_kernel<<<BTq * Cq / 4 / 256, 256>>>((const float4*)x, (const float4*)miu_x,
                                             (float4*)p_dxa, p_xmh, p_xml);
    // 1: weight transposes
    transpose_all<<<(622592 + 255) / 256, 256>>>(p_AloraTh, p_AloraTl, A_lora,
                                                 p_tdATh, p_tdATl, td_A,
                                                 p_tdBTh, p_tdBTl, td_B,
                                                 p_BloraT, B_lora);
    // 2: big weight hi/lo
    wconv_kernel<<<5 * 1048576 / 256, 256>>>(Wk, Wv, Wr, Wg, Wo, p_wbh, p_wbl);
    // 3: lora_h = tanh(xm @ A_lora)
    hgemm_one<<<dim3(2, 128), 256, HG_SMEM>>>(p_xmh, p_xml, p_AloraTh, p_AloraTl,
                                              p_lorap, 256, Cq, 2);
    // 4: ddlerp mix (f=0 -> fp16 hi/lo xx0; f=1..4 -> bf16 hi/lo k,v,r,g)
    mix_gemm<<<dim3(5, 128, 8), 256>>>(p_lorap, p_BloraT, x, p_dxa, lambda_,
                                       p_xx0h, p_xx0l, p_abh, p_abl);
    // 5: merged projections k, v, r, g
    hgemm_kvrg<<<dim3(8, 128, 4), 256, HG_SMEM>>>(p_abh, p_abl, p_wbh, p_wbl,
                                                  p_k, p_v, p_r, p_g);
    // 6: tdh = tanh(w_in @ td_A) -> fp16 hi/lo (padded N=128)
    hgemm_h<<<dim3(1, 128), 256, HG_SMEM>>>(p_xx0h, p_xx0l, p_tdATh, p_tdATl,
                                            nullptr, p_tdhh, p_tdhl, nullptr,
                                            128, Cq, Cq, Cq, 3);
    // 7: w = td_miu + tdh @ td_B   (A stride 128, K=64)
    hgemm_h<<<dim3(8, 128), 256, HG_SMEM>>>(p_tdhh, p_tdhl, p_tdBTh, p_tdBTl,
                                            p_w, nullptr, nullptr, td_miu,
                                            Cq, 64, 128, 64, 4);
    // 8: WKV6 scan
    wkv6_kernel<<<Bq * Hq, 256>>>(p_r, p_k, p_v, p_w, u, p_y);
    // 9: GroupNorm * gate -> bf16 hi/lo
    gnorm_kernel<<<BTq, 256>>>(p_y, p_g, gamma, beta, p_ygh, p_ygl);
    // 10: output projection
    hgemm_one<<<dim3(8, 128), 256, HG_SMEM>>>(p_ygh, p_ygl, p_wbh + 4*WWq, p_wbl + 4*WWq,
                                              out, Cq, Cq, 0);
}

// round 9
// speedup vs baseline: 1.9561x; 1.0086x over previous
#include <cuda_runtime.h>
#include <cuda_bf16.h>
#include <cuda_fp16.h>
#include <math.h>
#include <stdint.h>

#define Bq 8
#define Tq 2048
#define Cq 1024
#define Hq 16
#define BTq (Bq*Tq)
#define WWq (Cq*Cq)

typedef unsigned long long ull;
static const size_t SZq = (size_t)BTq * Cq;

// ---------------------------------------------------------------------------
// Scratch (static device globals — no runtime allocation)
// ---------------------------------------------------------------------------
__device__ float g_dxa [BTq*Cq];
__device__ float g_k   [BTq*Cq];
__device__ float g_v   [BTq*Cq];
__device__ float g_r   [BTq*Cq];
__device__ float g_g   [BTq*Cq];
__device__ float g_w   [BTq*Cq];
__device__ float g_y   [BTq*Cq];
__device__ float g_lorap [BTq*256];          // tanh(xm @ A_lora) fp32 (padded 256)
__device__ float g_BloraT[5*1024*32];        // B_lora^T per branch, fp32

__device__ __nv_bfloat16 g_xmh[BTq*Cq];      // xm hi/lo (bf16 split)
__device__ __nv_bfloat16 g_xml[BTq*Cq];
__device__ __nv_bfloat16 g_abh[4*BTq*Cq];    // k,v,r,g branch inputs hi
__device__ __nv_bfloat16 g_abl[4*BTq*Cq];    // lo
__device__ __nv_bfloat16 g_ygh[BTq*Cq];
__device__ __nv_bfloat16 g_ygl[BTq*Cq];
__device__ __nv_bfloat16 g_wbh[5*WWq];       // Wk,Wv,Wr,Wg,Wo hi
__device__ __nv_bfloat16 g_wbl[5*WWq];       // lo
__device__ __nv_bfloat16 g_AloraTh[256*1024];
__device__ __nv_bfloat16 g_AloraTl[256*1024];

// fp16-split td path (2^-22 residual — precision-safe for the decay scan)
__device__ __half g_xx0h[BTq*Cq];            // w_in branch hi/lo
__device__ __half g_xx0l[BTq*Cq];
__device__ __half g_tdhh[BTq*128];           // tanh(w_in @ td_A) hi/lo (padded 128)
__device__ __half g_tdhl[BTq*128];
__device__ __half g_tdATh[128*1024];
__device__ __half g_tdATl[128*1024];
__device__ __half g_tdBTh[1024*64];
__device__ __half g_tdBTl[1024*64];

// ---------------------------------------------------------------------------
// PTX helpers (sm_80+ — valid on compute_103 virtual arch)
// ---------------------------------------------------------------------------
__device__ __forceinline__ uint32_t sm2u32(const void* p){
    uint32_t a;
    asm("{ .reg .u64 t; cvta.to.shared.u64 t, %1; cvt.u32.u64 %0, t; }" : "=r"(a) : "l"(p));
    return a;
}
__device__ __forceinline__ void cpa16(uint32_t dst, const void* src){
    asm volatile("cp.async.cg.shared.global [%0], [%1], 16;" :: "r"(dst), "l"(src) : "memory");
}
__device__ __forceinline__ void cpa_commit(){
    asm volatile("cp.async.commit_group;" ::: "memory");
}
template<int N>
__device__ __forceinline__ void cpa_wait(){
    asm volatile("cp.async.wait_group %0;" :: "n"(N) : "memory");
}
__device__ __forceinline__ void ldsm_x4(uint32_t* r, uint32_t addr){
    asm volatile("ldmatrix.sync.aligned.m8n8.x4.shared.b16 {%0,%1,%2,%3}, [%4];"
        : "=r"(r[0]), "=r"(r[1]), "=r"(r[2]), "=r"(r[3]) : "r"(addr));
}
template<bool FP16>
__device__ __forceinline__ void mma_any(float* d, const uint32_t* a, const uint32_t* b){
    if (FP16){
        asm volatile("mma.sync.aligned.m16n8k16.row.col.f32.f16.f16.f32 "
            "{%0,%1,%2,%3}, {%4,%5,%6,%7}, {%8,%9}, {%0,%1,%2,%3};"
            : "+f"(d[0]), "+f"(d[1]), "+f"(d[2]), "+f"(d[3])
            : "r"(a[0]), "r"(a[1]), "r"(a[2]), "r"(a[3]), "r"(b[0]), "r"(b[1]));
    } else {
        asm volatile("mma.sync.aligned.m16n8k16.row.col.f32.bf16.bf16.f32 "
            "{%0,%1,%2,%3}, {%4,%5,%6,%7}, {%8,%9}, {%0,%1,%2,%3};"
            : "+f"(d[0]), "+f"(d[1]), "+f"(d[2]), "+f"(d[3])
            : "r"(a[0]), "r"(a[1]), "r"(a[2]), "r"(a[3]), "r"(b[0]), "r"(b[1]));
    }
}
__device__ __forceinline__ void splitv(float v, __nv_bfloat16& h, __nv_bfloat16& l){
    h = __float2bfloat16(v);
    l = __float2bfloat16(v - __bfloat162float(h));
}
__device__ __forceinline__ void splitv(float v, __half& h, __half& l){
    h = __float2half_rn(v);
    l = __float2half_rn(v - __half2float(h));
}
__device__ __forceinline__ uint16_t u16of(__half v){ return *(uint16_t*)&v; }
__device__ __forceinline__ uint16_t u16of(__nv_bfloat16 v){ return *(uint16_t*)&v; }

// ---------------------------------------------------------------------------
// split GEMM core via mma.sync: C = (Ah+Al)[M,K] @ (Bh+Bl)[N,K]^T (fp32 acc)
// 128x128 tile, BK=16, 4-stage cp.async ring, ONE __syncthreads per iter.
// Inner iteration is ldsm/mma INTERLEAVED: B frags first, then per-mf
// (2 ldsm -> 12 mma) so smem bursts hide under the tensor pipe.
// Row stride 48B (16B-aligned, conflict-free ldsm). 8 warps (2x4).
// epi: 0 none, 1 silu, 2 tanh->fp32, 3 tanh->split OT, 4 bias(e0)->fp32
// ---------------------------------------------------------------------------
#define NSTAGE    4
#define STG_ARR   6144                 // 128 rows * 48B
#define STG_BYTES 24576                // 4 arrays
#define HG_SMEM   (NSTAGE * STG_BYTES) // 98304

template<bool FP16, typename OT>
__device__ __forceinline__ void hg_core(
    const uint16_t* __restrict__ Ah, const uint16_t* __restrict__ Al,
    const uint16_t* __restrict__ Bh, const uint16_t* __restrict__ Bl,
    float* __restrict__ Cp, OT* __restrict__ Ch, OT* __restrict__ Cl,
    const float* __restrict__ e0,
    int N, int K, int lda, int ldb, int m0, int n0, int epi, char* sm)
{
    int tid = threadIdx.x, lane = tid & 31, wid = tid >> 5;
    int wy = wid & 1, wx = wid >> 1;
    uint32_t sb = sm2u32(sm);

    int arr0 = tid >> 7;
    int rowa = tid & 127;
    const uint16_t* p0 = ((arr0 == 0) ? Ah : Al) + (size_t)(m0 + rowa) * lda;
    const uint16_t* p1 = ((arr0 == 0) ? Bh : Bl) + (size_t)(n0 + rowa) * ldb;
    uint32_t so0 = (uint32_t)(arr0 * STG_ARR + rowa * 48);
    uint32_t so1 = so0 + 2 * STG_ARR;

    float acc[4][4][4];
    #pragma unroll
    for (int i = 0; i < 4; i++)
        #pragma unroll
        for (int j = 0; j < 4; j++)
            #pragma unroll
            for (int q = 0; q < 4; q++) acc[i][j][q] = 0.f;

    uint32_t a_row = (uint32_t)(wy * 64 + (lane & 15));
    uint32_t a_kh  = (uint32_t)((lane >> 4) * 8);
    uint32_t b_row0 = (uint32_t)(wx * 32 + (lane & 7) + ((lane >> 4) * 8));
    uint32_t b_kh   = (uint32_t)(((lane >> 3) & 1) * 8);

    const int NC = K >> 4;

    #pragma unroll
    for (int s = 0; s < 3; s++){
        uint32_t d = sb + (uint32_t)s * STG_BYTES;
        int kk = s * 16;
        cpa16(d + so0,      p0 + kk);  cpa16(d + so0 + 16, p0 + kk + 8);
        cpa16(d + so1,      p1 + kk);  cpa16(d + so1 + 16, p1 + kk + 8);
        cpa_commit();
    }

    #pragma unroll 4
    for (int c = 0; c < NC; c++){
        cpa_wait<2>();
        __syncthreads();
        if (c + 3 < NC){
            uint32_t d = sb + (uint32_t)((c + 3) & 3) * STG_BYTES;
            int kk = (c + 3) << 4;
            cpa16(d + so0,      p0 + kk);  cpa16(d + so0 + 16, p0 + kk + 8);
            cpa16(d + so1,      p1 + kk);  cpa16(d + so1 + 16, p1 + kk + 8);
        }
        cpa_commit();

        uint32_t base = sb + (uint32_t)(c & 3) * STG_BYTES;

        // B fragments up front (4 ldsm)
        uint32_t bh[2][4], bl[2][4];
        #pragma unroll
        for (int bi = 0; bi < 2; bi++){
            uint32_t bo = base + 2*STG_ARR + (b_row0 + bi * 16) * 48 + b_kh * 2;
            ldsm_x4(bh[bi], bo);
            ldsm_x4(bl[bi], bo + STG_ARR);
        }
        // per-mf: load A frags then immediately consume — smem hides under tensor
        #pragma unroll
        for (int mf = 0; mf < 4; mf++){
            uint32_t ah[4], al[4];
            uint32_t ao = base + (a_row + mf * 16) * 48 + a_kh * 2;
            ldsm_x4(ah, ao);
            ldsm_x4(al, ao + STG_ARR);
            #pragma unroll
            for (int nf = 0; nf < 4; nf++){
                const uint32_t* bhp = &bh[nf >> 1][(nf & 1) * 2];
                const uint32_t* blp = &bl[nf >> 1][(nf & 1) * 2];
                mma_any<FP16>(acc[mf][nf], ah, bhp);
                mma_any<FP16>(acc[mf][nf], ah, blp);
                mma_any<FP16>(acc[mf][nf], al, bhp);
            }
        }
    }

    #pragma unroll
    for (int mf = 0; mf < 4; mf++){
        int row0 = m0 + wy * 64 + mf * 16 + (lane >> 2);
        #pragma unroll
        for (int nf = 0; nf < 4; nf++){
            int col = n0 + wx * 32 + nf * 8 + (lane & 3) * 2;
            float v[4] = {acc[mf][nf][0], acc[mf][nf][1], acc[mf][nf][2], acc[mf][nf][3]};
            if (epi == 1){
                #pragma unroll
                for (int q = 0; q < 4; q++) v[q] = v[q] / (1.f + expf(-v[q]));
            } else if (epi == 2 || epi == 3){
                #pragma unroll
                for (int q = 0; q < 4; q++) v[q] = tanhf(v[q]);
            } else if (epi == 4){
                v[0] += e0[col]; v[1] += e0[col+1];
                v[2] += e0[col]; v[3] += e0[col+1];
            }
            size_t i01 = (size_t)row0 * N + col;
            size_t i23 = (size_t)(row0 + 8) * N + col;
            if (epi == 3){
                OT h[4], l[4];
                #pragma unroll
                for (int q = 0; q < 4; q++) splitv(v[q], h[q], l[q]);
                *(uint32_t*)(Ch + i01) = (uint32_t)u16of(h[0]) | ((uint32_t)u16of(h[1]) << 16);
                *(uint32_t*)(Cl + i01) = (uint32_t)u16of(l[0]) | ((uint32_t)u16of(l[1]) << 16);
                *(uint32_t*)(Ch + i23) = (uint32_t)u16of(h[2]) | ((uint32_t)u16of(h[3]) << 16);
                *(uint32_t*)(Cl + i23) = (uint32_t)u16of(l[2]) | ((uint32_t)u16of(l[3]) << 16);
            } else {
                *(float2*)(Cp + i01) = make_float2(v[0], v[1]);
                *(float2*)(Cp + i23) = make_float2(v[2], v[3]);
            }
        }
    }
}

// bf16 single-output kernel (lora epi2, Wo epi0)
__global__ void __launch_bounds__(256, 2) hgemm_one(
    const __nv_bfloat16* __restrict__ Ah, const __nv_bfloat16* __restrict__ Al,
    const __nv_bfloat16* __restrict__ Bh, const __nv_bfloat16* __restrict__ Bl,
    float* __restrict__ Cp, int N, int K, int epi)
{
    extern __shared__ char sm[];
    hg_core<false, __nv_bfloat16>((const uint16_t*)Ah, (const uint16_t*)Al,
        (const uint16_t*)Bh, (const uint16_t*)Bl,
        Cp, (__nv_bfloat16*)nullptr, (__nv_bfloat16*)nullptr, nullptr,
        N, K, K, K, blockIdx.y * 128, blockIdx.x * 128, epi, sm);
}

// merged k/v/r/g projections: z selects branch (g gets silu)
__global__ void __launch_bounds__(256, 2) hgemm_kvrg(
    const __nv_bfloat16* __restrict__ abh, const __nv_bfloat16* __restrict__ abl,
    const __nv_bfloat16* __restrict__ wbh, const __nv_bfloat16* __restrict__ wbl,
    float* __restrict__ C0, float* __restrict__ C1,
    float* __restrict__ C2, float* __restrict__ C3)
{
    extern __shared__ char sm[];
    int z = blockIdx.z;
    float* Cp = (z == 0) ? C0 : (z == 1) ? C1 : (z == 2) ? C2 : C3;
    hg_core<false, __nv_bfloat16>(
        (const uint16_t*)(abh + (size_t)z * SZq), (const uint16_t*)(abl + (size_t)z * SZq),
        (const uint16_t*)(wbh + (size_t)z * WWq), (const uint16_t*)(wbl + (size_t)z * WWq),
        Cp, (__nv_bfloat16*)nullptr, (__nv_bfloat16*)nullptr, nullptr,
        Cq, Cq, Cq, Cq, blockIdx.y * 128, blockIdx.x * 128, (z == 3) ? 1 : 0, sm);
}

// fp16-split kernel (td path; epi 3 = tanh->split out, epi 4 = bias->fp32)
__global__ void __launch_bounds__(256, 2) hgemm_h(
    const __half* __restrict__ Ah, const __half* __restrict__ Al,
    const __half* __restrict__ Bh, const __half* __restrict__ Bl,
    float* __restrict__ Cp, __half* __restrict__ Ch, __half* __restrict__ Cl,
    const float* __restrict__ e0, int N, int K, int lda, int ldb, int epi)
{
    extern __shared__ char sm[];
    hg_core<true, __half>((const uint16_t*)Ah, (const uint16_t*)Al,
        (const uint16_t*)Bh, (const uint16_t*)Bl,
        Cp, Ch, Cl, e0,
        N, K, lda, ldb, blockIdx.y * 128, blockIdx.x * 128, epi, sm);
}

// ---------------------------------------------------------------------------
// FFMA2 helpers (mix_gemm K=32, memory-bound)
// ---------------------------------------------------------------------------
__device__ __forceinline__ void fma2(ull& d, ull a, ull b){
    asm("fma.rn.f32x2 %0, %1, %2, %0;" : "+l"(d) : "l"(a), "l"(b));
}
__device__ __forceinline__ float2 unp(ull v){
    float2 r; asm("mov.b64 {%0, %1}, %2;" : "=f"(r.x), "=f"(r.y) : "l"(v)); return r;
}

// ---------------------------------------------------------------------------
// ddlerp MIX GEMM (K=32), f = blockIdx.x (fastest) for L2 reuse of x/dxa.
// f=0 -> fp16 hi/lo xx0 (w_in); f=1..4 -> bf16 hi/lo slots 0..3 (k,v,r,g).
// ---------------------------------------------------------------------------
__global__ void __launch_bounds__(256) mix_gemm(
    const float* __restrict__ lorap, const float* __restrict__ BloraT,
    const float* __restrict__ x, const float* __restrict__ dxa,
    const float* __restrict__ lam,
    __half* __restrict__ xx0h, __half* __restrict__ xx0l,
    __nv_bfloat16* __restrict__ abh, __nv_bfloat16* __restrict__ abl)
{
    __shared__ __align__(16) float As2[8][256];
    __shared__ __align__(16) float Bs [8][128];

    int f = blockIdx.x;
    const float* A  = lorap  + f*32;
    const float* Bm = BloraT + f*32768;
    const float* e2 = lam    + f*Cq;

    int tid  = threadIdx.x;
    int m0   = blockIdx.y * 128, n0 = blockIdx.z * 128;
    int lrow = tid >> 1;
    int lkq  = (tid & 1) * 4;
    const float* Ap = A  + (size_t)(m0 + lrow) * 256 + lkq;
    const float* Bp = Bm + (size_t)(n0 + lrow) * 32  + lkq;
    int ty = tid >> 4, tx = tid & 15;

    ull acc[8][4];
    #pragma unroll
    for (int i = 0; i < 8; i++)
        #pragma unroll
        for (int p = 0; p < 4; p++) acc[i][p] = 0ull;

    for (int k0 = 0; k0 < 32; k0 += 8) {
        float4 av = *(const float4*)(Ap + k0);
        float4 bv = *(const float4*)(Bp + k0);
        *(float2*)&As2[lkq+0][2*lrow] = make_float2(av.x, av.x);
        *(float2*)&As2[lkq+1][2*lrow] = make_float2(av.y, av.y);
        *(float2*)&As2[lkq+2][2*lrow] = make_float2(av.z, av.z);
        *(float2*)&As2[lkq+3][2*lrow] = make_float2(av.w, av.w);
        Bs[lkq+0][lrow] = bv.x;
        Bs[lkq+1][lrow] = bv.y;
        Bs[lkq+2][lrow] = bv.z;
        Bs[lkq+3][lrow] = bv.w;
        __syncthreads();
        #pragma unroll
        for (int kk = 0; kk < 8; kk++) {
            const ull* ar = (const ull*)As2[kk];
            const ull* br = (const ull*)Bs[kk];
            ull a_[8], b_[4];
            #pragma unroll
            for (int i = 0; i < 8; i++) a_[i] = ar[ty*8 + i];
            #pragma unroll
            for (int p = 0; p < 4; p++) b_[p] = br[tx*4 + p];
            #pragma unroll
            for (int i = 0; i < 8; i++)
                #pragma unroll
                for (int p = 0; p < 4; p++) fma2(acc[i][p], a_[i], b_[p]);
        }
        __syncthreads();
    }

    #pragma unroll
    for (int i = 0; i < 8; i++) {
        size_t m = (size_t)(m0 + ty*8 + i);
        #pragma unroll
        for (int p = 0; p < 4; p++) {
            float2 vv = unp(acc[i][p]);
            int n = n0 + tx*8 + 2*p;
            size_t idx = m * (size_t)Cq + n;
            float vx = x[idx]   + dxa[idx]   * (e2[n]   + vv.x);
            float vy = x[idx+1] + dxa[idx+1] * (e2[n+1] + vv.y);
            if (f == 0) {
                __half hx, lx, hy, ly;
                splitv(vx, hx, lx); splitv(vy, hy, ly);
                __half2 hp; hp.x = hx; hp.y = hy;
                __half2 lp; lp.x = lx; lp.y = ly;
                *(__half2*)(xx0h + idx) = hp;
                *(__half2*)(xx0l + idx) = lp;
            } else {
                size_t o = (size_t)(f-1) * SZq + idx;
                __nv_bfloat162 hp, lp;
                splitv(vx, hp.x, lp.x);
                splitv(vy, hp.y, lp.y);
                *(__nv_bfloat162*)(abh + o) = hp;
                *(__nv_bfloat162*)(abl + o) = lp;
            }
        }
    }
}

// ---------------------------------------------------------------------------
// prep: dxa = shift(x) - x (fp32) ; xm = x + dxa * miu_x -> bf16 hi/lo
// ---------------------------------------------------------------------------
__global__ void __launch_bounds__(256) prep_kernel(
    const float4* __restrict__ x4, const float4* __restrict__ mu4,
    float4* __restrict__ dxa4,
    __nv_bfloat16* __restrict__ xmh, __nv_bfloat16* __restrict__ xml)
{
    size_t i = (size_t)blockIdx.x * 256 + threadIdx.x;
    int m = (int)(i >> 8);
    int t = m & (Tq - 1);
    float4 xv = x4[i];
    float4 xl = make_float4(0.f, 0.f, 0.f, 0.f);
    if (t) xl = x4[i - 256];
    float4 mu = mu4[i & 255];
    float4 d  = make_float4(xl.x - xv.x, xl.y - xv.y, xl.z - xv.z, xl.w - xv.w);
    float xm0 = fmaf(d.x, mu.x, xv.x), xm1 = fmaf(d.y, mu.y, xv.y);
    float xm2 = fmaf(d.z, mu.z, xv.z), xm3 = fmaf(d.w, mu.w, xv.w);
    dxa4[i] = d;
    __nv_bfloat162 h0, l0, h1, l1;
    splitv(xm0, h0.x, l0.x); splitv(xm1, h0.y, l0.y);
    splitv(xm2, h1.x, l1.x); splitv(xm3, h1.y, l1.y);
    ((__nv_bfloat162*)xmh)[i*2]   = h0;
    ((__nv_bfloat162*)xmh)[i*2+1] = h1;
    ((__nv_bfloat162*)xml)[i*2]   = l0;
    ((__nv_bfloat162*)xml)[i*2+1] = l1;
}

// ---------------------------------------------------------------------------
// transposes: AloraT -> bf16 hi/lo; tdAT, tdBT -> fp16 hi/lo; BloraT fp32
// ---------------------------------------------------------------------------
__global__ void __launch_bounds__(256) transpose_all(
    __nv_bfloat16* __restrict__ AloraTh, __nv_bfloat16* __restrict__ AloraTl,
    const float* __restrict__ A_lora,
    __half* __restrict__ tdATh, __half* __restrict__ tdATl,
    const float* __restrict__ td_A,
    __half* __restrict__ tdBTh, __half* __restrict__ tdBTl,
    const float* __restrict__ td_B,
    float* __restrict__ BloraT, const float* __restrict__ B_lora)
{
    int i = blockIdx.x * 256 + threadIdx.x;
    if (i < 262144) {
        int n = i >> 10, k = i & 1023;
        float v = (n < 160) ? A_lora[k*160 + n] : 0.f;
        __nv_bfloat16 h, l; splitv(v, h, l);
        AloraTh[i] = h; AloraTl[i] = l;
    } else if (i < 393216) {
        int j = i - 262144; int n = j >> 10, k = j & 1023;
        float v = (n < 64) ? td_A[k*64 + n] : 0.f;
        __half h, l; splitv(v, h, l);
        tdATh[j] = h; tdATl[j] = l;
    } else if (i < 458752) {
        int j = i - 393216; int n = j >> 6, k = j & 63;
        float v = td_B[k*1024 + n];
        __half h, l; splitv(v, h, l);
        tdBTh[j] = h; tdBTl[j] = l;
    } else if (i < 622592) {
        int j = i - 458752;
        int f = j >> 15, rr = j & 32767, n = rr >> 5, k = rr & 31;
        BloraT[j] = B_lora[(f*32 + k)*1024 + n];
    }
}

// ---------------------------------------------------------------------------
// Weight bf16 hi/lo conversion (Wk,Wv,Wr,Wg,Wo)
// ---------------------------------------------------------------------------
__global__ void __launch_bounds__(256) wconv_kernel(
    const float* __restrict__ w0, const float* __restrict__ w1,
    const float* __restrict__ w2, const float* __restrict__ w3,
    const float* __restrict__ w4,
    __nv_bfloat16* __restrict__ h, __nv_bfloat16* __restrict__ l)
{
    int i = blockIdx.x * 256 + threadIdx.x;
    int w = i >> 20;
    int j = i & 1048575;
    const float* src = (w == 0) ? w0 : (w == 1) ? w1 : (w == 2) ? w2 : (w == 3) ? w3 : w4;
    float x = src[j];
    __nv_bfloat16 hh, ll; splitv(x, hh, ll);
    h[i] = hh;
    l[i] = ll;
}

// ---------------------------------------------------------------------------
// WKV6 scan — software-pipelined: t+1 global loads overlap compute of t.
// ---------------------------------------------------------------------------
__global__ void __launch_bounds__(256) wkv6_kernel(
    const float* __restrict__ rp, const float* __restrict__ kp,
    const float* __restrict__ vp, const float* __restrict__ wp,
    const float* __restrict__ up, float* __restrict__ yp)
{
    __shared__ float4 pk[2][4][17];
    __shared__ float  sv[2][64];
    int bh = blockIdx.x;
    int b = bh >> 4, h = bh & 15;
    size_t base = ((size_t)b * Tq) * Cq + h * 64;
    int tid = threadIdx.x;
    int j = tid >> 2, rg = tid & 3;
    float uu = 0.f;
    if (tid < 64) uu = up[h * 64 + tid];
    float S[16];
    #pragma unroll
    for (int i = 0; i < 16; i++) S[i] = 0.f;

    float lk = 0.f, lr = 0.f, lw = 0.f, lv = 0.f;
    if (tid < 64){
        lk = kp[base + tid]; lr = rp[base + tid];
        lw = wp[base + tid]; lv = vp[base + tid];
    }

    for (int t = 0; t < Tq; t++) {
        int buf = t & 1;
        size_t off = base + (size_t)t * Cq;
        if (tid < 64) {
            sv[buf][tid] = lv;
            float dd = expf(-expf(lw));
            pk[buf][tid >> 4][tid & 15] = make_float4(lk, uu * lk, lr, dd);
        }
        __syncthreads();
        if (t + 1 < Tq && tid < 64){
            size_t o2 = off + Cq + tid;
            lk = kp[o2]; lr = rp[o2]; lw = wp[o2]; lv = vp[o2];
        }
        float vj = sv[buf][j];
        float yv = 0.f;
        #pragma unroll
        for (int ii = 0; ii < 16; ii++) {
            float4 p = pk[buf][rg][ii];
            float s = S[ii];
            yv = fmaf(p.z, fmaf(p.y, vj, s), yv);
            S[ii] = fmaf(p.w, s, p.x * vj);
        }
        yv += __shfl_xor_sync(0xffffffffu, yv, 1);
        yv += __shfl_xor_sync(0xffffffffu, yv, 2);
        if (rg == 0) yp[off + j] = yv;
    }
}

// ---------------------------------------------------------------------------
// GroupNorm * gate -> bf16 hi/lo
// ---------------------------------------------------------------------------
__global__ void __launch_bounds__(256) gnorm_kernel(
    const float* __restrict__ y, const float* __restrict__ g,
    const float* __restrict__ gamma, const float* __restrict__ beta,
    __nv_bfloat16* __restrict__ ygh, __nv_bfloat16* __restrict__ ygl)
{
    int m = blockIdx.x, tid = threadIdx.x;
    size_t i4 = (size_t)m * 256 + tid;
    float4 yv = ((const float4*)y)[i4];
    float s  = yv.x + yv.y + yv.z + yv.w;
    float ss = yv.x*yv.x + yv.y*yv.y + yv.z*yv.z + yv.w*yv.w;
    #pragma unroll
    for (int o = 1; o < 16; o <<= 1) {
        s  += __shfl_xor_sync(0xffffffffu, s,  o);
        ss += __shfl_xor_sync(0xffffffffu, ss, o);
    }
    float mean = s * (1.f / 64.f);
    float var  = ss * (1.f / 64.f) - mean * mean;
    float rstd = rsqrtf(fmaxf(var, 0.f) + 1.6e-4f);
    float4 ga = ((const float4*)gamma)[tid];
    float4 be = ((const float4*)beta)[tid];
    float4 gv = ((const float4*)g)[i4];
    float o0 = ((yv.x - mean) * rstd * ga.x + be.x) * gv.x;
    float o1 = ((yv.y - mean) * rstd * ga.y + be.y) * gv.y;
    float o2 = ((yv.z - mean) * rstd * ga.z + be.z) * gv.z;
    float o3 = ((yv.w - mean) * rstd * ga.w + be.w) * gv.w;

    __nv_bfloat162 hp0, lp0, hp1, lp1;
    splitv(o0, hp0.x, lp0.x); splitv(o1, hp0.y, lp0.y);
    splitv(o2, hp1.x, lp1.x); splitv(o3, hp1.y, lp1.y);
    ((__nv_bfloat162*)ygh)[i4*2]   = hp0;
    ((__nv_bfloat162*)ygh)[i4*2+1] = hp1;
    ((__nv_bfloat162*)ygl)[i4*2]   = lp0;
    ((__nv_bfloat162*)ygl)[i4*2+1] = lp1;
}

// ---------------------------------------------------------------------------
// Launch
// ---------------------------------------------------------------------------
extern "C" void kernel_launch(void* const* d_in, const int* in_sizes, int n_in,
                              void* d_out, int out_size)
{
    (void)in_sizes; (void)n_in; (void)out_size;
    const float* x       = (const float*)d_in[0];
    const float* miu_x   = (const float*)d_in[1];
    const float* lambda_ = (const float*)d_in[2];
    const float* A_lora  = (const float*)d_in[3];
    const float* B_lora  = (const float*)d_in[4];
    const float* td_miu  = (const float*)d_in[5];
    const float* td_A    = (const float*)d_in[6];
    const float* td_B    = (const float*)d_in[7];
    const float* u       = (const float*)d_in[8];
    const float* Wr      = (const float*)d_in[9];
    const float* Wk      = (const float*)d_in[10];
    const float* Wv      = (const float*)d_in[11];
    const float* Wg      = (const float*)d_in[12];
    const float* Wo      = (const float*)d_in[13];
    const float* gamma   = (const float*)d_in[14];
    const float* beta    = (const float*)d_in[15];
    float* out = (float*)d_out;

    float *p_dxa,*p_k,*p_v,*p_r,*p_g,*p_w,*p_y,*p_lorap,*p_BloraT;
    __nv_bfloat16 *p_xmh,*p_xml,*p_abh,*p_abl,*p_ygh,*p_ygl,*p_wbh,*p_wbl,
                  *p_AloraTh,*p_AloraTl;
    __half *p_xx0h,*p_xx0l,*p_tdhh,*p_tdhl,*p_tdATh,*p_tdATl,*p_tdBTh,*p_tdBTl;
    { void* t;
      cudaGetSymbolAddress(&t, g_dxa);     p_dxa     = (float*)t;
      cudaGetSymbolAddress(&t, g_k);       p_k       = (float*)t;
      cudaGetSymbolAddress(&t, g_v);       p_v       = (float*)t;
      cudaGetSymbolAddress(&t, g_r);       p_r       = (float*)t;
      cudaGetSymbolAddress(&t, g_g);       p_g       = (float*)t;
      cudaGetSymbolAddress(&t, g_w);       p_w       = (float*)t;
      cudaGetSymbolAddress(&t, g_y);       p_y       = (float*)t;
      cudaGetSymbolAddress(&t, g_lorap);   p_lorap   = (float*)t;
      cudaGetSymbolAddress(&t, g_BloraT);  p_BloraT  = (float*)t;
      cudaGetSymbolAddress(&t, g_xmh);     p_xmh     = (__nv_bfloat16*)t;
      cudaGetSymbolAddress(&t, g_xml);     p_xml     = (__nv_bfloat16*)t;
      cudaGetSymbolAddress(&t, g_abh);     p_abh     = (__nv_bfloat16*)t;
      cudaGetSymbolAddress(&t, g_abl);     p_abl     = (__nv_bfloat16*)t;
      cudaGetSymbolAddress(&t, g_ygh);     p_ygh     = (__nv_bfloat16*)t;
      cudaGetSymbolAddress(&t, g_ygl);     p_ygl     = (__nv_bfloat16*)t;
      cudaGetSymbolAddress(&t, g_wbh);     p_wbh     = (__nv_bfloat16*)t;
      cudaGetSymbolAddress(&t, g_wbl);     p_wbl     = (__nv_bfloat16*)t;
      cudaGetSymbolAddress(&t, g_AloraTh); p_AloraTh = (__nv_bfloat16*)t;
      cudaGetSymbolAddress(&t, g_AloraTl); p_AloraTl = (__nv_bfloat16*)t;
      cudaGetSymbolAddress(&t, g_xx0h);    p_xx0h    = (__half*)t;
      cudaGetSymbolAddress(&t, g_xx0l);    p_xx0l    = (__half*)t;
      cudaGetSymbolAddress(&t, g_tdhh);    p_tdhh    = (__half*)t;
      cudaGetSymbolAddress(&t, g_tdhl);    p_tdhl    = (__half*)t;
      cudaGetSymbolAddress(&t, g_tdATh);   p_tdATh   = (__half*)t;
      cudaGetSymbolAddress(&t, g_tdATl);   p_tdATl   = (__half*)t;
      cudaGetSymbolAddress(&t, g_tdBTh);   p_tdBTh   = (__half*)t;
      cudaGetSymbolAddress(&t, g_tdBTl);   p_tdBTl   = (__half*)t;
    }

    cudaFuncSetAttribute(hgemm_one,  cudaFuncAttributeMaxDynamicSharedMemorySize, HG_SMEM);
    cudaFuncSetAttribute(hgemm_kvrg, cudaFuncAttributeMaxDynamicSharedMemorySize, HG_SMEM);
    cudaFuncSetAttribute(hgemm_h,    cudaFuncAttributeMaxDynamicSharedMemorySize, HG_SMEM);

    // 0: token shift + static lerp (xm -> bf16 hi/lo)
    prep_kernel<<<BTq * Cq / 4 / 256, 256>>>((const float4*)x, (const float4*)miu_x,
                                             (float4*)p_dxa, p_xmh, p_xml);
    // 1: weight transposes
    transpose_all<<<(622592 + 255) / 256, 256>>>(p_AloraTh, p_AloraTl, A_lora,
                                                 p_tdATh, p_tdATl, td_A,
                                                 p_tdBTh, p_tdBTl, td_B,
                                                 p_BloraT, B_lora);
    // 2: big weight hi/lo
    wconv_kernel<<<5 * 1048576 / 256, 256>>>(Wk, Wv, Wr, Wg, Wo, p_wbh, p_wbl);
    // 3: lora_h = tanh(xm @ A_lora)
    hgemm_one<<<dim3(2, 128), 256, HG_SMEM>>>(p_xmh, p_xml, p_AloraTh, p_AloraTl,
                                              p_lorap, 256, Cq, 2);
    // 4: ddlerp mix (f=0 -> fp16 hi/lo xx0; f=1..4 -> bf16 hi/lo k,v,r,g)
    mix_gemm<<<dim3(5, 128, 8), 256>>>(p_lorap, p_BloraT, x, p_dxa, lambda_,
                                       p_xx0h, p_xx0l, p_abh, p_abl);
    // 5: merged projections k, v, r, g
    hgemm_kvrg<<<dim3(8, 128, 4), 256, HG_SMEM>>>(p_abh, p_abl, p_wbh, p_wbl,
                                                  p_k, p_v, p_r, p_g);
    // 6: tdh = tanh(w_in @ td_A) -> fp16 hi/lo (padded N=128)
    hgemm_h<<<dim3(1, 128), 256, HG_SMEM>>>(p_xx0h, p_xx0l, p_tdATh, p_tdATl,
                                            nullptr, p_tdhh, p_tdhl, nullptr,
                                            128, Cq, Cq, Cq, 3);
    // 7: w = td_miu + tdh @ td_B   (A stride 128, K=64)
    hgemm_h<<<dim3(8, 128), 256, HG_SMEM>>>(p_tdhh, p_tdhl, p_tdBTh, p_tdBTl,
                                            p_w, nullptr, nullptr, td_miu,
                                            Cq, 64, 128, 64, 4);
    // 8: WKV6 scan
    wkv6_kernel<<<Bq * Hq, 256>>>(p_r, p_k, p_v, p_w, u, p_y);
    // 9: GroupNorm * gate -> bf16 hi/lo
    gnorm_kernel<<<BTq, 256>>>(p_y, p_g, gamma, beta, p_ygh, p_ygl);
    // 10: output projection
    hgemm_one<<<dim3(8, 128), 256, HG_SMEM>>>(p_ygh, p_ygl, p_wbh + 4*WWq, p_wbl + 4*WWq,
                                              out, Cq, Cq, 0);
}

// round 10
// speedup vs baseline: 2.6634x; 1.3616x over previous
#include <cuda_runtime.h>
#include <cuda_bf16.h>
#include <cuda_fp16.h>
#include <math.h>
#include <stdint.h>

#define Bq 8
#define Tq 2048
#define Cq 1024
#define Hq 16
#define BTq (Bq*Tq)
#define WWq (Cq*Cq)

typedef unsigned long long ull;
static const size_t SZq = (size_t)BTq * Cq;

// ---------------------------------------------------------------------------
// Scratch (static device globals — no runtime allocation)
// ---------------------------------------------------------------------------
__device__ float g_dxa [BTq*Cq];
__device__ float g_k   [BTq*Cq];
__device__ float g_v   [BTq*Cq];
__device__ float g_r   [BTq*Cq];
__device__ float g_g   [BTq*Cq];
__device__ float g_w   [BTq*Cq];
__device__ float g_y   [BTq*Cq];
__device__ float g_lorap [BTq*256];          // tanh(xm @ A_lora) fp32 (padded 256)
__device__ float g_BloraT[5*1024*32];        // B_lora^T per branch, fp32

__device__ __nv_bfloat16 g_xmh[BTq*Cq];      // xm hi/lo (bf16 split)
__device__ __nv_bfloat16 g_xml[BTq*Cq];
__device__ __nv_bfloat16 g_abh[4*BTq*Cq];    // k,v,r,g branch inputs hi
__device__ __nv_bfloat16 g_abl[4*BTq*Cq];    // lo
__device__ __nv_bfloat16 g_ygh[BTq*Cq];
__device__ __nv_bfloat16 g_ygl[BTq*Cq];
__device__ __nv_bfloat16 g_wbh[5*WWq];       // Wk,Wv,Wr,Wg,Wo hi
__device__ __nv_bfloat16 g_wbl[5*WWq];       // lo
__device__ __nv_bfloat16 g_AloraTh[256*1024];
__device__ __nv_bfloat16 g_AloraTl[256*1024];

// fp16-split td path (2^-22 residual — precision-safe for the decay scan)
__device__ __half g_xx0h[BTq*Cq];            // w_in branch hi/lo
__device__ __half g_xx0l[BTq*Cq];
__device__ __half g_tdhh[BTq*128];           // tanh(w_in @ td_A) hi/lo (padded 128)
__device__ __half g_tdhl[BTq*128];
__device__ __half g_tdATh[128*1024];
__device__ __half g_tdATl[128*1024];
__device__ __half g_tdBTh[1024*64];
__device__ __half g_tdBTl[1024*64];

// ---------------------------------------------------------------------------
// PTX helpers (sm_80+ — valid on compute_103 virtual arch)
// ---------------------------------------------------------------------------
__device__ __forceinline__ uint32_t sm2u32(const void* p){
    uint32_t a;
    asm("{ .reg .u64 t; cvta.to.shared.u64 t, %1; cvt.u32.u64 %0, t; }" : "=r"(a) : "l"(p));
    return a;
}
__device__ __forceinline__ void cpa16(uint32_t dst, const void* src){
    asm volatile("cp.async.cg.shared.global [%0], [%1], 16;" :: "r"(dst), "l"(src) : "memory");
}
__device__ __forceinline__ void cpa_commit(){
    asm volatile("cp.async.commit_group;" ::: "memory");
}
template<int N>
__device__ __forceinline__ void cpa_wait(){
    asm volatile("cp.async.wait_group %0;" :: "n"(N) : "memory");
}
__device__ __forceinline__ void ldsm_x4(uint32_t* r, uint32_t addr){
    asm volatile("ldmatrix.sync.aligned.m8n8.x4.shared.b16 {%0,%1,%2,%3}, [%4];"
        : "=r"(r[0]), "=r"(r[1]), "=r"(r[2]), "=r"(r[3]) : "r"(addr));
}
template<bool FP16>
__device__ __forceinline__ void mma_any(float* d, const uint32_t* a, const uint32_t* b){
    if (FP16){
        asm volatile("mma.sync.aligned.m16n8k16.row.col.f32.f16.f16.f32 "
            "{%0,%1,%2,%3}, {%4,%5,%6,%7}, {%8,%9}, {%0,%1,%2,%3};"
            : "+f"(d[0]), "+f"(d[1]), "+f"(d[2]), "+f"(d[3])
            : "r"(a[0]), "r"(a[1]), "r"(a[2]), "r"(a[3]), "r"(b[0]), "r"(b[1]));
    } else {
        asm volatile("mma.sync.aligned.m16n8k16.row.col.f32.bf16.bf16.f32 "
            "{%0,%1,%2,%3}, {%4,%5,%6,%7}, {%8,%9}, {%0,%1,%2,%3};"
            : "+f"(d[0]), "+f"(d[1]), "+f"(d[2]), "+f"(d[3])
            : "r"(a[0]), "r"(a[1]), "r"(a[2]), "r"(a[3]), "r"(b[0]), "r"(b[1]));
    }
}
__device__ __forceinline__ void splitv(float v, __nv_bfloat16& h, __nv_bfloat16& l){
    h = __float2bfloat16(v);
    l = __float2bfloat16(v - __bfloat162float(h));
}
__device__ __forceinline__ void splitv(float v, __half& h, __half& l){
    h = __float2half_rn(v);
    l = __float2half_rn(v - __half2float(h));
}
__device__ __forceinline__ uint16_t u16of(__half v){ return *(uint16_t*)&v; }
__device__ __forceinline__ uint16_t u16of(__nv_bfloat16 v){ return *(uint16_t*)&v; }

// ---------------------------------------------------------------------------
// split GEMM core via mma.sync (proven round-9 structure)
// ---------------------------------------------------------------------------
#define NSTAGE    4
#define STG_ARR   6144                 // 128 rows * 48B
#define STG_BYTES 24576                // 4 arrays
#define HG_SMEM   (NSTAGE * STG_BYTES) // 98304

template<bool FP16, typename OT>
__device__ __forceinline__ void hg_core(
    const uint16_t* __restrict__ Ah, const uint16_t* __restrict__ Al,
    const uint16_t* __restrict__ Bh, const uint16_t* __restrict__ Bl,
    float* __restrict__ Cp, OT* __restrict__ Ch, OT* __restrict__ Cl,
    const float* __restrict__ e0,
    int N, int K, int lda, int ldb, int m0, int n0, int epi, char* sm)
{
    int tid = threadIdx.x, lane = tid & 31, wid = tid >> 5;
    int wy = wid & 1, wx = wid >> 1;
    uint32_t sb = sm2u32(sm);

    int arr0 = tid >> 7;
    int rowa = tid & 127;
    const uint16_t* p0 = ((arr0 == 0) ? Ah : Al) + (size_t)(m0 + rowa) * lda;
    const uint16_t* p1 = ((arr0 == 0) ? Bh : Bl) + (size_t)(n0 + rowa) * ldb;
    uint32_t so0 = (uint32_t)(arr0 * STG_ARR + rowa * 48);
    uint32_t so1 = so0 + 2 * STG_ARR;

    float acc[4][4][4];
    #pragma unroll
    for (int i = 0; i < 4; i++)
        #pragma unroll
        for (int j = 0; j < 4; j++)
            #pragma unroll
            for (int q = 0; q < 4; q++) acc[i][j][q] = 0.f;

    uint32_t a_row = (uint32_t)(wy * 64 + (lane & 15));
    uint32_t a_kh  = (uint32_t)((lane >> 4) * 8);
    uint32_t b_row0 = (uint32_t)(wx * 32 + (lane & 7) + ((lane >> 4) * 8));
    uint32_t b_kh   = (uint32_t)(((lane >> 3) & 1) * 8);

    const int NC = K >> 4;

    #pragma unroll
    for (int s = 0; s < 3; s++){
        uint32_t d = sb + (uint32_t)s * STG_BYTES;
        int kk = s * 16;
        cpa16(d + so0,      p0 + kk);  cpa16(d + so0 + 16, p0 + kk + 8);
        cpa16(d + so1,      p1 + kk);  cpa16(d + so1 + 16, p1 + kk + 8);
        cpa_commit();
    }

    #pragma unroll 4
    for (int c = 0; c < NC; c++){
        cpa_wait<2>();
        __syncthreads();
        if (c + 3 < NC){
            uint32_t d = sb + (uint32_t)((c + 3) & 3) * STG_BYTES;
            int kk = (c + 3) << 4;
            cpa16(d + so0,      p0 + kk);  cpa16(d + so0 + 16, p0 + kk + 8);
            cpa16(d + so1,      p1 + kk);  cpa16(d + so1 + 16, p1 + kk + 8);
        }
        cpa_commit();

        uint32_t base = sb + (uint32_t)(c & 3) * STG_BYTES;

        uint32_t bh[2][4], bl[2][4];
        #pragma unroll
        for (int bi = 0; bi < 2; bi++){
            uint32_t bo = base + 2*STG_ARR + (b_row0 + bi * 16) * 48 + b_kh * 2;
            ldsm_x4(bh[bi], bo);
            ldsm_x4(bl[bi], bo + STG_ARR);
        }
        #pragma unroll
        for (int mf = 0; mf < 4; mf++){
            uint32_t ah[4], al[4];
            uint32_t ao = base + (a_row + mf * 16) * 48 + a_kh * 2;
            ldsm_x4(ah, ao);
            ldsm_x4(al, ao + STG_ARR);
            #pragma unroll
            for (int nf = 0; nf < 4; nf++){
                const uint32_t* bhp = &bh[nf >> 1][(nf & 1) * 2];
                const uint32_t* blp = &bl[nf >> 1][(nf & 1) * 2];
                mma_any<FP16>(acc[mf][nf], ah, bhp);
                mma_any<FP16>(acc[mf][nf], ah, blp);
                mma_any<FP16>(acc[mf][nf], al, bhp);
            }
        }
    }

    #pragma unroll
    for (int mf = 0; mf < 4; mf++){
        int row0 = m0 + wy * 64 + mf * 16 + (lane >> 2);
        #pragma unroll
        for (int nf = 0; nf < 4; nf++){
            int col = n0 + wx * 32 + nf * 8 + (lane & 3) * 2;
            float v[4] = {acc[mf][nf][0], acc[mf][nf][1], acc[mf][nf][2], acc[mf][nf][3]};
            if (epi == 1){
                #pragma unroll
                for (int q = 0; q < 4; q++) v[q] = v[q] / (1.f + expf(-v[q]));
            } else if (epi == 2 || epi == 3){
                #pragma unroll
                for (int q = 0; q < 4; q++) v[q] = tanhf(v[q]);
            } else if (epi == 4){
                v[0] += e0[col]; v[1] += e0[col+1];
                v[2] += e0[col]; v[3] += e0[col+1];
            }
            size_t i01 = (size_t)row0 * N + col;
            size_t i23 = (size_t)(row0 + 8) * N + col;
            if (epi == 3){
                OT h[4], l[4];
                #pragma unroll
                for (int q = 0; q < 4; q++) splitv(v[q], h[q], l[q]);
                *(uint32_t*)(Ch + i01) = (uint32_t)u16of(h[0]) | ((uint32_t)u16of(h[1]) << 16);
                *(uint32_t*)(Cl + i01) = (uint32_t)u16of(l[0]) | ((uint32_t)u16of(l[1]) << 16);
                *(uint32_t*)(Ch + i23) = (uint32_t)u16of(h[2]) | ((uint32_t)u16of(h[3]) << 16);
                *(uint32_t*)(Cl + i23) = (uint32_t)u16of(l[2]) | ((uint32_t)u16of(l[3]) << 16);
            } else {
                *(float2*)(Cp + i01) = make_float2(v[0], v[1]);
                *(float2*)(Cp + i23) = make_float2(v[2], v[3]);
            }
        }
    }
}

__global__ void __launch_bounds__(256, 2) hgemm_one(
    const __nv_bfloat16* __restrict__ Ah, const __nv_bfloat16* __restrict__ Al,
    const __nv_bfloat16* __restrict__ Bh, const __nv_bfloat16* __restrict__ Bl,
    float* __restrict__ Cp, int N, int K, int epi)
{
    extern __shared__ char sm[];
    hg_core<false, __nv_bfloat16>((const uint16_t*)Ah, (const uint16_t*)Al,
        (const uint16_t*)Bh, (const uint16_t*)Bl,
        Cp, (__nv_bfloat16*)nullptr, (__nv_bfloat16*)nullptr, nullptr,
        N, K, K, K, blockIdx.y * 128, blockIdx.x * 128, epi, sm);
}

__global__ void __launch_bounds__(256, 2) hgemm_kvrg(
    const __nv_bfloat16* __restrict__ abh, const __nv_bfloat16* __restrict__ abl,
    const __nv_bfloat16* __restrict__ wbh, const __nv_bfloat16* __restrict__ wbl,
    float* __restrict__ C0, float* __restrict__ C1,
    float* __restrict__ C2, float* __restrict__ C3)
{
    extern __shared__ char sm[];
    int z = blockIdx.z;
    float* Cp = (z == 0) ? C0 : (z == 1) ? C1 : (z == 2) ? C2 : C3;
    hg_core<false, __nv_bfloat16>(
        (const uint16_t*)(abh + (size_t)z * SZq), (const uint16_t*)(abl + (size_t)z * SZq),
        (const uint16_t*)(wbh + (size_t)z * WWq), (const uint16_t*)(wbl + (size_t)z * WWq),
        Cp, (__nv_bfloat16*)nullptr, (__nv_bfloat16*)nullptr, nullptr,
        Cq, Cq, Cq, Cq, blockIdx.y * 128, blockIdx.x * 128, (z == 3) ? 1 : 0, sm);
}

__global__ void __launch_bounds__(256, 2) hgemm_h(
    const __half* __restrict__ Ah, const __half* __restrict__ Al,
    const __half* __restrict__ Bh, const __half* __restrict__ Bl,
    float* __restrict__ Cp, __half* __restrict__ Ch, __half* __restrict__ Cl,
    const float* __restrict__ e0, int N, int K, int lda, int ldb, int epi)
{
    extern __shared__ char sm[];
    hg_core<true, __half>((const uint16_t*)Ah, (const uint16_t*)Al,
        (const uint16_t*)Bh, (const uint16_t*)Bl,
        Cp, Ch, Cl, e0,
        N, K, lda, ldb, blockIdx.y * 128, blockIdx.x * 128, epi, sm);
}

// ---------------------------------------------------------------------------
// FFMA2 helpers
// ---------------------------------------------------------------------------
__device__ __forceinline__ void fma2(ull& d, ull a, ull b){
    asm("fma.rn.f32x2 %0, %1, %2, %0;" : "+l"(d) : "l"(a), "l"(b));
}
__device__ __forceinline__ float2 unp(ull v){
    float2 r; asm("mov.b64 {%0, %1}, %2;" : "=f"(r.x), "=f"(r.y) : "l"(v)); return r;
}

// ---------------------------------------------------------------------------
// ddlerp MIX GEMM (K=32), SINGLE load phase (all K in smem), ONE barrier.
// f = blockIdx.x (fastest) for L2 reuse of x/dxa.
// f=0 -> fp16 hi/lo xx0 (w_in); f=1..4 -> bf16 hi/lo slots 0..3 (k,v,r,g).
// ---------------------------------------------------------------------------
__global__ void __launch_bounds__(256) mix_gemm(
    const float* __restrict__ lorap, const float* __restrict__ BloraT,
    const float* __restrict__ x, const float* __restrict__ dxa,
    const float* __restrict__ lam,
    __half* __restrict__ xx0h, __half* __restrict__ xx0l,
    __nv_bfloat16* __restrict__ abh, __nv_bfloat16* __restrict__ abl)
{
    __shared__ __align__(16) float As2[32][256];   // 32 KB (A duplicated)
    __shared__ __align__(16) float Bs [32][128];   // 16 KB

    int f = blockIdx.x;
    const float* A  = lorap  + f*32;
    const float* Bm = BloraT + f*32768;
    const float* e2 = lam    + f*Cq;

    int tid  = threadIdx.x;
    int m0   = blockIdx.y * 128, n0 = blockIdx.z * 128;
    int ty = tid >> 4, tx = tid & 15;

    // single load phase: 4 float4 of A + 4 float4 of B per thread
    #pragma unroll
    for (int t2 = 0; t2 < 4; t2++){
        int i = t2 * 256 + tid;          // 0..1023
        int row = i >> 3, q = (i & 7) * 4;
        float4 av = *(const float4*)(A + (size_t)(m0 + row) * 256 + q);
        *(float2*)&As2[q+0][2*row] = make_float2(av.x, av.x);
        *(float2*)&As2[q+1][2*row] = make_float2(av.y, av.y);
        *(float2*)&As2[q+2][2*row] = make_float2(av.z, av.z);
        *(float2*)&As2[q+3][2*row] = make_float2(av.w, av.w);
        float4 bv = *(const float4*)(Bm + (size_t)(n0 + row) * 32 + q);
        Bs[q+0][row] = bv.x;
        Bs[q+1][row] = bv.y;
        Bs[q+2][row] = bv.z;
        Bs[q+3][row] = bv.w;
    }
    __syncthreads();

    ull acc[8][4];
    #pragma unroll
    for (int i = 0; i < 8; i++)
        #pragma unroll
        for (int p = 0; p < 4; p++) acc[i][p] = 0ull;

    #pragma unroll 8
    for (int kk = 0; kk < 32; kk++) {
        const ull* ar = (const ull*)As2[kk];
        const ull* br = (const ull*)Bs[kk];
        ull a_[8], b_[4];
        #pragma unroll
        for (int i = 0; i < 8; i++) a_[i] = ar[ty*8 + i];
        #pragma unroll
        for (int p = 0; p < 4; p++) b_[p] = br[tx*4 + p];
        #pragma unroll
        for (int i = 0; i < 8; i++)
            #pragma unroll
            for (int p = 0; p < 4; p++) fma2(acc[i][p], a_[i], b_[p]);
    }

    #pragma unroll
    for (int i = 0; i < 8; i++) {
        size_t m = (size_t)(m0 + ty*8 + i);
        #pragma unroll
        for (int p = 0; p < 4; p++) {
            float2 vv = unp(acc[i][p]);
            int n = n0 + tx*8 + 2*p;
            size_t idx = m * (size_t)Cq + n;
            float vx = x[idx]   + dxa[idx]   * (e2[n]   + vv.x);
            float vy = x[idx+1] + dxa[idx+1] * (e2[n+1] + vv.y);
            if (f == 0) {
                __half hx, lx, hy, ly;
                splitv(vx, hx, lx); splitv(vy, hy, ly);
                __half2 hp; hp.x = hx; hp.y = hy;
                __half2 lp; lp.x = lx; lp.y = ly;
                *(__half2*)(xx0h + idx) = hp;
                *(__half2*)(xx0l + idx) = lp;
            } else {
                size_t o = (size_t)(f-1) * SZq + idx;
                __nv_bfloat162 hp, lp;
                splitv(vx, hp.x, lp.x);
                splitv(vy, hp.y, lp.y);
                *(__nv_bfloat162*)(abh + o) = hp;
                *(__nv_bfloat162*)(abl + o) = lp;
            }
        }
    }
}

// ---------------------------------------------------------------------------
// prep: dxa = shift(x) - x (fp32) ; xm = x + dxa * miu_x -> bf16 hi/lo
// ---------------------------------------------------------------------------
__global__ void __launch_bounds__(256) prep_kernel(
    const float4* __restrict__ x4, const float4* __restrict__ mu4,
    float4* __restrict__ dxa4,
    __nv_bfloat16* __restrict__ xmh, __nv_bfloat16* __restrict__ xml)
{
    size_t i = (size_t)blockIdx.x * 256 + threadIdx.x;
    int m = (int)(i >> 8);
    int t = m & (Tq - 1);
    float4 xv = x4[i];
    float4 xl = make_float4(0.f, 0.f, 0.f, 0.f);
    if (t) xl = x4[i - 256];
    float4 mu = mu4[i & 255];
    float4 d  = make_float4(xl.x - xv.x, xl.y - xv.y, xl.z - xv.z, xl.w - xv.w);
    float xm0 = fmaf(d.x, mu.x, xv.x), xm1 = fmaf(d.y, mu.y, xv.y);
    float xm2 = fmaf(d.z, mu.z, xv.z), xm3 = fmaf(d.w, mu.w, xv.w);
    dxa4[i] = d;
    __nv_bfloat162 h0, l0, h1, l1;
    splitv(xm0, h0.x, l0.x); splitv(xm1, h0.y, l0.y);
    splitv(xm2, h1.x, l1.x); splitv(xm3, h1.y, l1.y);
    ((__nv_bfloat162*)xmh)[i*2]   = h0;
    ((__nv_bfloat162*)xmh)[i*2+1] = h1;
    ((__nv_bfloat162*)xml)[i*2]   = l0;
    ((__nv_bfloat162*)xml)[i*2+1] = l1;
}

// ---------------------------------------------------------------------------
// transposes: AloraT -> bf16 hi/lo; tdAT, tdBT -> fp16 hi/lo; BloraT fp32
// ---------------------------------------------------------------------------
__global__ void __launch_bounds__(256) transpose_all(
    __nv_bfloat16* __restrict__ AloraTh, __nv_bfloat16* __restrict__ AloraTl,
    const float* __restrict__ A_lora,
    __half* __restrict__ tdATh, __half* __restrict__ tdATl,
    const float* __restrict__ td_A,
    __half* __restrict__ tdBTh, __half* __restrict__ tdBTl,
    const float* __restrict__ td_B,
    float* __restrict__ BloraT, const float* __restrict__ B_lora)
{
    int i = blockIdx.x * 256 + threadIdx.x;
    if (i < 262144) {
        int n = i >> 10, k = i & 1023;
        float v = (n < 160) ? A_lora[k*160 + n] : 0.f;
        __nv_bfloat16 h, l; splitv(v, h, l);
        AloraTh[i] = h; AloraTl[i] = l;
    } else if (i < 393216) {
        int j = i - 262144; int n = j >> 10, k = j & 1023;
        float v = (n < 64) ? td_A[k*64 + n] : 0.f;
        __half h, l; splitv(v, h, l);
        tdATh[j] = h; tdATl[j] = l;
    } else if (i < 458752) {
        int j = i - 393216; int n = j >> 6, k = j & 63;
        float v = td_B[k*1024 + n];
        __half h, l; splitv(v, h, l);
        tdBTh[j] = h; tdBTl[j] = l;
    } else if (i < 622592) {
        int j = i - 458752;
        int f = j >> 15, rr = j & 32767, n = rr >> 5, k = rr & 31;
        BloraT[j] = B_lora[(f*32 + k)*1024 + n];
    }
}

// ---------------------------------------------------------------------------
// Weight bf16 hi/lo conversion (Wk,Wv,Wr,Wg,Wo)
// ---------------------------------------------------------------------------
__global__ void __launch_bounds__(256) wconv_kernel(
    const float* __restrict__ w0, const float* __restrict__ w1,
    const float* __restrict__ w2, const float* __restrict__ w3,
    const float* __restrict__ w4,
    __nv_bfloat16* __restrict__ h, __nv_bfloat16* __restrict__ l)
{
    int i = blockIdx.x * 256 + threadIdx.x;
    int w = i >> 20;
    int j = i & 1048575;
    const float* src = (w == 0) ? w0 : (w == 1) ? w1 : (w == 2) ? w2 : (w == 3) ? w3 : w4;
    float x = src[j];
    __nv_bfloat16 hh, ll; splitv(x, hh, ll);
    h[i] = hh;
    l[i] = ll;
}

// ---------------------------------------------------------------------------
// WKV6 scan — 4-buffer ring, ONE barrier per TWO timesteps; t+2/t+3 loads
// overlap compute of t/t+1.
// ---------------------------------------------------------------------------
__global__ void __launch_bounds__(256) wkv6_kernel(
    const float* __restrict__ rp, const float* __restrict__ kp,
    const float* __restrict__ vp, const float* __restrict__ wp,
    const float* __restrict__ up, float* __restrict__ yp)
{
    __shared__ float4 pk[4][4][17];
    __shared__ float  sv[4][64];
    int bh = blockIdx.x;
    int b = bh >> 4, h = bh & 15;
    size_t base = ((size_t)b * Tq) * Cq + h * 64;
    int tid = threadIdx.x;
    int j = tid >> 2, rg = tid & 3;
    float uu = 0.f;
    if (tid < 64) uu = up[h * 64 + tid];
    float S[16];
    #pragma unroll
    for (int i = 0; i < 16; i++) S[i] = 0.f;

    float lk0 = 0.f, lr0 = 0.f, lw0 = 0.f, lv0 = 0.f;
    float lk1 = 0.f, lr1 = 0.f, lw1 = 0.f, lv1 = 0.f;
    if (tid < 64){
        size_t o0 = base + tid;
        lk0 = kp[o0]; lr0 = rp[o0]; lw0 = wp[o0]; lv0 = vp[o0];
        size_t o1 = o0 + Cq;
        lk1 = kp[o1]; lr1 = rp[o1]; lw1 = wp[o1]; lv1 = vp[o1];
    }

    for (int t = 0; t < Tq; t += 2) {
        int b0 = t & 3, b1 = (t + 1) & 3;
        size_t off = base + (size_t)t * Cq;
        if (tid < 64) {
            sv[b0][tid] = lv0;
            pk[b0][tid >> 4][tid & 15] = make_float4(lk0, uu * lk0, lr0, expf(-expf(lw0)));
            sv[b1][tid] = lv1;
            pk[b1][tid >> 4][tid & 15] = make_float4(lk1, uu * lk1, lr1, expf(-expf(lw1)));
        }
        __syncthreads();
        if (t + 2 < Tq && tid < 64){
            size_t o2 = off + 2 * Cq + tid;
            lk0 = kp[o2]; lr0 = rp[o2]; lw0 = wp[o2]; lv0 = vp[o2];
            size_t o3 = o2 + Cq;
            lk1 = kp[o3]; lr1 = rp[o3]; lw1 = wp[o3]; lv1 = vp[o3];
        }
        // step t
        {
            float vj = sv[b0][j];
            float yv = 0.f;
            #pragma unroll
            for (int ii = 0; ii < 16; ii++) {
                float4 p = pk[b0][rg][ii];
                float s = S[ii];
                yv = fmaf(p.z, fmaf(p.y, vj, s), yv);
                S[ii] = fmaf(p.w, s, p.x * vj);
            }
            yv += __shfl_xor_sync(0xffffffffu, yv, 1);
            yv += __shfl_xor_sync(0xffffffffu, yv, 2);
            if (rg == 0) yp[off + j] = yv;
        }
        // step t+1
        {
            float vj = sv[b1][j];
            float yv = 0.f;
            #pragma unroll
            for (int ii = 0; ii < 16; ii++) {
                float4 p = pk[b1][rg][ii];
                float s = S[ii];
                yv = fmaf(p.z, fmaf(p.y, vj, s), yv);
                S[ii] = fmaf(p.w, s, p.x * vj);
            }
            yv += __shfl_xor_sync(0xffffffffu, yv, 1);
            yv += __shfl_xor_sync(0xffffffffu, yv, 2);
            if (rg == 0) yp[off + Cq + j] = yv;
        }
    }
}

// ---------------------------------------------------------------------------
// GroupNorm * gate -> bf16 hi/lo
// ---------------------------------------------------------------------------
__global__ void __launch_bounds__(256) gnorm_kernel(
    const float* __restrict__ y, const float* __restrict__ g,
    const float* __restrict__ gamma, const float* __restrict__ beta,
    __nv_bfloat16* __restrict__ ygh, __nv_bfloat16* __restrict__ ygl)
{
    int m = blockIdx.x, tid = threadIdx.x;
    size_t i4 = (size_t)m * 256 + tid;
    float4 yv = ((const float4*)y)[i4];
    float s  = yv.x + yv.y + yv.z + yv.w;
    float ss = yv.x*yv.x + yv.y*yv.y + yv.z*yv.z + yv.w*yv.w;
    #pragma unroll
    for (int o = 1; o < 16; o <<= 1) {
        s  += __shfl_xor_sync(0xffffffffu, s,  o);
        ss += __shfl_xor_sync(0xffffffffu, ss, o);
    }
    float mean = s * (1.f / 64.f);
    float var  = ss * (1.f / 64.f) - mean * mean;
    float rstd = rsqrtf(fmaxf(var, 0.f) + 1.6e-4f);
    float4 ga = ((const float4*)gamma)[tid];
    float4 be = ((const float4*)beta)[tid];
    float4 gv = ((const float4*)g)[i4];
    float o0 = ((yv.x - mean) * rstd * ga.x + be.x) * gv.x;
    float o1 = ((yv.y - mean) * rstd * ga.y + be.y) * gv.y;
    float o2 = ((yv.z - mean) * rstd * ga.z + be.z) * gv.z;
    float o3 = ((yv.w - mean) * rstd * ga.w + be.w) * gv.w;

    __nv_bfloat162 hp0, lp0, hp1, lp1;
    splitv(o0, hp0.x, lp0.x); splitv(o1, hp0.y, lp0.y);
    splitv(o2, hp1.x, lp1.x); splitv(o3, hp1.y, lp1.y);
    ((__nv_bfloat162*)ygh)[i4*2]   = hp0;
    ((__nv_bfloat162*)ygh)[i4*2+1] = hp1;
    ((__nv_bfloat162*)ygl)[i4*2]   = lp0;
    ((__nv_bfloat162*)ygl)[i4*2+1] = lp1;
}

// ---------------------------------------------------------------------------
// Launch
// ---------------------------------------------------------------------------
extern "C" void kernel_launch(void* const* d_in, const int* in_sizes, int n_in,
                              void* d_out, int out_size)
{
    (void)in_sizes; (void)n_in; (void)out_size;
    const float* x       = (const float*)d_in[0];
    const float* miu_x   = (const float*)d_in[1];
    const float* lambda_ = (const float*)d_in[2];
    const float* A_lora  = (const float*)d_in[3];
    const float* B_lora  = (const float*)d_in[4];
    const float* td_miu  = (const float*)d_in[5];
    const float* td_A    = (const float*)d_in[6];
    const float* td_B    = (const float*)d_in[7];
    const float* u       = (const float*)d_in[8];
    const float* Wr      = (const float*)d_in[9];
    const float* Wk      = (const float*)d_in[10];
    const float* Wv      = (const float*)d_in[11];
    const float* Wg      = (const float*)d_in[12];
    const float* Wo      = (const float*)d_in[13];
    const float* gamma   = (const float*)d_in[14];
    const float* beta    = (const float*)d_in[15];
    float* out = (float*)d_out;

    float *p_dxa,*p_k,*p_v,*p_r,*p_g,*p_w,*p_y,*p_lorap,*p_BloraT;
    __nv_bfloat16 *p_xmh,*p_xml,*p_abh,*p_abl,*p_ygh,*p_ygl,*p_wbh,*p_wbl,
                  *p_AloraTh,*p_AloraTl;
    __half *p_xx0h,*p_xx0l,*p_tdhh,*p_tdhl,*p_tdATh,*p_tdATl,*p_tdBTh,*p_tdBTl;
    { void* t;
      cudaGetSymbolAddress(&t, g_dxa);     p_dxa     = (float*)t;
      cudaGetSymbolAddress(&t, g_k);       p_k       = (float*)t;
      cudaGetSymbolAddress(&t, g_v);       p_v       = (float*)t;
      cudaGetSymbolAddress(&t, g_r);       p_r       = (float*)t;
      cudaGetSymbolAddress(&t, g_g);       p_g       = (float*)t;
      cudaGetSymbolAddress(&t, g_w);       p_w       = (float*)t;
      cudaGetSymbolAddress(&t, g_y);       p_y       = (float*)t;
      cudaGetSymbolAddress(&t, g_lorap);   p_lorap   = (float*)t;
      cudaGetSymbolAddress(&t, g_BloraT);  p_BloraT  = (float*)t;
      cudaGetSymbolAddress(&t, g_xmh);     p_xmh     = (__nv_bfloat16*)t;
      cudaGetSymbolAddress(&t, g_xml);     p_xml     = (__nv_bfloat16*)t;
      cudaGetSymbolAddress(&t, g_abh);     p_abh     = (__nv_bfloat16*)t;
      cudaGetSymbolAddress(&t, g_abl);     p_abl     = (__nv_bfloat16*)t;
      cudaGetSymbolAddress(&t, g_ygh);     p_ygh     = (__nv_bfloat16*)t;
      cudaGetSymbolAddress(&t, g_ygl);     p_ygl     = (__nv_bfloat16*)t;
      cudaGetSymbolAddress(&t, g_wbh);     p_wbh     = (__nv_bfloat16*)t;
      cudaGetSymbolAddress(&t, g_wbl);     p_wbl     = (__nv_bfloat16*)t;
      cudaGetSymbolAddress(&t, g_AloraTh); p_AloraTh = (__nv_bfloat16*)t;
      cudaGetSymbolAddress(&t, g_AloraTl); p_AloraTl = (__nv_bfloat16*)t;
      cudaGetSymbolAddress(&t, g_xx0h);    p_xx0h    = (__half*)t;
      cudaGetSymbolAddress(&t, g_xx0l);    p_xx0l    = (__half*)t;
      cudaGetSymbolAddress(&t, g_tdhh);    p_tdhh    = (__half*)t;
      cudaGetSymbolAddress(&t, g_tdhl);    p_tdhl    = (__half*)t;
      cudaGetSymbolAddress(&t, g_tdATh);   p_tdATh   = (__half*)t;
      cudaGetSymbolAddress(&t, g_tdATl);   p_tdATl   = (__half*)t;
      cudaGetSymbolAddress(&t, g_tdBTh);   p_tdBTh   = (__half*)t;
      cudaGetSymbolAddress(&t, g_tdBTl);   p_tdBTl   = (__half*)t;
    }

    cudaFuncSetAttribute(hgemm_one,  cudaFuncAttributeMaxDynamicSharedMemorySize, HG_SMEM);
    cudaFuncSetAttribute(hgemm_kvrg, cudaFuncAttributeMaxDynamicSharedMemorySize, HG_SMEM);
    cudaFuncSetAttribute(hgemm_h,    cudaFuncAttributeMaxDynamicSharedMemorySize, HG_SMEM);

    // 0: token shift + static lerp (xm -> bf16 hi/lo)
    prep_kernel<<<BTq * Cq / 4 / 256, 256>>>((const float4*)x, (const float4*)miu_x,
                                             (float4*)p_dxa, p_xmh, p_xml);
    // 1: weight transposes
    transpose_all<<<(622592 + 255) / 256, 256>>>(p_AloraTh, p_AloraTl, A_lora,
                                                 p_tdATh, p_tdATl, td_A,
                                                 p_tdBTh, p_tdBTl, td_B,
                                                 p_BloraT, B_lora);
    // 2: lora_h = tanh(xm @ A_lora)
    hgemm_one<<<dim3(2, 128), 256, HG_SMEM>>>(p_xmh, p_xml, p_AloraTh, p_AloraTl,
                                              p_lorap, 256, Cq, 2);
    // 3: ddlerp mix (f=0 -> fp16 hi/lo xx0; f=1..4 -> bf16 hi/lo k,v,r,g)
    mix_gemm<<<dim3(5, 128, 8), 256>>>(p_lorap, p_BloraT, x, p_dxa, lambda_,
                                       p_xx0h, p_xx0l, p_abh, p_abl);
    // 4: big weight hi/lo (moved here — only needed before kvrg)
    wconv_kernel<<<5 * 1048576 / 256, 256>>>(Wk, Wv, Wr, Wg, Wo, p_wbh, p_wbl);
    // 5: merged projections k, v, r, g
    hgemm_kvrg<<<dim3(8, 128, 4), 256, HG_SMEM>>>(p_abh, p_abl, p_wbh, p_wbl,
                                                  p_k, p_v, p_r, p_g);
    // 6: tdh = tanh(w_in @ td_A) -> fp16 hi/lo (padded N=128)
    hgemm_h<<<dim3(1, 128), 256, HG_SMEM>>>(p_xx0h, p_xx0l, p_tdATh, p_tdATl,
                                            nullptr, p_tdhh, p_tdhl, nullptr,
                                            128, Cq, Cq, Cq, 3);
    // 7: w = td_miu + tdh @ td_B   (A stride 128, K=64)
    hgemm_h<<<dim3(8, 128), 256, HG_SMEM>>>(p_tdhh, p_tdhl, p_tdBTh, p_tdBTl,
                                            p_w, nullptr, nullptr, td_miu,
                                            Cq, 64, 128, 64, 4);
    // 8: WKV6 scan
    wkv6_kernel<<<Bq * Hq, 256>>>(p_r, p_k, p_v, p_w, u, p_y);
    // 9: GroupNorm * gate -> bf16 hi/lo
    gnorm_kernel<<<BTq, 256>>>(p_y, p_g, gamma, beta, p_ygh, p_ygl);
    // 10: output projection
    hgemm_one<<<dim3(8, 128), 256, HG_SMEM>>>(p_ygh, p_ygl, p_wbh + 4*WWq, p_wbl + 4*WWq,
                                              out, Cq, Cq, 0);
}